// round 2
// baseline (speedup 1.0000x reference)
#include <cuda_runtime.h>
#include <math.h>

#define B_    4
#define CIN_  256
#define MID_  128
#define COUT_ 64
#define H_    128
#define W_    128
#define WS_   8
#define HEADS_ 8
#define HD_   16
#define NTOK  64
#define NWIN  1024   /* B * 16 * 16 */

// ---------------- scratch (static device memory; no allocs) ----------------
__device__ float g_h    [B_*MID_*H_*W_];
__device__ float g_local[B_*MID_*H_*W_];
__device__ float g_qkv  [3*NWIN*HEADS_*NTOK*HD_];
__device__ float g_dots [NWIN*HEADS_*NTOK*NTOK];
__device__ float g_g1   [NWIN*HEADS_*NTOK];
__device__ float g_g2   [NWIN*NTOK*HEADS_];
__device__ float g_g3   [NWIN*NTOK*NTOK];
__device__ float g_o    [B_*MID_*H_*W_];
__device__ float g_out  [B_*MID_*H_*W_];
__device__ float g_dw   [B_*MID_*H_*W_];
__device__ float g_proj [B_*MID_*H_*W_];

__device__ __forceinline__ float sigmoidf_(float x){ return 1.f/(1.f+expf(-x)); }

// ---------------- K1: conv3x3 256->128 + BN + ReLU -> g_h -------------------
__global__ void k_conv1(const float* __restrict__ x, const float* __restrict__ w,
                        const float* __restrict__ g, const float* __restrict__ bb){
  __shared__ float s_in[18*18];
  __shared__ float s_w[72];
  int tid = threadIdx.x;
  int tx = tid & 15, ty = tid >> 4;
  int bx = blockIdx.x*16, by = blockIdx.y*16;
  int b   = blockIdx.z >> 4;
  int cog = (blockIdx.z & 15) * 8;
  float acc[8] = {0,0,0,0,0,0,0,0};
  for (int ci = 0; ci < CIN_; ci++){
    const float* xp = x + (size_t)(b*CIN_+ci)*H_*W_;
    for (int i = tid; i < 324; i += 256){
      int iy = i/18, ix = i - iy*18;
      int gy = by+iy-1, gx = bx+ix-1;
      s_in[i] = (gy>=0 && gy<H_ && gx>=0 && gx<W_) ? xp[gy*W_+gx] : 0.f;
    }
    if (tid < 72){
      int co = tid/9, k = tid - co*9;
      s_w[tid] = w[((size_t)(cog+co)*CIN_+ci)*9 + k];
    }
    __syncthreads();
    float v[9];
#pragma unroll
    for (int ky=0;ky<3;ky++)
#pragma unroll
      for (int kx=0;kx<3;kx++)
        v[ky*3+kx] = s_in[(ty+ky)*18 + tx+kx];
#pragma unroll
    for (int co=0;co<8;co++){
      float a = acc[co];
#pragma unroll
      for (int k=0;k<9;k++) a = fmaf(v[k], s_w[co*9+k], a);
      acc[co]=a;
    }
    __syncthreads();
  }
  int y = by+ty, xx = bx+tx;
#pragma unroll
  for (int co=0;co<8;co++){
    int c = cog+co;
    float r = acc[co]*g[c] + bb[c];
    g_h[((size_t)(b*MID_+c)*H_+y)*W_+xx] = fmaxf(r, 0.f);
  }
}

// --------- K2: local = bn(conv1x1 loc2) + bn(conv3x3 loc1) -> g_local -------
__global__ void k_local(const float* __restrict__ w3, const float* __restrict__ g3,
                        const float* __restrict__ b3, const float* __restrict__ w1,
                        const float* __restrict__ g1, const float* __restrict__ b1){
  __shared__ float s_in[18*18];
  __shared__ float s_w3[72];
  __shared__ float s_w1[8];
  int tid = threadIdx.x;
  int tx = tid & 15, ty = tid >> 4;
  int bx = blockIdx.x*16, by = blockIdx.y*16;
  int b   = blockIdx.z >> 4;
  int cog = (blockIdx.z & 15) * 8;
  float a3[8] = {0,0,0,0,0,0,0,0};
  float a1[8] = {0,0,0,0,0,0,0,0};
  for (int ci = 0; ci < MID_; ci++){
    const float* xp = g_h + (size_t)(b*MID_+ci)*H_*W_;
    for (int i = tid; i < 324; i += 256){
      int iy = i/18, ix = i - iy*18;
      int gy = by+iy-1, gx = bx+ix-1;
      s_in[i] = (gy>=0 && gy<H_ && gx>=0 && gx<W_) ? xp[gy*W_+gx] : 0.f;
    }
    if (tid < 72){
      int co = tid/9, k = tid - co*9;
      s_w3[tid] = w3[((size_t)(cog+co)*MID_+ci)*9 + k];
    } else if (tid < 80){
      s_w1[tid-72] = w1[(size_t)(cog+tid-72)*MID_ + ci];
    }
    __syncthreads();
    float v[9];
#pragma unroll
    for (int ky=0;ky<3;ky++)
#pragma unroll
      for (int kx=0;kx<3;kx++)
        v[ky*3+kx] = s_in[(ty+ky)*18 + tx+kx];
#pragma unroll
    for (int co=0;co<8;co++){
      float a = a3[co];
#pragma unroll
      for (int k=0;k<9;k++) a = fmaf(v[k], s_w3[co*9+k], a);
      a3[co]=a;
      a1[co] = fmaf(v[4], s_w1[co], a1[co]);
    }
    __syncthreads();
  }
  int y = by+ty, xx = bx+tx;
#pragma unroll
  for (int co=0;co<8;co++){
    int c = cog+co;
    float r = (a1[co]*g1[c] + b1[c]) + (a3[co]*g3[c] + b3[c]);
    g_local[((size_t)(b*MID_+c)*H_+y)*W_+xx] = r;
  }
}

// ---------------- K3: qkv 1x1 conv 128->384, windowed layout ----------------
__global__ void k_qkv(const float* __restrict__ w){
  __shared__ float s_in[16*256];
  __shared__ float s_w[8*16];
  int tid = threadIdx.x;
  int tx = tid & 15, ty = tid >> 4;
  int y = blockIdx.y*16+ty, x = blockIdx.x*16+tx;
  int b   = blockIdx.z / 48;
  int cog = (blockIdx.z % 48) * 8;
  float acc[8] = {0,0,0,0,0,0,0,0};
  const float* in = g_h + (size_t)b*MID_*H_*W_ + (size_t)y*W_ + x;
  for (int c0 = 0; c0 < MID_; c0 += 16){
#pragma unroll
    for (int c=0;c<16;c++) s_in[c*256+tid] = in[(size_t)(c0+c)*H_*W_];
    if (tid < 128) s_w[tid] = w[(size_t)(cog + (tid>>4))*MID_ + c0 + (tid&15)];
    __syncthreads();
#pragma unroll
    for (int c=0;c<16;c++){
      float v = s_in[c*256+tid];
#pragma unroll
      for (int co=0;co<8;co++) acc[co] = fmaf(v, s_w[co*16+c], acc[co]);
    }
    __syncthreads();
  }
  int yh = y>>3, wy = y&7, xw = x>>3, wx = x&7;
  int bp = (b*16+yh)*16+xw;
  int n  = wy*8+wx;
#pragma unroll
  for (int co=0;co<8;co++){
    int c = cog+co;
    int s = c>>7, hd = (c>>4)&7, d = c&15;
    g_qkv[(((size_t)(s*NWIN+bp)*HEADS_+hd)*NTOK+n)*HD_ + d] = acc[co];
  }
}

// ---------------- K4: dots = q k^T * 0.25 + rel bias ------------------------
__global__ void k_dots(const float* __restrict__ rel){
  int bh = blockIdx.x;                 // 0..8191
  int bp = bh >> 3, head = bh & 7;
  int tid = threadIdx.x;
  __shared__ float sq[NTOK*HD_], sk[NTOK*HD_];
  const float* qp = g_qkv + ((size_t)(0*NWIN+bp)*HEADS_+head)*NTOK*HD_;
  const float* kp = g_qkv + ((size_t)(1*NWIN+bp)*HEADS_+head)*NTOK*HD_;
  for (int i=tid;i<NTOK*HD_;i+=256){ sq[i]=qp[i]; sk[i]=kp[i]; }
  __syncthreads();
  for (int idx=tid; idx<4096; idx+=256){
    int n = idx>>6, m = idx&63;
    float s = 0.f;
#pragma unroll
    for (int d=0;d<HD_;d++) s = fmaf(sq[n*HD_+d], sk[m*HD_+d], s);
    int y1=n>>3, x1=n&7, y2=m>>3, x2=m&7;
    int ridx = (y1-y2+7)*15 + (x1-x2+7);
    g_dots[(size_t)bh*4096 + idx] = s*0.25f + rel[ridx*HEADS_ + head];
  }
}

// ---------------- K5: gating maps (3x reductions + 7x7 convs) ---------------
__global__ void k_gate(const float* __restrict__ cw_w, const float* __restrict__ cw_g, const float* __restrict__ cw_b,
                       const float* __restrict__ hc_w, const float* __restrict__ hc_g, const float* __restrict__ hc_b,
                       const float* __restrict__ hw_w, const float* __restrict__ hw_g, const float* __restrict__ hw_b){
  __shared__ float z3mx[4096], z3sm[4096];
  __shared__ float z1mx[512],  z1sm[512];
  __shared__ float z2mx[512],  z2sm[512];
  __shared__ float swc[98], swh[98], sww[98];
  int bp = blockIdx.x, tid = threadIdx.x;
  if (tid < 98){ swc[tid]=cw_w[tid]; swh[tid]=hc_w[tid]; sww[tid]=hw_w[tid]; }
  const float* dp = g_dots + (size_t)bp*HEADS_*4096;
  // z3: reduce over heads -> (n,m)
  for (int idx=tid; idx<4096; idx+=256){
    float mx=-1e30f, sm=0.f;
#pragma unroll
    for (int h=0;h<8;h++){ float v = dp[h*4096+idx]; mx=fmaxf(mx,v); sm+=v; }
    z3mx[idx]=mx; z3sm[idx]=sm*0.125f;
  }
  // z1: reduce over n -> (h,m)
  for (int idx=tid; idx<512; idx+=256){
    int h = idx>>6, m = idx&63;
    float mx=-1e30f, sm=0.f;
    for (int n=0;n<64;n++){ float v = dp[h*4096 + n*64 + m]; mx=fmaxf(mx,v); sm+=v; }
    z1mx[idx]=mx; z1sm[idx]=sm*(1.f/64.f);
  }
  // z2: reduce over m -> (n,h)
  for (int idx=tid; idx<512; idx+=256){
    int n = idx>>3, h = idx&7;
    float mx=-1e30f, sm=0.f;
    const float* rp = dp + h*4096 + n*64;
    for (int m=0;m<64;m++){ float v = rp[m]; mx=fmaxf(mx,v); sm+=v; }
    z2mx[idx]=mx; z2sm[idx]=sm*(1.f/64.f);
  }
  __syncthreads();
  float hwg = hw_g[0], hwb = hw_b[0];
  float cwg = cw_g[0], cwb = cw_b[0];
  float hcg = hc_g[0], hcb = hc_b[0];
  // gmap3: spatial (n=64, m=64), conv hw
  for (int idx=tid; idx<4096; idx+=256){
    int n = idx>>6, m = idx&63;
    float s = 0.f;
    for (int ky=0;ky<7;ky++){
      int pn = n-3+ky; if (pn<0||pn>=64) continue;
      for (int kx=0;kx<7;kx++){
        int pm = m-3+kx; if (pm<0||pm>=64) continue;
        int zi = pn*64+pm;
        s += z3mx[zi]*sww[ky*7+kx] + z3sm[zi]*sww[49+ky*7+kx];
      }
    }
    g_g3[(size_t)bp*4096+idx] = sigmoidf_(s*hwg + hwb);
  }
  // gmap1: spatial (h=8 rows, m=64 cols), conv cw
  for (int idx=tid; idx<512; idx+=256){
    int h = idx>>6, m = idx&63;
    float s = 0.f;
    for (int ky=0;ky<7;ky++){
      int ph = h-3+ky; if (ph<0||ph>=8) continue;
      for (int kx=0;kx<7;kx++){
        int pm = m-3+kx; if (pm<0||pm>=64) continue;
        int zi = ph*64+pm;
        s += z1mx[zi]*swc[ky*7+kx] + z1sm[zi]*swc[49+ky*7+kx];
      }
    }
    g_g1[(size_t)bp*512+idx] = sigmoidf_(s*cwg + cwb);
  }
  // gmap2: spatial (n=64 rows, h=8 cols), conv hc
  for (int idx=tid; idx<512; idx+=256){
    int n = idx>>3, h = idx&7;
    float s = 0.f;
    for (int ky=0;ky<7;ky++){
      int pn = n-3+ky; if (pn<0||pn>=64) continue;
      for (int kx=0;kx<7;kx++){
        int ph = h-3+kx; if (ph<0||ph>=8) continue;
        int zi = pn*8+ph;
        s += z2mx[zi]*swh[ky*7+kx] + z2sm[zi]*swh[49+ky*7+kx];
      }
    }
    g_g2[(size_t)bp*512+idx] = sigmoidf_(s*hcg + hcb);
  }
}

// ---------------- K6: gated dots -> softmax -> attn@v -> g_o ----------------
__global__ void k_attn(){
  int bh = blockIdx.x;
  int bp = bh >> 3, head = bh & 7;
  int tid = threadIdx.x;
  __shared__ float sd[4096];
  __shared__ float sv[NTOK*HD_];
  const float* dp = g_dots + (size_t)bh*4096;
  for (int idx=tid; idx<4096; idx+=256){
    int n = idx>>6, m = idx&63;
    float gsum = g_g1[(size_t)(bp*8+head)*64 + m]
               + g_g2[(size_t)(bp*64+n)*8 + head]
               + g_g3[(size_t)bp*4096 + n*64 + m];
    sd[idx] = dp[idx] * gsum * (1.f/3.f);
  }
  const float* vp = g_qkv + ((size_t)(2*NWIN+bp)*HEADS_+head)*NTOK*HD_;
  for (int i=tid;i<NTOK*HD_;i+=256) sv[i]=vp[i];
  __syncthreads();
  if (tid < 64){
    float mx = -1e30f;
    for (int m=0;m<64;m++) mx = fmaxf(mx, sd[tid*64+m]);
    float sm = 0.f;
    for (int m=0;m<64;m++){ float e = expf(sd[tid*64+m]-mx); sd[tid*64+m]=e; sm+=e; }
    float inv = 1.f/sm;
    for (int m=0;m<64;m++) sd[tid*64+m] *= inv;
  }
  __syncthreads();
  int b = bp>>8, yh = (bp>>4)&15, xw = bp&15;
  for (int idx=tid; idx<NTOK*HD_; idx+=256){
    int n = idx>>4, d = idx&15;
    float s = 0.f;
#pragma unroll
    for (int m=0;m<64;m++) s = fmaf(sd[n*64+m], sv[m*HD_+d], s);
    int c = head*HD_ + d;
    int y = yh*8 + (n>>3), x = xw*8 + (n&7);
    g_o[((size_t)(b*MID_+c)*H_+y)*W_+x] = s;
  }
}

// ---------------- K7: Fh@Fw gating, out = o*gmat + local --------------------
__global__ void k_gmat(){
  __shared__ float Fh[128*32];
  __shared__ float Fw[32*128];
  int bc = blockIdx.x, tid = threadIdx.x;
  const float* op = g_o + (size_t)bc*H_*W_;
  for (int idx=tid; idx<4096; idx+=256){
    { // Fw[k][w]: reduce over 4 rows
      int k = idx>>7, w = idx&127;
      float mx=-1e30f, sm=0.f;
#pragma unroll
      for (int j=0;j<4;j++){ float v = op[(k*4+j)*W_+w]; mx=fmaxf(mx,v); sm+=v; }
      Fw[idx] = sigmoidf_(sm*0.25f + mx);
    }
    { // Fh[y][k]: reduce over 4 cols
      int y = idx>>5, k = idx&31;
      float mx=-1e30f, sm=0.f;
#pragma unroll
      for (int j=0;j<4;j++){ float v = op[y*W_ + k*4+j]; mx=fmaxf(mx,v); sm+=v; }
      Fh[idx] = sigmoidf_(sm*0.25f + mx);
    }
  }
  __syncthreads();
  const float* lp = g_local + (size_t)bc*H_*W_;
  float* outp = g_out + (size_t)bc*H_*W_;
  for (int idx=tid; idx<H_*W_; idx+=256){
    int y = idx>>7, w = idx&127;
    float gm = 0.f;
#pragma unroll
    for (int k=0;k<32;k++) gm = fmaf(Fh[y*32+k], Fw[k*128+w], gm);
    outp[idx] = op[idx]*gm + lp[idx];
  }
}

// ---------------- K8a: reflect-pad + depthwise 8x8 + BN ---------------------
__global__ void k_dw(const float* __restrict__ dww, const float* __restrict__ g,
                     const float* __restrict__ bb){
  __shared__ float sw[64];
  int y  = blockIdx.x;
  int bc = blockIdx.y;
  int c  = bc & 127;
  int tid = threadIdx.x;
  if (tid < 64) sw[tid] = dww[c*64 + tid];
  __syncthreads();
  int x = tid;
  const float* op = g_out + (size_t)bc*H_*W_;
  float acc = 0.f;
  for (int ky=0;ky<8;ky++){
    int py = y-3+ky;
    if (py < 0 || py > 128) continue;
    int ry = (py==128) ? 126 : py;
    for (int kx=0;kx<8;kx++){
      int px = x-3+kx;
      if (px < 0 || px > 128) continue;
      int rx = (px==128) ? 126 : px;
      acc = fmaf(op[ry*W_+rx], sw[ky*8+kx], acc);
    }
  }
  g_dw[(size_t)bc*H_*W_ + y*W_ + x] = acc*g[c] + bb[c];
}

// ---------------- K8b: pointwise 1x1 128->128 -> g_proj ---------------------
__global__ void k_pw(const float* __restrict__ w){
  __shared__ float s_in[16*256];
  __shared__ float s_w[8*16];
  int tid = threadIdx.x;
  int tx = tid & 15, ty = tid >> 4;
  int y = blockIdx.y*16+ty, x = blockIdx.x*16+tx;
  int b   = blockIdx.z >> 4;
  int cog = (blockIdx.z & 15) * 8;
  float acc[8] = {0,0,0,0,0,0,0,0};
  const float* in = g_dw + (size_t)b*MID_*H_*W_ + (size_t)y*W_ + x;
  for (int c0 = 0; c0 < MID_; c0 += 16){
#pragma unroll
    for (int c=0;c<16;c++) s_in[c*256+tid] = in[(size_t)(c0+c)*H_*W_];
    if (tid < 128) s_w[tid] = w[(size_t)(cog + (tid>>4))*MID_ + c0 + (tid&15)];
    __syncthreads();
#pragma unroll
    for (int c=0;c<16;c++){
      float v = s_in[c*256+tid];
#pragma unroll
      for (int co=0;co<8;co++) acc[co] = fmaf(v, s_w[co*16+c], acc[co]);
    }
    __syncthreads();
  }
#pragma unroll
  for (int co=0;co<8;co++)
    g_proj[((size_t)(b*MID_+cog+co)*H_+y)*W_+x] = acc[co];
}

// ---------------- K9: transposed conv (lhs_dilation=2) -> d_out -------------
__global__ void k_up(const float* __restrict__ upw, float* __restrict__ out){
  __shared__ float sw[8*128*9];
  int tid = threadIdx.x;
  int oy  = blockIdx.x;
  int b   = blockIdx.y >> 3;
  int cog = (blockIdx.y & 7) * 8;
  for (int i=tid;i<8*128*9;i+=256) sw[i] = upw[(size_t)cog*128*9 + i];
  __syncthreads();
  int ox = tid;
  float acc[8] = {0,0,0,0,0,0,0,0};
  const float* pp = g_proj + (size_t)b*MID_*H_*W_;
  for (int ky=0;ky<3;ky++){
    int t = oy+ky-1;
    if (t < 0 || t > 254 || (t & 1)) continue;
    int iy = t >> 1;
    for (int kx=0;kx<3;kx++){
      int u = ox+kx-1;
      if (u < 0 || u > 254 || (u & 1)) continue;
      int ix = u >> 1;
      int k = ky*3+kx;
      const float* ip = pp + iy*W_ + ix;
      for (int ci=0;ci<128;ci++){
        float v = ip[(size_t)ci*H_*W_];
#pragma unroll
        for (int co=0;co<8;co++) acc[co] = fmaf(v, sw[(co*128+ci)*9+k], acc[co]);
      }
    }
  }
#pragma unroll
  for (int co=0;co<8;co++)
    out[(((size_t)(b*COUT_+cog+co))*256+oy)*256+ox] = acc[co];
}

// ---------------------------------------------------------------------------
extern "C" void kernel_launch(void* const* d_in, const int* in_sizes, int n_in,
                              void* d_out, int out_size){
  const float* x      = (const float*)d_in[0];
  const float* conv_w = (const float*)d_in[1];
  const float* bn1_g  = (const float*)d_in[2];
  const float* bn1_b  = (const float*)d_in[3];
  const float* qkv_w  = (const float*)d_in[4];
  const float* loc1_w = (const float*)d_in[5];
  const float* loc1_g = (const float*)d_in[6];
  const float* loc1_b = (const float*)d_in[7];
  const float* loc2_w = (const float*)d_in[8];
  const float* loc2_g = (const float*)d_in[9];
  const float* loc2_b = (const float*)d_in[10];
  const float* rel_t  = (const float*)d_in[11];
  const float* cw_w   = (const float*)d_in[12];
  const float* cw_g   = (const float*)d_in[13];
  const float* cw_b   = (const float*)d_in[14];
  const float* hc_w   = (const float*)d_in[15];
  const float* hc_g   = (const float*)d_in[16];
  const float* hc_b   = (const float*)d_in[17];
  const float* hw_w   = (const float*)d_in[18];
  const float* hw_g   = (const float*)d_in[19];
  const float* hw_b   = (const float*)d_in[20];
  const float* pdw    = (const float*)d_in[21];
  const float* pg     = (const float*)d_in[22];
  const float* pb     = (const float*)d_in[23];
  const float* ppw    = (const float*)d_in[24];
  const float* upw    = (const float*)d_in[25];
  float* out = (float*)d_out;

  k_conv1<<<dim3(8,8,64), 256>>>(x, conv_w, bn1_g, bn1_b);
  k_local<<<dim3(8,8,64), 256>>>(loc1_w, loc1_g, loc1_b, loc2_w, loc2_g, loc2_b);
  k_qkv  <<<dim3(8,8,192), 256>>>(qkv_w);
  k_dots <<<8192, 256>>>(rel_t);
  k_gate <<<1024, 256>>>(cw_w, cw_g, cw_b, hc_w, hc_g, hc_b, hw_w, hw_g, hw_b);
  k_attn <<<8192, 256>>>();
  k_gmat <<<512, 256>>>();
  k_dw   <<<dim3(128, 512), 128>>>(pdw, pg, pb);
  k_pw   <<<dim3(8,8,64), 256>>>(ppw);
  k_up   <<<dim3(256, 32), 256>>>(upw, out);
}

// round 3
// speedup vs baseline: 1.0249x; 1.0249x over previous
#include <cuda_runtime.h>
#include <math.h>

#define B_    4
#define CIN_  256
#define MID_  128
#define COUT_ 64
#define H_    128
#define W_    128
#define WS_   8
#define HEADS_ 8
#define HD_   16
#define NTOK  64
#define NWIN  1024   /* B * 16 * 16 */

// ---------------- scratch (static device memory; no allocs) ----------------
__device__ float g_h    [B_*MID_*H_*W_];
__device__ float g_local[B_*MID_*H_*W_];
__device__ float g_qkv  [3*NWIN*HEADS_*NTOK*HD_];
__device__ float g_o    [B_*MID_*H_*W_];
__device__ float g_out  [B_*MID_*H_*W_];
__device__ float g_dw   [B_*MID_*H_*W_];
__device__ float g_proj [B_*MID_*H_*W_];

__device__ __forceinline__ float sigmoidf_(float x){ return 1.f/(1.f+expf(-x)); }

// ---------------- K1: conv3x3 256->128 + BN + ReLU -> g_h -------------------
// 32x32 spatial tile, 8 couts, 2x2 pixels/thread, 2 input channels per sync.
__global__ void k_conv1(const float* __restrict__ x, const float* __restrict__ w,
                        const float* __restrict__ g, const float* __restrict__ bb){
  __shared__ float s_in[2][34*34];
  __shared__ float s_w[2][72];
  int tid = threadIdx.x;
  int tx = tid & 15, ty = tid >> 4;
  int bx = blockIdx.x*32, by = blockIdx.y*32;
  int b   = blockIdx.z >> 4;
  int cog = (blockIdx.z & 15) * 8;
  float acc[4][8];
#pragma unroll
  for (int p=0;p<4;p++)
#pragma unroll
    for (int c=0;c<8;c++) acc[p][c]=0.f;

  for (int ci0 = 0; ci0 < CIN_; ci0 += 2){
#pragma unroll
    for (int c=0;c<2;c++){
      const float* xp = x + (size_t)(b*CIN_+ci0+c)*H_*W_;
      for (int i = tid; i < 34*34; i += 256){
        int iy = i/34, ix = i - iy*34;
        int gy = by+iy-1, gx = bx+ix-1;
        s_in[c][i] = (gy>=0 && gy<H_ && gx>=0 && gx<W_) ? xp[gy*W_+gx] : 0.f;
      }
    }
    if (tid < 144){
      int c = tid >= 72; int t = tid - c*72;
      int co = t/9, k = t - co*9;
      s_w[c][t] = w[((size_t)(cog+co)*CIN_+ci0+c)*9 + k];
    }
    __syncthreads();
#pragma unroll
    for (int c=0;c<2;c++){
      float v[16];
#pragma unroll
      for (int iy=0;iy<4;iy++)
#pragma unroll
        for (int ix=0;ix<4;ix++)
          v[iy*4+ix] = s_in[c][(ty*2+iy)*34 + tx*2+ix];
#pragma unroll
      for (int co=0;co<8;co++){
#pragma unroll
        for (int py=0;py<2;py++)
#pragma unroll
          for (int px=0;px<2;px++){
            float a = acc[py*2+px][co];
#pragma unroll
            for (int ky=0;ky<3;ky++)
#pragma unroll
              for (int kx=0;kx<3;kx++)
                a = fmaf(v[(py+ky)*4+px+kx], s_w[c][co*9+ky*3+kx], a);
            acc[py*2+px][co] = a;
          }
      }
    }
    __syncthreads();
  }
  int y0 = by+ty*2, x0 = bx+tx*2;
#pragma unroll
  for (int co=0;co<8;co++){
    int c = cog+co;
    float gg = g[c], bbv = bb[c];
#pragma unroll
    for (int py=0;py<2;py++)
#pragma unroll
      for (int px=0;px<2;px++){
        float r = acc[py*2+px][co]*gg + bbv;
        g_h[((size_t)(b*MID_+c)*H_+y0+py)*W_+x0+px] = fmaxf(r, 0.f);
      }
  }
}

// --------- K2: local = bn(conv1x1 loc2) + bn(conv3x3 loc1) -> g_local -------
__global__ void k_local(const float* __restrict__ w3, const float* __restrict__ g3,
                        const float* __restrict__ b3, const float* __restrict__ w1,
                        const float* __restrict__ g1, const float* __restrict__ b1){
  __shared__ float s_in[2][34*34];
  __shared__ float s_w3[2][72];
  __shared__ float s_w1[2][8];
  int tid = threadIdx.x;
  int tx = tid & 15, ty = tid >> 4;
  int bx = blockIdx.x*32, by = blockIdx.y*32;
  int b   = blockIdx.z >> 4;
  int cog = (blockIdx.z & 15) * 8;
  float a3[4][8], a1[4][8];
#pragma unroll
  for (int p=0;p<4;p++)
#pragma unroll
    for (int c=0;c<8;c++){ a3[p][c]=0.f; a1[p][c]=0.f; }

  for (int ci0 = 0; ci0 < MID_; ci0 += 2){
#pragma unroll
    for (int c=0;c<2;c++){
      const float* xp = g_h + (size_t)(b*MID_+ci0+c)*H_*W_;
      for (int i = tid; i < 34*34; i += 256){
        int iy = i/34, ix = i - iy*34;
        int gy = by+iy-1, gx = bx+ix-1;
        s_in[c][i] = (gy>=0 && gy<H_ && gx>=0 && gx<W_) ? xp[gy*W_+gx] : 0.f;
      }
    }
    if (tid < 144){
      int c = tid >= 72; int t = tid - c*72;
      int co = t/9, k = t - co*9;
      s_w3[c][t] = w3[((size_t)(cog+co)*MID_+ci0+c)*9 + k];
    } else if (tid < 160){
      int t = tid - 144; int c = t >> 3, co = t & 7;
      s_w1[c][co] = w1[(size_t)(cog+co)*MID_ + ci0+c];
    }
    __syncthreads();
#pragma unroll
    for (int c=0;c<2;c++){
      float v[16];
#pragma unroll
      for (int iy=0;iy<4;iy++)
#pragma unroll
        for (int ix=0;ix<4;ix++)
          v[iy*4+ix] = s_in[c][(ty*2+iy)*34 + tx*2+ix];
#pragma unroll
      for (int co=0;co<8;co++){
        float w1v = s_w1[c][co];
#pragma unroll
        for (int py=0;py<2;py++)
#pragma unroll
          for (int px=0;px<2;px++){
            float a = a3[py*2+px][co];
#pragma unroll
            for (int ky=0;ky<3;ky++)
#pragma unroll
              for (int kx=0;kx<3;kx++)
                a = fmaf(v[(py+ky)*4+px+kx], s_w3[c][co*9+ky*3+kx], a);
            a3[py*2+px][co] = a;
            a1[py*2+px][co] = fmaf(v[(py+1)*4+px+1], w1v, a1[py*2+px][co]);
          }
      }
    }
    __syncthreads();
  }
  int y0 = by+ty*2, x0 = bx+tx*2;
#pragma unroll
  for (int co=0;co<8;co++){
    int c = cog+co;
    float g3v=g3[c], b3v=b3[c], g1v=g1[c], b1v=b1[c];
#pragma unroll
    for (int py=0;py<2;py++)
#pragma unroll
      for (int px=0;px<2;px++){
        float r = (a1[py*2+px][co]*g1v + b1v) + (a3[py*2+px][co]*g3v + b3v);
        g_local[((size_t)(b*MID_+c)*H_+y0+py)*W_+x0+px] = r;
      }
  }
}

// ---------------- K3: qkv 1x1 conv 128->384, windowed layout ----------------
// tile: 8 rows x 128 cols (1024 px), 4 px/thread, 8 couts, 8-ci chunks.
__global__ void k_qkv(const float* __restrict__ w){
  __shared__ float s_in[8][1024];
  __shared__ float s_w[64];
  int tid = threadIdx.x;
  int tx = tid & 31, ty = tid >> 5;
  int by = blockIdx.y;               // 0..15 (row-tile)
  int b   = blockIdx.z / 48;
  int cog = (blockIdx.z % 48) * 8;
  float acc[8][4];
#pragma unroll
  for (int co=0;co<8;co++)
#pragma unroll
    for (int j=0;j<4;j++) acc[co][j]=0.f;
  const float* in = g_h + (size_t)b*MID_*H_*W_ + (size_t)(by*8)*W_;
  for (int c0 = 0; c0 < MID_; c0 += 8){
    for (int i = tid; i < 8192; i += 256){
      int c = i >> 10, p = i & 1023;
      s_in[c][p] = in[(size_t)(c0+c)*H_*W_ + p];
    }
    if (tid < 64) s_w[tid] = w[(size_t)(cog + (tid>>3))*MID_ + c0 + (tid&7)];
    __syncthreads();
#pragma unroll
    for (int c=0;c<8;c++){
      float v[4];
#pragma unroll
      for (int j=0;j<4;j++) v[j] = s_in[c][ty*128 + tx + 32*j];
#pragma unroll
      for (int co=0;co<8;co++){
        float wv = s_w[co*8+c];
#pragma unroll
        for (int j=0;j<4;j++) acc[co][j] = fmaf(v[j], wv, acc[co][j]);
      }
    }
    __syncthreads();
  }
  int y = by*8 + ty;
  int yh = y>>3, wy = y&7;
#pragma unroll
  for (int j=0;j<4;j++){
    int x = tx + 32*j;
    int xw = x>>3, wx = x&7;
    int bp = (b*16+yh)*16+xw;
    int n  = wy*8+wx;
#pragma unroll
    for (int co=0;co<8;co++){
      int c = cog+co;
      int s = c>>7, hd = (c>>4)&7, d = c&15;
      g_qkv[(((size_t)(s*NWIN+bp)*HEADS_+hd)*NTOK+n)*HD_ + d] = acc[co][j];
    }
  }
}

// ---------- K4: fused dots -> gates -> softmax -> attn@v -> g_o -------------
// one block per window bp; dynamic smem ~98.5KB; dots recomputed in pass 3.
__global__ void k_attnf(const float* __restrict__ rel,
                        const float* __restrict__ cw_w, const float* __restrict__ cw_g, const float* __restrict__ cw_b,
                        const float* __restrict__ hc_w, const float* __restrict__ hc_g, const float* __restrict__ hc_b,
                        const float* __restrict__ hw_w, const float* __restrict__ hw_g, const float* __restrict__ hw_b){
  extern __shared__ float sm[];
  float* sq   = sm;              // 1024
  float* sk   = sq   + 1024;     // 1024
  float* sv   = sk   + 1024;     // 1024
  float* sdh  = sv   + 1024;     // 4096
  float* z3mx = sdh  + 4096;     // 4096
  float* z3sm = z3mx + 4096;     // 4096
  float* z1mx = z3sm + 4096;     // 512
  float* z1sm = z1mx + 512;      // 512
  float* z2mx = z1sm + 512;      // 512
  float* z2sm = z2mx + 512;      // 512
  float* sg1  = z2sm + 512;      // 512
  float* sg2  = sg1  + 512;      // 512
  float* sg3  = sg2  + 512;      // 4096
  float* swc  = sg3  + 4096;     // 98
  float* swh  = swc  + 98;       // 98
  float* sww  = swh  + 98;       // 98
  float* srel = sww  + 98;       // 1800

  int bp = blockIdx.x, tid = threadIdx.x;
  if (tid < 98){ swc[tid]=cw_w[tid]; swh[tid]=hc_w[tid]; sww[tid]=hw_w[tid]; }
  for (int i=tid; i<1800; i+=256) srel[i] = rel[i];

  int dn = tid >> 2;          // 0..63
  int dmg = (tid & 3) * 16;   // m group base
  int y1 = dn>>3, x1 = dn&7;

  // ---- pass 1: per-head dots -> z reductions ----
  for (int h=0; h<8; h++){
    const float* qp = g_qkv + ((size_t)(0*NWIN+bp)*HEADS_+h)*NTOK*HD_;
    const float* kp = g_qkv + ((size_t)(1*NWIN+bp)*HEADS_+h)*NTOK*HD_;
    for (int i=tid;i<1024;i+=256){ sq[i]=qp[i]; sk[i]=kp[i]; }
    __syncthreads();
    {
      const float4* q4 = (const float4*)sq;
      const float4* k4 = (const float4*)sk;
      float4 qa = q4[dn*4+0], qb = q4[dn*4+1], qc = q4[dn*4+2], qd = q4[dn*4+3];
#pragma unroll
      for (int mm=0;mm<16;mm++){
        int m = dmg + mm;
        float4 ka = k4[m*4+0], kb = k4[m*4+1], kc = k4[m*4+2], kd = k4[m*4+3];
        float s = qa.x*ka.x + qa.y*ka.y + qa.z*ka.z + qa.w*ka.w
                + qb.x*kb.x + qb.y*kb.y + qb.z*kb.z + qb.w*kb.w
                + qc.x*kc.x + qc.y*kc.y + qc.z*kc.z + qc.w*kc.w
                + qd.x*kd.x + qd.y*kd.y + qd.z*kd.z + qd.w*kd.w;
        int y2 = m>>3, x2 = m&7;
        int ridx = (y1-y2+7)*15 + (x1-x2+7);
        float val = s*0.25f + srel[ridx*HEADS_ + h];
        int idx = dn*64 + m;
        sdh[idx] = val;
        if (h == 0){ z3mx[idx] = val; z3sm[idx] = val; }
        else { z3mx[idx] = fmaxf(z3mx[idx], val); z3sm[idx] += val; }
      }
    }
    __syncthreads();
    if (tid < 64){               // z1: per (h, m), reduce over n
      int m = tid;
      float mx=-1e30f, s=0.f;
      for (int n=0;n<64;n++){ float v = sdh[n*64+m]; mx=fmaxf(mx,v); s+=v; }
      z1mx[h*64+m]=mx; z1sm[h*64+m]=s;
    } else if (tid < 128){       // z2: per (n, h), reduce over m
      int n = tid-64;
      float mx=-1e30f, s=0.f;
      for (int j=0;j<64;j++){ float v = sdh[n*64 + ((j+n)&63)]; mx=fmaxf(mx,v); s+=v; }
      z2mx[n*8+h]=mx; z2sm[n*8+h]=s;
    }
    __syncthreads();
  }

  // ---- pass 2: gate maps ----
  float hwg = hw_g[0], hwb = hw_b[0];
  float cwg = cw_g[0], cwb = cw_b[0];
  float hcg = hc_g[0], hcb = hc_b[0];
  for (int idx=tid; idx<4096; idx+=256){
    int n = idx>>6, m = idx&63;
    float s = 0.f;
    for (int ky=0;ky<7;ky++){
      int pn = n-3+ky; if (pn<0||pn>=64) continue;
      for (int kx=0;kx<7;kx++){
        int pm = m-3+kx; if (pm<0||pm>=64) continue;
        int zi = pn*64+pm;
        s += z3mx[zi]*sww[ky*7+kx] + z3sm[zi]*0.125f*sww[49+ky*7+kx];
      }
    }
    sg3[idx] = sigmoidf_(s*hwg + hwb);
  }
  for (int idx=tid; idx<512; idx+=256){
    { // g1: spatial (h=8 rows, m=64 cols)
      int h = idx>>6, m = idx&63;
      float s = 0.f;
      for (int ky=0;ky<7;ky++){
        int ph = h-3+ky; if (ph<0||ph>=8) continue;
        for (int kx=0;kx<7;kx++){
          int pm = m-3+kx; if (pm<0||pm>=64) continue;
          int zi = ph*64+pm;
          s += z1mx[zi]*swc[ky*7+kx] + z1sm[zi]*(1.f/64.f)*swc[49+ky*7+kx];
        }
      }
      sg1[idx] = sigmoidf_(s*cwg + cwb);
    }
    { // g2: spatial (n=64 rows, h=8 cols)
      int n = idx>>3, h = idx&7;
      float s = 0.f;
      for (int ky=0;ky<7;ky++){
        int pn = n-3+ky; if (pn<0||pn>=64) continue;
        for (int kx=0;kx<7;kx++){
          int ph = h-3+kx; if (ph<0||ph>=8) continue;
          int zi = pn*8+ph;
          s += z2mx[zi]*swh[ky*7+kx] + z2sm[zi]*(1.f/64.f)*swh[49+ky*7+kx];
        }
      }
      sg2[idx] = sigmoidf_(s*hcg + hcb);
    }
  }
  __syncthreads();

  // ---- pass 3: per-head gated dots -> softmax -> AV ----
  int b = bp>>8, yh = (bp>>4)&15, xw = bp&15;
  for (int h=0; h<8; h++){
    const float* qp = g_qkv + ((size_t)(0*NWIN+bp)*HEADS_+h)*NTOK*HD_;
    const float* kp = g_qkv + ((size_t)(1*NWIN+bp)*HEADS_+h)*NTOK*HD_;
    const float* vp = g_qkv + ((size_t)(2*NWIN+bp)*HEADS_+h)*NTOK*HD_;
    for (int i=tid;i<1024;i+=256){ sq[i]=qp[i]; sk[i]=kp[i]; sv[i]=vp[i]; }
    __syncthreads();
    {
      const float4* q4 = (const float4*)sq;
      const float4* k4 = (const float4*)sk;
      float4 qa = q4[dn*4+0], qb = q4[dn*4+1], qc = q4[dn*4+2], qd = q4[dn*4+3];
#pragma unroll
      for (int mm=0;mm<16;mm++){
        int m = dmg + mm;
        float4 ka = k4[m*4+0], kb = k4[m*4+1], kc = k4[m*4+2], kd = k4[m*4+3];
        float s = qa.x*ka.x + qa.y*ka.y + qa.z*ka.z + qa.w*ka.w
                + qb.x*kb.x + qb.y*kb.y + qb.z*kb.z + qb.w*kb.w
                + qc.x*kc.x + qc.y*kc.y + qc.z*kc.z + qc.w*kc.w
                + qd.x*kd.x + qd.y*kd.y + qd.z*kd.z + qd.w*kd.w;
        int y2 = m>>3, x2 = m&7;
        int ridx = (y1-y2+7)*15 + (x1-x2+7);
        float val = s*0.25f + srel[ridx*HEADS_ + h];
        float gsum = sg1[h*64+m] + sg2[dn*8+h] + sg3[dn*64+m];
        sdh[dn*64+m] = val * gsum * (1.f/3.f);
      }
    }
    __syncthreads();
    if (tid < 64){
      int n = tid;
      float mx = -1e30f;
      for (int j=0;j<64;j++) mx = fmaxf(mx, sdh[n*64+((j+n)&63)]);
      float s = 0.f;
      for (int j=0;j<64;j++){
        int mi = n*64+((j+n)&63);
        float e = expf(sdh[mi]-mx); sdh[mi]=e; s+=e;
      }
      float inv = 1.f/s;
      for (int j=0;j<64;j++) sdh[n*64+((j+n)&63)] *= inv;
    }
    __syncthreads();
    for (int idx=tid; idx<1024; idx+=256){
      int n = idx>>4, d = idx&15;
      float s = 0.f;
#pragma unroll
      for (int m=0;m<64;m++) s = fmaf(sdh[n*64+m], sv[m*HD_+d], s);
      int c = h*HD_ + d;
      int y = yh*8 + (n>>3), x = xw*8 + (n&7);
      g_o[((size_t)(b*MID_+c)*H_+y)*W_+x] = s;
    }
    __syncthreads();
  }
}

// ---------------- K5: Fh@Fw gating, out = o*gmat + local --------------------
__global__ void k_gmat(){
  __shared__ float Fh[128*32];
  __shared__ float Fw[32*128];
  int bc = blockIdx.x, tid = threadIdx.x;
  const float* op = g_o + (size_t)bc*H_*W_;
  for (int idx=tid; idx<4096; idx+=256){
    { // Fw[k][w]
      int k = idx>>7, w = idx&127;
      float mx=-1e30f, sm=0.f;
#pragma unroll
      for (int j=0;j<4;j++){ float v = op[(k*4+j)*W_+w]; mx=fmaxf(mx,v); sm+=v; }
      Fw[idx] = sigmoidf_(sm*0.25f + mx);
    }
    { // Fh[y][k]
      int y = idx>>5, k = idx&31;
      float mx=-1e30f, sm=0.f;
#pragma unroll
      for (int j=0;j<4;j++){ float v = op[y*W_ + k*4+j]; mx=fmaxf(mx,v); sm+=v; }
      Fh[idx] = sigmoidf_(sm*0.25f + mx);
    }
  }
  __syncthreads();
  const float* lp = g_local + (size_t)bc*H_*W_;
  float* outp = g_out + (size_t)bc*H_*W_;
  for (int idx=tid; idx<H_*W_; idx+=256){
    int y = idx>>7, w = idx&127;
    float gm = 0.f;
#pragma unroll
    for (int k=0;k<32;k++) gm = fmaf(Fh[y*32+k], Fw[k*128+w], gm);
    outp[idx] = op[idx]*gm + lp[idx];
  }
}

// ---------------- K6: reflect-pad + depthwise 8x8 + BN (smem-tiled) ---------
__global__ void k_dw(const float* __restrict__ dww, const float* __restrict__ g,
                     const float* __restrict__ bb){
  __shared__ float s_t[23*23];
  __shared__ float sw[64];
  int tid = threadIdx.x;
  int tx = tid & 15, ty = tid >> 4;
  int bx = blockIdx.x*16, by = blockIdx.y*16;
  int bc = blockIdx.z;
  int c  = bc & 127;
  if (tid < 64) sw[tid] = dww[c*64 + tid];
  const float* op = g_out + (size_t)bc*H_*W_;
  for (int i = tid; i < 23*23; i += 256){
    int iy = i/23, ix = i - iy*23;
    int py = by-3+iy, px = bx-3+ix;
    float v = 0.f;
    if (py >= 0 && py <= 128 && px >= 0 && px <= 128){
      int ry = (py==128) ? 126 : py;
      int rx = (px==128) ? 126 : px;
      v = op[ry*W_+rx];
    }
    s_t[i] = v;
  }
  __syncthreads();
  float acc = 0.f;
#pragma unroll
  for (int ky=0;ky<8;ky++)
#pragma unroll
    for (int kx=0;kx<8;kx++)
      acc = fmaf(s_t[(ty+ky)*23 + tx+kx], sw[ky*8+kx], acc);
  g_dw[(size_t)bc*H_*W_ + (by+ty)*W_ + bx+tx] = acc*g[c] + bb[c];
}

// ---------------- K7: pointwise 1x1 128->128 -> g_proj ----------------------
__global__ void k_pw(const float* __restrict__ w){
  __shared__ float s_in[8][1024];
  __shared__ float s_w[64];
  int tid = threadIdx.x;
  int tx = tid & 31, ty = tid >> 5;
  int by = blockIdx.y;
  int b   = blockIdx.z >> 4;
  int cog = (blockIdx.z & 15) * 8;
  float acc[8][4];
#pragma unroll
  for (int co=0;co<8;co++)
#pragma unroll
    for (int j=0;j<4;j++) acc[co][j]=0.f;
  const float* in = g_dw + (size_t)b*MID_*H_*W_ + (size_t)(by*8)*W_;
  for (int c0 = 0; c0 < MID_; c0 += 8){
    for (int i = tid; i < 8192; i += 256){
      int c = i >> 10, p = i & 1023;
      s_in[c][p] = in[(size_t)(c0+c)*H_*W_ + p];
    }
    if (tid < 64) s_w[tid] = w[(size_t)(cog + (tid>>3))*MID_ + c0 + (tid&7)];
    __syncthreads();
#pragma unroll
    for (int c=0;c<8;c++){
      float v[4];
#pragma unroll
      for (int j=0;j<4;j++) v[j] = s_in[c][ty*128 + tx + 32*j];
#pragma unroll
      for (int co=0;co<8;co++){
        float wv = s_w[co*8+c];
#pragma unroll
        for (int j=0;j<4;j++) acc[co][j] = fmaf(v[j], wv, acc[co][j]);
      }
    }
    __syncthreads();
  }
  int y = by*8 + ty;
#pragma unroll
  for (int co=0;co<8;co++)
#pragma unroll
    for (int j=0;j<4;j++)
      g_proj[((size_t)(b*MID_+cog+co)*H_+y)*W_ + tx + 32*j] = acc[co][j];
}

// ---------------- K8: transposed conv (lhs_dilation=2) -> d_out -------------
__global__ void k_up(const float* __restrict__ upw, float* __restrict__ out){
  __shared__ float sw[8*128*9];
  int tid = threadIdx.x;
  int oy  = blockIdx.x;
  int b   = blockIdx.y >> 3;
  int cog = (blockIdx.y & 7) * 8;
  for (int i=tid;i<8*128*9;i+=256) sw[i] = upw[(size_t)cog*128*9 + i];
  __syncthreads();
  int ox = tid;
  float acc[8] = {0,0,0,0,0,0,0,0};
  const float* pp = g_proj + (size_t)b*MID_*H_*W_;
  for (int ky=0;ky<3;ky++){
    int t = oy+ky-1;
    if (t < 0 || t > 254 || (t & 1)) continue;
    int iy = t >> 1;
    for (int kx=0;kx<3;kx++){
      int u = ox+kx-1;
      if (u < 0 || u > 254 || (u & 1)) continue;
      int ix = u >> 1;
      int k = ky*3+kx;
      const float* ip = pp + iy*W_ + ix;
      for (int ci=0;ci<128;ci++){
        float v = ip[(size_t)ci*H_*W_];
#pragma unroll
        for (int co=0;co<8;co++) acc[co] = fmaf(v, sw[(co*128+ci)*9+k], acc[co]);
      }
    }
  }
#pragma unroll
  for (int co=0;co<8;co++)
    out[(((size_t)(b*COUT_+cog+co))*256+oy)*256+ox] = acc[co];
}

// ---------------------------------------------------------------------------
#define ATTNF_SMEM (24622*4)

extern "C" void kernel_launch(void* const* d_in, const int* in_sizes, int n_in,
                              void* d_out, int out_size){
  const float* x      = (const float*)d_in[0];
  const float* conv_w = (const float*)d_in[1];
  const float* bn1_g  = (const float*)d_in[2];
  const float* bn1_b  = (const float*)d_in[3];
  const float* qkv_w  = (const float*)d_in[4];
  const float* loc1_w = (const float*)d_in[5];
  const float* loc1_g = (const float*)d_in[6];
  const float* loc1_b = (const float*)d_in[7];
  const float* loc2_w = (const float*)d_in[8];
  const float* loc2_g = (const float*)d_in[9];
  const float* loc2_b = (const float*)d_in[10];
  const float* rel_t  = (const float*)d_in[11];
  const float* cw_w   = (const float*)d_in[12];
  const float* cw_g   = (const float*)d_in[13];
  const float* cw_b   = (const float*)d_in[14];
  const float* hc_w   = (const float*)d_in[15];
  const float* hc_g   = (const float*)d_in[16];
  const float* hc_b   = (const float*)d_in[17];
  const float* hw_w   = (const float*)d_in[18];
  const float* hw_g   = (const float*)d_in[19];
  const float* hw_b   = (const float*)d_in[20];
  const float* pdw    = (const float*)d_in[21];
  const float* pg     = (const float*)d_in[22];
  const float* pb     = (const float*)d_in[23];
  const float* ppw    = (const float*)d_in[24];
  const float* upw    = (const float*)d_in[25];
  float* out = (float*)d_out;

  cudaFuncSetAttribute(k_attnf, cudaFuncAttributeMaxDynamicSharedMemorySize, ATTNF_SMEM);

  k_conv1<<<dim3(4,4,64), 256>>>(x, conv_w, bn1_g, bn1_b);
  k_local<<<dim3(4,4,64), 256>>>(loc1_w, loc1_g, loc1_b, loc2_w, loc2_g, loc2_b);
  k_qkv  <<<dim3(1,16,192), 256>>>(qkv_w);
  k_attnf<<<1024, 256, ATTNF_SMEM>>>(rel_t, cw_w, cw_g, cw_b, hc_w, hc_g, hc_b, hw_w, hw_g, hw_b);
  k_gmat <<<512, 256>>>();
  k_dw   <<<dim3(8,8,512), 256>>>(pdw, pg, pb);
  k_pw   <<<dim3(1,16,64), 256>>>(ppw);
  k_up   <<<dim3(256, 32), 256>>>(upw, out);
}

// round 4
// speedup vs baseline: 1.3575x; 1.3246x over previous
#include <cuda_runtime.h>
#include <math.h>

#define B_    4
#define CIN_  256
#define MID_  128
#define COUT_ 64
#define H_    128
#define W_    128
#define HW_   16384
#define WS_   8
#define HEADS_ 8
#define HD_   16
#define NTOK  64
#define NWIN  1024   /* B * 16 * 16 */

// ---------------- scratch (static device memory; no allocs) ----------------
__device__ float g_h    [B_*MID_*H_*W_];
__device__ float g_local[B_*MID_*H_*W_];
__device__ float g_qkv  [3*NWIN*HEADS_*NTOK*HD_];
__device__ float g_o    [B_*MID_*H_*W_];
__device__ float g_out  [B_*MID_*H_*W_];
__device__ float g_dw   [B_*MID_*H_*W_];
__device__ float g_proj [B_*MID_*H_*W_];
__device__ float g_dummy[32];

__device__ __forceinline__ float sigmoidf_(float x){ return 1.f/(1.f+expf(-x)); }

// ---- packed f32x2 helpers --------------------------------------------------
__device__ __forceinline__ void fma2(unsigned long long& d, unsigned long long a, unsigned long long b){
  asm("fma.rn.f32x2 %0, %1, %2, %3;" : "=l"(d) : "l"(a), "l"(b), "l"(d));
}
__device__ __forceinline__ unsigned long long pk2u(unsigned int lo, unsigned int hi){
  unsigned long long d; asm("mov.b64 %0, {%1, %2};" : "=l"(d) : "r"(lo), "r"(hi)); return d;
}
__device__ __forceinline__ unsigned long long pkf(float lo, float hi){
  return pk2u(__float_as_uint(lo), __float_as_uint(hi));
}
__device__ __forceinline__ void upk(unsigned long long v, float& a, float& b){
  unsigned int lo, hi; asm("mov.b64 {%0, %1}, %2;" : "=r"(lo), "=r"(hi) : "l"(v));
  a = __uint_as_float(lo); b = __uint_as_float(hi);
}
__device__ __forceinline__ unsigned int lo32(unsigned long long v){ return (unsigned int)v; }
__device__ __forceinline__ unsigned int hi32(unsigned long long v){ return (unsigned int)(v>>32); }

// ---------------- dummy (shifts ncu capture so launch#4 = conv1) ------------
__global__ void k_nop(){ g_dummy[threadIdx.x] = 0.f; }

// ---------------- K1: conv3x3 CIN->MID (f32x2), BN folded, ReLU -------------
// tile 64x32, per thread 4x2 px (4 packed pairs), 8 couts, 2 ci per sync.
template<int CI>
__global__ void __launch_bounds__(256,2)
k_conv3(const float* __restrict__ x, const float* __restrict__ w,
        const float* __restrict__ g, const float* __restrict__ bb,
        const float* __restrict__ w1, const float* __restrict__ g1,
        const float* __restrict__ b1, float* __restrict__ outp, int relu){
  __shared__ float s_in[2][34*68];
  __shared__ unsigned long long s_w2[2][72];
  int tid = threadIdx.x;
  int tx = tid & 15, ty = tid >> 4;
  int bx = blockIdx.x*64, by = blockIdx.y*32;
  int b   = blockIdx.z >> 4;
  int cog = (blockIdx.z & 15) * 8;
  unsigned long long acc[2][2][8];
#pragma unroll
  for (int py=0;py<2;py++)
#pragma unroll
    for (int pr=0;pr<2;pr++)
#pragma unroll
      for (int co=0;co<8;co++) acc[py][pr][co]=0ULL;

  for (int ci0 = 0; ci0 < CI; ci0 += 2){
#pragma unroll
    for (int c=0;c<2;c++){
      const float* xp = x + (size_t)(b*CI+ci0+c)*HW_;
      for (int i = tid; i < 34*68; i += 256){
        int iy = i/68, ix = i - iy*68;
        int gy = by+iy-1, gx = bx+ix-1;
        s_in[c][i] = (gy>=0 && gy<H_ && gx>=0 && gx<W_ && ix<66) ? xp[gy*W_+gx] : 0.f;
      }
    }
    if (tid < 144){
      int c = tid >= 72; int t = tid - c*72;
      int co = t/9, k = t - co*9;
      float wv = g[cog+co] * w[((size_t)(cog+co)*CI+ci0+c)*9 + k];
      if (w1 && k==4) wv += g1[cog+co] * w1[(size_t)(cog+co)*CI + ci0+c];
      s_w2[c][t] = pkf(wv, wv);
    }
    __syncthreads();
#pragma unroll
    for (int c=0;c<2;c++){
      unsigned long long vp[4][5];
#pragma unroll
      for (int r=0;r<4;r++){
        const unsigned long long* rp = (const unsigned long long*)&s_in[c][(ty*2+r)*68 + tx*4];
        unsigned long long A=rp[0], Bv=rp[1], Cv=rp[2];
        vp[r][0]=A; vp[r][2]=Bv; vp[r][4]=Cv;
        vp[r][1]=pk2u(hi32(A), lo32(Bv));
        vp[r][3]=pk2u(hi32(Bv), lo32(Cv));
      }
#pragma unroll
      for (int co=0;co<8;co++){
        const unsigned long long* wp = &s_w2[c][co*9];
#pragma unroll
        for (int ky=0;ky<3;ky++)
#pragma unroll
          for (int kx=0;kx<3;kx++){
            unsigned long long wv = wp[ky*3+kx];
            fma2(acc[0][0][co], vp[ky  ][kx  ], wv);
            fma2(acc[0][1][co], vp[ky  ][kx+2], wv);
            fma2(acc[1][0][co], vp[ky+1][kx  ], wv);
            fma2(acc[1][1][co], vp[ky+1][kx+2], wv);
          }
      }
    }
    __syncthreads();
  }
  int y0 = by+ty*2, x0 = bx+tx*4;
#pragma unroll
  for (int co=0;co<8;co++){
    int c = cog+co;
    float bv = bb[c] + (w1 ? b1[c] : 0.f);
    float* op = outp + ((size_t)(b*MID_+c)*H_)*W_;
#pragma unroll
    for (int py=0;py<2;py++)
#pragma unroll
      for (int pr=0;pr<2;pr++){
        float f0,f1; upk(acc[py][pr][co], f0, f1);
        f0 += bv; f1 += bv;
        if (relu){ f0=fmaxf(f0,0.f); f1=fmaxf(f1,0.f); }
        op[(y0+py)*W_ + x0+pr*2  ] = f0;
        op[(y0+py)*W_ + x0+pr*2+1] = f1;
      }
  }
}

// ---------------- K3: 1x1 conv 128->8co (f32x2), generic store --------------
// tile: 8 rows x 128 cols (1024 px), 4 adjacent px/thread.
__global__ void k_qkv(const float* __restrict__ w){
  __shared__ float s_in[8*1024];
  __shared__ unsigned long long s_w2[64];
  int tid = threadIdx.x;
  int p0 = tid*4;
  int by = blockIdx.y;
  int b   = blockIdx.z / 48;
  int cog = (blockIdx.z % 48) * 8;
  unsigned long long acc[8][2];
#pragma unroll
  for (int co=0;co<8;co++){ acc[co][0]=0ULL; acc[co][1]=0ULL; }
  const float* in = g_h + (size_t)b*MID_*HW_ + (size_t)(by*8)*W_;
  for (int c0 = 0; c0 < MID_; c0 += 8){
    for (int i = tid; i < 2048; i += 256){
      int c = i>>8, p4 = (i&255)*4;
      *(float4*)&s_in[c*1024+p4] = *(const float4*)&in[(size_t)(c0+c)*HW_ + p4];
    }
    if (tid < 64){
      float wv = w[(size_t)(cog + (tid>>3))*MID_ + c0 + (tid&7)];
      s_w2[tid] = pkf(wv, wv);
    }
    __syncthreads();
#pragma unroll
    for (int c=0;c<8;c++){
      const unsigned long long* vp = (const unsigned long long*)&s_in[c*1024+p0];
      unsigned long long v0 = vp[0], v1 = vp[1];
#pragma unroll
      for (int co=0;co<8;co++){
        unsigned long long wv = s_w2[co*8+c];
        fma2(acc[co][0], v0, wv);
        fma2(acc[co][1], v1, wv);
      }
    }
    __syncthreads();
  }
#pragma unroll
  for (int co=0;co<8;co++){
    int c = cog+co;
    int s = c>>7, hd = (c>>4)&7, d = c&15;
#pragma unroll
    for (int pr=0;pr<2;pr++){
      float f0,f1; upk(acc[co][pr], f0, f1);
#pragma unroll
      for (int e=0;e<2;e++){
        int p = p0 + pr*2 + e;
        int y = by*8 + (p>>7), xx = p&127;
        int yh=y>>3, wy=y&7, xw=xx>>3, wx=xx&7;
        int bp = (b*16+yh)*16+xw;
        int n  = wy*8+wx;
        g_qkv[(((size_t)(s*NWIN+bp)*HEADS_+hd)*NTOK+n)*HD_ + d] = e ? f1 : f0;
      }
    }
  }
}

// ---------- K4: fused dots -> gates -> softmax -> attn@v -> g_o -------------
__global__ void k_attnf(const float* __restrict__ rel,
                        const float* __restrict__ cw_w, const float* __restrict__ cw_g, const float* __restrict__ cw_b,
                        const float* __restrict__ hc_w, const float* __restrict__ hc_g, const float* __restrict__ hc_b,
                        const float* __restrict__ hw_w, const float* __restrict__ hw_g, const float* __restrict__ hw_b){
  extern __shared__ float sm[];
  float* sq   = sm;              // 1024
  float* sk   = sq   + 1024;     // 1024
  float* sv   = sk   + 1024;     // 1024
  float* sdh  = sv   + 1024;     // 4096
  float* z3mx = sdh  + 4096;     // 4096
  float* z3sm = z3mx + 4096;     // 4096
  float* z1mx = z3sm + 4096;     // 512
  float* z1sm = z1mx + 512;      // 512
  float* z2mx = z1sm + 512;      // 512
  float* z2sm = z2mx + 512;      // 512
  float* sg1  = z2sm + 512;      // 512
  float* sg2  = sg1  + 512;      // 512
  float* sg3  = sg2  + 512;      // 4096
  float* swc  = sg3  + 4096;     // 98
  float* swh  = swc  + 98;       // 98
  float* sww  = swh  + 98;       // 98
  float* srel = sww  + 98;       // 1800

  int bp = blockIdx.x, tid = threadIdx.x;
  if (tid < 98){ swc[tid]=cw_w[tid]; swh[tid]=hc_w[tid]; sww[tid]=hw_w[tid]; }
  for (int i=tid; i<1800; i+=256) srel[i] = rel[i];

  int dn = tid >> 2;          // 0..63
  int dmg = (tid & 3) * 16;   // m group base
  int y1 = dn>>3, x1 = dn&7;

  // ---- pass 1: per-head dots -> z reductions ----
  for (int h=0; h<8; h++){
    const float* qp = g_qkv + ((size_t)(0*NWIN+bp)*HEADS_+h)*NTOK*HD_;
    const float* kp = g_qkv + ((size_t)(1*NWIN+bp)*HEADS_+h)*NTOK*HD_;
    for (int i=tid;i<1024;i+=256){ sq[i]=qp[i]; sk[i]=kp[i]; }
    __syncthreads();
    {
      const float4* q4 = (const float4*)sq;
      const float4* k4 = (const float4*)sk;
      float4 qa = q4[dn*4+0], qb = q4[dn*4+1], qc = q4[dn*4+2], qd = q4[dn*4+3];
#pragma unroll
      for (int mm=0;mm<16;mm++){
        int m = dmg + mm;
        float4 ka = k4[m*4+0], kb = k4[m*4+1], kc = k4[m*4+2], kd = k4[m*4+3];
        float s = qa.x*ka.x + qa.y*ka.y + qa.z*ka.z + qa.w*ka.w
                + qb.x*kb.x + qb.y*kb.y + qb.z*kb.z + qb.w*kb.w
                + qc.x*kc.x + qc.y*kc.y + qc.z*kc.z + qc.w*kc.w
                + qd.x*kd.x + qd.y*kd.y + qd.z*kd.z + qd.w*kd.w;
        int y2 = m>>3, x2 = m&7;
        int ridx = (y1-y2+7)*15 + (x1-x2+7);
        float val = s*0.25f + srel[ridx*HEADS_ + h];
        int idx = dn*64 + m;
        sdh[idx] = val;
        if (h == 0){ z3mx[idx] = val; z3sm[idx] = val; }
        else { z3mx[idx] = fmaxf(z3mx[idx], val); z3sm[idx] += val; }
      }
    }
    __syncthreads();
    if (tid < 64){               // z1: per (h, m), reduce over n
      int m = tid;
      float mx=-1e30f, s=0.f;
      for (int n=0;n<64;n++){ float v = sdh[n*64+m]; mx=fmaxf(mx,v); s+=v; }
      z1mx[h*64+m]=mx; z1sm[h*64+m]=s;
    } else if (tid < 128){       // z2: per (n, h), reduce over m
      int n = tid-64;
      float mx=-1e30f, s=0.f;
      for (int j=0;j<64;j++){ float v = sdh[n*64 + ((j+n)&63)]; mx=fmaxf(mx,v); s+=v; }
      z2mx[n*8+h]=mx; z2sm[n*8+h]=s;
    }
    __syncthreads();
  }

  // ---- pass 2: gate maps ----
  float hwg = hw_g[0], hwb = hw_b[0];
  float cwg = cw_g[0], cwb = cw_b[0];
  float hcg = hc_g[0], hcb = hc_b[0];
  for (int idx=tid; idx<4096; idx+=256){
    int n = idx>>6, m = idx&63;
    float s = 0.f;
    for (int ky=0;ky<7;ky++){
      int pn = n-3+ky; if (pn<0||pn>=64) continue;
      for (int kx=0;kx<7;kx++){
        int pm = m-3+kx; if (pm<0||pm>=64) continue;
        int zi = pn*64+pm;
        s += z3mx[zi]*sww[ky*7+kx] + z3sm[zi]*0.125f*sww[49+ky*7+kx];
      }
    }
    sg3[idx] = sigmoidf_(s*hwg + hwb);
  }
  for (int idx=tid; idx<512; idx+=256){
    { // g1: spatial (h=8 rows, m=64 cols)
      int h = idx>>6, m = idx&63;
      float s = 0.f;
      for (int ky=0;ky<7;ky++){
        int ph = h-3+ky; if (ph<0||ph>=8) continue;
        for (int kx=0;kx<7;kx++){
          int pm = m-3+kx; if (pm<0||pm>=64) continue;
          int zi = ph*64+pm;
          s += z1mx[zi]*swc[ky*7+kx] + z1sm[zi]*(1.f/64.f)*swc[49+ky*7+kx];
        }
      }
      sg1[idx] = sigmoidf_(s*cwg + cwb);
    }
    { // g2: spatial (n=64 rows, h=8 cols)
      int n = idx>>3, h = idx&7;
      float s = 0.f;
      for (int ky=0;ky<7;ky++){
        int pn = n-3+ky; if (pn<0||pn>=64) continue;
        for (int kx=0;kx<7;kx++){
          int ph = h-3+kx; if (ph<0||ph>=8) continue;
          int zi = pn*8+ph;
          s += z2mx[zi]*swh[ky*7+kx] + z2sm[zi]*(1.f/64.f)*swh[49+ky*7+kx];
        }
      }
      sg2[idx] = sigmoidf_(s*hcg + hcb);
    }
  }
  __syncthreads();

  // ---- pass 3: per-head gated dots -> softmax -> AV ----
  int b = bp>>8, yh = (bp>>4)&15, xw = bp&15;
  for (int h=0; h<8; h++){
    const float* qp = g_qkv + ((size_t)(0*NWIN+bp)*HEADS_+h)*NTOK*HD_;
    const float* kp = g_qkv + ((size_t)(1*NWIN+bp)*HEADS_+h)*NTOK*HD_;
    const float* vp = g_qkv + ((size_t)(2*NWIN+bp)*HEADS_+h)*NTOK*HD_;
    for (int i=tid;i<1024;i+=256){ sq[i]=qp[i]; sk[i]=kp[i]; sv[i]=vp[i]; }
    __syncthreads();
    {
      const float4* q4 = (const float4*)sq;
      const float4* k4 = (const float4*)sk;
      float4 qa = q4[dn*4+0], qb = q4[dn*4+1], qc = q4[dn*4+2], qd = q4[dn*4+3];
#pragma unroll
      for (int mm=0;mm<16;mm++){
        int m = dmg + mm;
        float4 ka = k4[m*4+0], kb = k4[m*4+1], kc = k4[m*4+2], kd = k4[m*4+3];
        float s = qa.x*ka.x + qa.y*ka.y + qa.z*ka.z + qa.w*ka.w
                + qb.x*kb.x + qb.y*kb.y + qb.z*kb.z + qb.w*kb.w
                + qc.x*kc.x + qc.y*kc.y + qc.z*kc.z + qc.w*kc.w
                + qd.x*kd.x + qd.y*kd.y + qd.z*kd.z + qd.w*kd.w;
        int y2 = m>>3, x2 = m&7;
        int ridx = (y1-y2+7)*15 + (x1-x2+7);
        float val = s*0.25f + srel[ridx*HEADS_ + h];
        float gsum = sg1[h*64+m] + sg2[dn*8+h] + sg3[dn*64+m];
        sdh[dn*64+m] = val * gsum * (1.f/3.f);
      }
    }
    __syncthreads();
    if (tid < 64){
      int n = tid;
      float mx = -1e30f;
      for (int j=0;j<64;j++) mx = fmaxf(mx, sdh[n*64+((j+n)&63)]);
      float s = 0.f;
      for (int j=0;j<64;j++){
        int mi = n*64+((j+n)&63);
        float e = expf(sdh[mi]-mx); sdh[mi]=e; s+=e;
      }
      float inv = 1.f/s;
      for (int j=0;j<64;j++) sdh[n*64+((j+n)&63)] *= inv;
    }
    __syncthreads();
    for (int idx=tid; idx<1024; idx+=256){
      int n = idx>>4, d = idx&15;
      float s = 0.f;
#pragma unroll
      for (int m=0;m<64;m++) s = fmaf(sdh[n*64+m], sv[m*HD_+d], s);
      int c = h*HD_ + d;
      int y = yh*8 + (n>>3), x = xw*8 + (n&7);
      g_o[((size_t)(b*MID_+c)*H_+y)*W_+x] = s;
    }
    __syncthreads();
  }
}

// ---------------- K5: Fh@Fw gating, out = o*gmat + local --------------------
__global__ void k_gmat(){
  __shared__ float Fh[128*32];
  __shared__ float Fw[32*128];
  int bc = blockIdx.x, tid = threadIdx.x;
  const float* op = g_o + (size_t)bc*HW_;
  for (int idx=tid; idx<4096; idx+=256){
    { // Fw[k][w]
      int k = idx>>7, w = idx&127;
      float mx=-1e30f, sm_=0.f;
#pragma unroll
      for (int j=0;j<4;j++){ float v = op[(k*4+j)*W_+w]; mx=fmaxf(mx,v); sm_+=v; }
      Fw[idx] = sigmoidf_(sm_*0.25f + mx);
    }
    { // Fh[y][k]
      int y = idx>>5, k = idx&31;
      float mx=-1e30f, sm_=0.f;
#pragma unroll
      for (int j=0;j<4;j++){ float v = op[y*W_ + k*4+j]; mx=fmaxf(mx,v); sm_+=v; }
      Fh[idx] = sigmoidf_(sm_*0.25f + mx);
    }
  }
  __syncthreads();
  const float* lp = g_local + (size_t)bc*HW_;
  float* outp = g_out + (size_t)bc*HW_;
  for (int idx=tid; idx<HW_; idx+=256){
    int y = idx>>7, w = idx&127;
    float gm = 0.f;
#pragma unroll
    for (int k=0;k<32;k++) gm = fmaf(Fh[y*32+k], Fw[k*128+w], gm);
    outp[idx] = op[idx]*gm + lp[idx];
  }
}

// ---------------- K6: reflect-pad + depthwise 8x8 + BN (smem-tiled) ---------
__global__ void k_dw(const float* __restrict__ dww, const float* __restrict__ g,
                     const float* __restrict__ bb){
  __shared__ float s_t[23*23];
  __shared__ float sw[64];
  int tid = threadIdx.x;
  int tx = tid & 15, ty = tid >> 4;
  int bx = blockIdx.x*16, by = blockIdx.y*16;
  int bc = blockIdx.z;
  int c  = bc & 127;
  if (tid < 64) sw[tid] = dww[c*64 + tid];
  const float* op = g_out + (size_t)bc*HW_;
  for (int i = tid; i < 23*23; i += 256){
    int iy = i/23, ix = i - iy*23;
    int py = by-3+iy, px = bx-3+ix;
    float v = 0.f;
    if (py >= 0 && py <= 128 && px >= 0 && px <= 128){
      int ry = (py==128) ? 126 : py;
      int rx = (px==128) ? 126 : px;
      v = op[ry*W_+rx];
    }
    s_t[i] = v;
  }
  __syncthreads();
  float acc = 0.f;
#pragma unroll
  for (int ky=0;ky<8;ky++)
#pragma unroll
    for (int kx=0;kx<8;kx++)
      acc = fmaf(s_t[(ty+ky)*23 + tx+kx], sw[ky*8+kx], acc);
  g_dw[(size_t)bc*HW_ + (by+ty)*W_ + bx+tx] = acc*g[c] + bb[c];
}

// ---------------- K7: pointwise 1x1 128->128 (f32x2) -> g_proj --------------
__global__ void k_pw(const float* __restrict__ w){
  __shared__ float s_in[8*1024];
  __shared__ unsigned long long s_w2[64];
  int tid = threadIdx.x;
  int p0 = tid*4;
  int by = blockIdx.y;
  int b   = blockIdx.z >> 4;
  int cog = (blockIdx.z & 15) * 8;
  unsigned long long acc[8][2];
#pragma unroll
  for (int co=0;co<8;co++){ acc[co][0]=0ULL; acc[co][1]=0ULL; }
  const float* in = g_dw + (size_t)b*MID_*HW_ + (size_t)(by*8)*W_;
  for (int c0 = 0; c0 < MID_; c0 += 8){
    for (int i = tid; i < 2048; i += 256){
      int c = i>>8, p4 = (i&255)*4;
      *(float4*)&s_in[c*1024+p4] = *(const float4*)&in[(size_t)(c0+c)*HW_ + p4];
    }
    if (tid < 64){
      float wv = w[(size_t)(cog + (tid>>3))*MID_ + c0 + (tid&7)];
      s_w2[tid] = pkf(wv, wv);
    }
    __syncthreads();
#pragma unroll
    for (int c=0;c<8;c++){
      const unsigned long long* vp = (const unsigned long long*)&s_in[c*1024+p0];
      unsigned long long v0 = vp[0], v1 = vp[1];
#pragma unroll
      for (int co=0;co<8;co++){
        unsigned long long wv = s_w2[co*8+c];
        fma2(acc[co][0], v0, wv);
        fma2(acc[co][1], v1, wv);
      }
    }
    __syncthreads();
  }
  float* op = g_proj + (size_t)(b*MID_+cog)*HW_ + by*1024;
#pragma unroll
  for (int co=0;co<8;co++){
    float f0,f1,f2,f3;
    upk(acc[co][0], f0, f1);
    upk(acc[co][1], f2, f3);
    float4 r = make_float4(f0,f1,f2,f3);
    *(float4*)&op[(size_t)co*HW_ + p0] = r;
  }
}

// ---------------- K8: transposed conv (lhs_dilation=2), parity-split --------
__global__ void k_up(const float* __restrict__ upw, float* __restrict__ out){
  __shared__ float sw[1152*8];   // [ci*9+k][co]
  int tid = threadIdx.x;
  int oy0 = blockIdx.x*4;
  int b   = blockIdx.y >> 3;
  int cog = (blockIdx.y & 7) * 8;
  for (int i=tid;i<9216;i+=256){
    int co = i/1152, rem = i - co*1152;
    sw[rem*8+co] = upw[(size_t)(cog+co)*1152 + rem];
  }
  __syncthreads();
  int odd = tid >= 128;
  int t   = odd ? tid-128 : tid;
  int ox  = 2*t + odd;
  int ixs[2], kxs[2]; int nix;
  if (odd){
    ixs[0]=(ox-1)>>1; kxs[0]=0; nix=1;
    if (ox+1<=254){ ixs[1]=(ox+1)>>1; kxs[1]=2; nix=2; }
  } else {
    ixs[0]=ox>>1; kxs[0]=1; nix=1;
  }
  const float* pp = g_proj + (size_t)b*MID_*HW_;
  for (int oyl=0; oyl<4; oyl++){
    int oy = oy0 + oyl;
    int iys[2], kys[2]; int niy;
    if (oy & 1){
      iys[0]=(oy-1)>>1; kys[0]=0; niy=1;
      if (oy+1<=254){ iys[1]=(oy+1)>>1; kys[1]=2; niy=2; }
    } else {
      iys[0]=oy>>1; kys[0]=1; niy=1;
    }
    unsigned long long acc[4] = {0ULL,0ULL,0ULL,0ULL};
    for (int a=0;a<niy;a++){
      for (int e=0;e<nix;e++){
        const float* ip = pp + iys[a]*W_ + ixs[e];
        int kbase = kys[a]*3 + kxs[e];
#pragma unroll 4
        for (int ci=0; ci<128; ci++){
          float v = ip[(size_t)ci*HW_];
          unsigned long long vv = pkf(v, v);
          const unsigned long long* wp = (const unsigned long long*)&sw[(ci*9+kbase)*8];
          fma2(acc[0], vv, wp[0]);
          fma2(acc[1], vv, wp[1]);
          fma2(acc[2], vv, wp[2]);
          fma2(acc[3], vv, wp[3]);
        }
      }
    }
#pragma unroll
    for (int j=0;j<4;j++){
      float f0,f1; upk(acc[j], f0, f1);
      out[(((size_t)(b*COUT_+cog+2*j  ))*256+oy)*256+ox] = f0;
      out[(((size_t)(b*COUT_+cog+2*j+1))*256+oy)*256+ox] = f1;
    }
  }
}

// ---------------------------------------------------------------------------
#define ATTNF_SMEM (24622*4)

extern "C" void kernel_launch(void* const* d_in, const int* in_sizes, int n_in,
                              void* d_out, int out_size){
  const float* x      = (const float*)d_in[0];
  const float* conv_w = (const float*)d_in[1];
  const float* bn1_g  = (const float*)d_in[2];
  const float* bn1_b  = (const float*)d_in[3];
  const float* qkv_w  = (const float*)d_in[4];
  const float* loc1_w = (const float*)d_in[5];
  const float* loc1_g = (const float*)d_in[6];
  const float* loc1_b = (const float*)d_in[7];
  const float* loc2_w = (const float*)d_in[8];
  const float* loc2_g = (const float*)d_in[9];
  const float* loc2_b = (const float*)d_in[10];
  const float* rel_t  = (const float*)d_in[11];
  const float* cw_w   = (const float*)d_in[12];
  const float* cw_g   = (const float*)d_in[13];
  const float* cw_b   = (const float*)d_in[14];
  const float* hc_w   = (const float*)d_in[15];
  const float* hc_g   = (const float*)d_in[16];
  const float* hc_b   = (const float*)d_in[17];
  const float* hw_w   = (const float*)d_in[18];
  const float* hw_g   = (const float*)d_in[19];
  const float* hw_b   = (const float*)d_in[20];
  const float* pdw    = (const float*)d_in[21];
  const float* pg     = (const float*)d_in[22];
  const float* pb     = (const float*)d_in[23];
  const float* ppw    = (const float*)d_in[24];
  const float* upw    = (const float*)d_in[25];
  float* out = (float*)d_out;

  cudaFuncSetAttribute(k_attnf, cudaFuncAttributeMaxDynamicSharedMemorySize, ATTNF_SMEM);

  float* g_h_p;     cudaGetSymbolAddress((void**)&g_h_p, g_h);
  float* g_local_p; cudaGetSymbolAddress((void**)&g_local_p, g_local);

  // 3 no-op launches so ncu's captured launch (#4) is k_conv3<CIN_> (conv1)
  k_nop<<<1,32>>>();
  k_nop<<<1,32>>>();
  k_nop<<<1,32>>>();
  k_conv3<CIN_><<<dim3(2,4,64), 256>>>(x, conv_w, bn1_g, bn1_b,
                                       (const float*)0, (const float*)0, (const float*)0,
                                       g_h_p, 1);
  k_conv3<MID_><<<dim3(2,4,64), 256>>>(g_h_p, loc1_w, loc1_g, loc1_b,
                                       loc2_w, loc2_g, loc2_b,
                                       g_local_p, 0);
  k_qkv  <<<dim3(1,16,192), 256>>>(qkv_w);
  k_attnf<<<1024, 256, ATTNF_SMEM>>>(rel_t, cw_w, cw_g, cw_b, hc_w, hc_g, hc_b, hw_w, hw_g, hw_b);
  k_gmat <<<512, 256>>>();
  k_dw   <<<dim3(8,8,512), 256>>>(pdw, pg, pb);
  k_pw   <<<dim3(1,16,64), 256>>>(ppw);
  k_up   <<<dim3(64, 32), 256>>>(upw, out);
}

// round 5
// speedup vs baseline: 1.5505x; 1.1422x over previous
#include <cuda_runtime.h>
#include <math.h>

#define B_    4
#define CIN_  256
#define MID_  128
#define COUT_ 64
#define H_    128
#define W_    128
#define HW_   16384
#define WS_   8
#define HEADS_ 8
#define HD_   16
#define NTOK  64
#define NWIN  1024   /* B * 16 * 16 */

// ---------------- scratch (static device memory; no allocs) ----------------
__device__ float g_h    [B_*MID_*H_*W_];
__device__ float g_local[B_*MID_*H_*W_];
__device__ float g_qkv  [3*NWIN*HEADS_*NTOK*HD_];
__device__ float g_o    [B_*MID_*H_*W_];
__device__ float g_out  [B_*MID_*H_*W_];
__device__ float g_dw   [B_*MID_*H_*W_];
__device__ float g_proj [B_*MID_*H_*W_];   // pixel-major: [b][p][c]
__device__ float g_dummy[32];

__device__ __forceinline__ float sigmoidf_(float x){ return 1.f/(1.f+expf(-x)); }

// ---- packed f32x2 helpers --------------------------------------------------
__device__ __forceinline__ void fma2(unsigned long long& d, unsigned long long a, unsigned long long b){
  asm("fma.rn.f32x2 %0, %1, %2, %3;" : "=l"(d) : "l"(a), "l"(b), "l"(d));
}
__device__ __forceinline__ unsigned long long pk2u(unsigned int lo, unsigned int hi){
  unsigned long long d; asm("mov.b64 %0, {%1, %2};" : "=l"(d) : "r"(lo), "r"(hi)); return d;
}
__device__ __forceinline__ unsigned long long pkf(float lo, float hi){
  return pk2u(__float_as_uint(lo), __float_as_uint(hi));
}
__device__ __forceinline__ void upk(unsigned long long v, float& a, float& b){
  unsigned int lo, hi; asm("mov.b64 {%0, %1}, %2;" : "=r"(lo), "=r"(hi) : "l"(v));
  a = __uint_as_float(lo); b = __uint_as_float(hi);
}
__device__ __forceinline__ unsigned int lo32(unsigned long long v){ return (unsigned int)v; }
__device__ __forceinline__ unsigned int hi32(unsigned long long v){ return (unsigned int)(v>>32); }

// ---------------- dummy (shifts ncu capture so launch#4 = conv1) ------------
__global__ void k_nop(){ g_dummy[threadIdx.x] = 0.f; }

// ---------------- K1: conv3x3 CI->MID (f32x2), BN folded, ReLU --------------
// tile 64x32, per thread 4x2 px (4 packed pairs), 8 couts, 4 ci per sync.
// Fill addressing hoisted out of ci loop; boundary zeros written once.
template<int CI>
__global__ void __launch_bounds__(256,2)
k_conv3(const float* __restrict__ x, const float* __restrict__ w,
        const float* __restrict__ g, const float* __restrict__ bb,
        const float* __restrict__ w1, const float* __restrict__ g1,
        const float* __restrict__ b1, float* __restrict__ outp, int relu){
  __shared__ float s_in[4][34*68];
  __shared__ unsigned long long s_w2[4][72];
  int tid = threadIdx.x;
  int tx = tid & 15, ty = tid >> 4;
  int bx = blockIdx.x*64, by = blockIdx.y*32;
  int b   = blockIdx.z >> 4;
  int cog = (blockIdx.z & 15) * 8;

  // ---- fill-slot precompute + one-time boundary zeroing ----
  int off[10];
#pragma unroll
  for (int s=0;s<10;s++){
    int i = tid + 256*s;
    if (i < 2312){
      int iy = i/68, ix = i - iy*68;
      int gy = by+iy-1, gx = bx+ix-1;
      bool inb = (gy>=0 && gy<H_ && gx>=0 && gx<W_ && ix<66);
      off[s] = inb ? (gy*W_+gx) : -1;
      if (!inb){ s_in[0][i]=0.f; s_in[1][i]=0.f; s_in[2][i]=0.f; s_in[3][i]=0.f; }
    } else off[s] = -1;
  }

  // ---- weight-slot precompute (two slots cover 288 entries) ----
  int c0 = tid/72, r0 = tid - c0*72, co0 = r0/9, k0 = r0 - co0*9;
  int t1 = tid + 256;
  int c1 = t1/72, r1 = t1 - c1*72, co1 = r1/9, k1 = r1 - co1*9;
  bool has1 = (t1 < 288);
  float gA  = g[cog+co0];
  float g1A = w1 ? g1[cog+co0] : 0.f;
  float gB  = has1 ? g[cog+co1] : 0.f;
  float g1B = (w1 && has1) ? g1[cog+co1] : 0.f;
  size_t wofs0  = ((size_t)(cog+co0)*CI + c0)*9 + k0;
  size_t w1ofs0 = (size_t)(cog+co0)*CI + c0;
  size_t wofs1  = has1 ? (((size_t)(cog+co1)*CI + c1)*9 + k1) : 0;
  size_t w1ofs1 = has1 ? ((size_t)(cog+co1)*CI + c1) : 0;

  unsigned long long acc[2][2][8];
#pragma unroll
  for (int py=0;py<2;py++)
#pragma unroll
    for (int pr=0;pr<2;pr++)
#pragma unroll
      for (int co=0;co<8;co++) acc[py][pr][co]=0ULL;

  for (int ci0 = 0; ci0 < CI; ci0 += 4){
#pragma unroll
    for (int c=0;c<4;c++){
      const float* xp = x + (size_t)(b*CI+ci0+c)*HW_;
#pragma unroll
      for (int s=0;s<10;s++)
        if (off[s] >= 0) s_in[c][tid+256*s] = xp[off[s]];
    }
    {
      float wv = gA * w[wofs0 + (size_t)ci0*9];
      if (w1 && k0==4) wv += g1A * w1[w1ofs0 + ci0];
      s_w2[c0][r0] = pkf(wv, wv);
      if (has1){
        float wv1 = gB * w[wofs1 + (size_t)ci0*9];
        if (w1 && k1==4) wv1 += g1B * w1[w1ofs1 + ci0];
        s_w2[c1][r1] = pkf(wv1, wv1);
      }
    }
    __syncthreads();
#pragma unroll
    for (int c=0;c<4;c++){
      unsigned long long vp[4][5];
#pragma unroll
      for (int r=0;r<4;r++){
        const unsigned long long* rp = (const unsigned long long*)&s_in[c][(ty*2+r)*68 + tx*4];
        unsigned long long A=rp[0], Bv=rp[1], Cv=rp[2];
        vp[r][0]=A; vp[r][2]=Bv; vp[r][4]=Cv;
        vp[r][1]=pk2u(hi32(A), lo32(Bv));
        vp[r][3]=pk2u(hi32(Bv), lo32(Cv));
      }
#pragma unroll
      for (int co=0;co<8;co++){
        const unsigned long long* wp = &s_w2[c][co*9];
#pragma unroll
        for (int ky=0;ky<3;ky++)
#pragma unroll
          for (int kx=0;kx<3;kx++){
            unsigned long long wv = wp[ky*3+kx];
            fma2(acc[0][0][co], vp[ky  ][kx  ], wv);
            fma2(acc[0][1][co], vp[ky  ][kx+2], wv);
            fma2(acc[1][0][co], vp[ky+1][kx  ], wv);
            fma2(acc[1][1][co], vp[ky+1][kx+2], wv);
          }
      }
    }
    __syncthreads();
  }
  int y0 = by+ty*2, x0 = bx+tx*4;
#pragma unroll
  for (int co=0;co<8;co++){
    int c = cog+co;
    float bv = bb[c] + (w1 ? b1[c] : 0.f);
    float* op = outp + ((size_t)(b*MID_+c)*H_)*W_;
#pragma unroll
    for (int py=0;py<2;py++)
#pragma unroll
      for (int pr=0;pr<2;pr++){
        float f0,f1; upk(acc[py][pr][co], f0, f1);
        f0 += bv; f1 += bv;
        if (relu){ f0=fmaxf(f0,0.f); f1=fmaxf(f1,0.f); }
        op[(y0+py)*W_ + x0+pr*2  ] = f0;
        op[(y0+py)*W_ + x0+pr*2+1] = f1;
      }
  }
}

// ---------------- K3: 1x1 conv 128->8co (f32x2), windowed store -------------
__global__ void k_qkv(const float* __restrict__ w){
  __shared__ float s_in[8*1024];
  __shared__ unsigned long long s_w2[64];
  int tid = threadIdx.x;
  int p0 = tid*4;
  int by = blockIdx.y;
  int b   = blockIdx.z / 48;
  int cog = (blockIdx.z % 48) * 8;
  unsigned long long acc[8][2];
#pragma unroll
  for (int co=0;co<8;co++){ acc[co][0]=0ULL; acc[co][1]=0ULL; }
  const float* in = g_h + (size_t)b*MID_*HW_ + (size_t)(by*8)*W_;
  for (int c0 = 0; c0 < MID_; c0 += 8){
    for (int i = tid; i < 2048; i += 256){
      int c = i>>8, p4 = (i&255)*4;
      *(float4*)&s_in[c*1024+p4] = *(const float4*)&in[(size_t)(c0+c)*HW_ + p4];
    }
    if (tid < 64){
      float wv = w[(size_t)(cog + (tid>>3))*MID_ + c0 + (tid&7)];
      s_w2[tid] = pkf(wv, wv);
    }
    __syncthreads();
#pragma unroll
    for (int c=0;c<8;c++){
      const unsigned long long* vp = (const unsigned long long*)&s_in[c*1024+p0];
      unsigned long long v0 = vp[0], v1 = vp[1];
#pragma unroll
      for (int co=0;co<8;co++){
        unsigned long long wv = s_w2[co*8+c];
        fma2(acc[co][0], v0, wv);
        fma2(acc[co][1], v1, wv);
      }
    }
    __syncthreads();
  }
#pragma unroll
  for (int co=0;co<8;co++){
    int c = cog+co;
    int s = c>>7, hd = (c>>4)&7, d = c&15;
#pragma unroll
    for (int pr=0;pr<2;pr++){
      float f0,f1; upk(acc[co][pr], f0, f1);
#pragma unroll
      for (int e=0;e<2;e++){
        int p = p0 + pr*2 + e;
        int y = by*8 + (p>>7), xx = p&127;
        int yh=y>>3, wy=y&7, xw=xx>>3, wx=xx&7;
        int bp = (b*16+yh)*16+xw;
        int n  = wy*8+wx;
        g_qkv[(((size_t)(s*NWIN+bp)*HEADS_+hd)*NTOK+n)*HD_ + d] = e ? f1 : f0;
      }
    }
  }
}

// ---------- K4: fused dots -> gates -> softmax -> attn@v -> g_o -------------
__global__ void k_attnf(const float* __restrict__ rel,
                        const float* __restrict__ cw_w, const float* __restrict__ cw_g, const float* __restrict__ cw_b,
                        const float* __restrict__ hc_w, const float* __restrict__ hc_g, const float* __restrict__ hc_b,
                        const float* __restrict__ hw_w, const float* __restrict__ hw_g, const float* __restrict__ hw_b){
  extern __shared__ float sm[];
  float* sq   = sm;              // 1024
  float* sk   = sq   + 1024;     // 1024
  float* sv   = sk   + 1024;     // 1024
  float* sdh  = sv   + 1024;     // 4096
  float* z3mx = sdh  + 4096;     // 4096
  float* z3sm = z3mx + 4096;     // 4096
  float* z1mx = z3sm + 4096;     // 512
  float* z1sm = z1mx + 512;      // 512
  float* z2mx = z1sm + 512;      // 512
  float* z2sm = z2mx + 512;      // 512
  float* sg1  = z2sm + 512;      // 512
  float* sg2  = sg1  + 512;      // 512
  float* sg3  = sg2  + 512;      // 4096
  float* swc  = sg3  + 4096;     // 98
  float* swh  = swc  + 98;       // 98
  float* sww  = swh  + 98;       // 98
  float* srel = sww  + 98;       // 1800

  int bp = blockIdx.x, tid = threadIdx.x;
  if (tid < 98){ swc[tid]=cw_w[tid]; swh[tid]=hc_w[tid]; sww[tid]=hw_w[tid]; }
  for (int i=tid; i<1800; i+=256) srel[i] = rel[i];

  int dn = tid >> 2;          // 0..63
  int dmg = (tid & 3) * 16;   // m group base
  int y1 = dn>>3, x1 = dn&7;

  // ---- pass 1: per-head dots -> z reductions ----
  for (int h=0; h<8; h++){
    const float* qp = g_qkv + ((size_t)(0*NWIN+bp)*HEADS_+h)*NTOK*HD_;
    const float* kp = g_qkv + ((size_t)(1*NWIN+bp)*HEADS_+h)*NTOK*HD_;
    for (int i=tid;i<1024;i+=256){ sq[i]=qp[i]; sk[i]=kp[i]; }
    __syncthreads();
    {
      const float4* q4 = (const float4*)sq;
      const float4* k4 = (const float4*)sk;
      float4 qa = q4[dn*4+0], qb = q4[dn*4+1], qc = q4[dn*4+2], qd = q4[dn*4+3];
#pragma unroll
      for (int mm=0;mm<16;mm++){
        int m = dmg + mm;
        float4 ka = k4[m*4+0], kb = k4[m*4+1], kc = k4[m*4+2], kd = k4[m*4+3];
        float s = qa.x*ka.x + qa.y*ka.y + qa.z*ka.z + qa.w*ka.w
                + qb.x*kb.x + qb.y*kb.y + qb.z*kb.z + qb.w*kb.w
                + qc.x*kc.x + qc.y*kc.y + qc.z*kc.z + qc.w*kc.w
                + qd.x*kd.x + qd.y*kd.y + qd.z*kd.z + qd.w*kd.w;
        int y2 = m>>3, x2 = m&7;
        int ridx = (y1-y2+7)*15 + (x1-x2+7);
        float val = s*0.25f + srel[ridx*HEADS_ + h];
        int idx = dn*64 + m;
        sdh[idx] = val;
        if (h == 0){ z3mx[idx] = val; z3sm[idx] = val; }
        else { z3mx[idx] = fmaxf(z3mx[idx], val); z3sm[idx] += val; }
      }
    }
    __syncthreads();
    if (tid < 64){               // z1: per (h, m), reduce over n
      int m = tid;
      float mx=-1e30f, s=0.f;
      for (int n=0;n<64;n++){ float v = sdh[n*64+m]; mx=fmaxf(mx,v); s+=v; }
      z1mx[h*64+m]=mx; z1sm[h*64+m]=s;
    } else if (tid < 128){       // z2: per (n, h), reduce over m
      int n = tid-64;
      float mx=-1e30f, s=0.f;
      for (int j=0;j<64;j++){ float v = sdh[n*64 + ((j+n)&63)]; mx=fmaxf(mx,v); s+=v; }
      z2mx[n*8+h]=mx; z2sm[n*8+h]=s;
    }
    __syncthreads();
  }

  // ---- pass 2: gate maps ----
  float hwg = hw_g[0], hwb = hw_b[0];
  float cwg = cw_g[0], cwb = cw_b[0];
  float hcg = hc_g[0], hcb = hc_b[0];
  for (int idx=tid; idx<4096; idx+=256){
    int n = idx>>6, m = idx&63;
    float s = 0.f;
    for (int ky=0;ky<7;ky++){
      int pn = n-3+ky; if (pn<0||pn>=64) continue;
      for (int kx=0;kx<7;kx++){
        int pm = m-3+kx; if (pm<0||pm>=64) continue;
        int zi = pn*64+pm;
        s += z3mx[zi]*sww[ky*7+kx] + z3sm[zi]*0.125f*sww[49+ky*7+kx];
      }
    }
    sg3[idx] = sigmoidf_(s*hwg + hwb);
  }
  for (int idx=tid; idx<512; idx+=256){
    { // g1: spatial (h=8 rows, m=64 cols)
      int h = idx>>6, m = idx&63;
      float s = 0.f;
      for (int ky=0;ky<7;ky++){
        int ph = h-3+ky; if (ph<0||ph>=8) continue;
        for (int kx=0;kx<7;kx++){
          int pm = m-3+kx; if (pm<0||pm>=64) continue;
          int zi = ph*64+pm;
          s += z1mx[zi]*swc[ky*7+kx] + z1sm[zi]*(1.f/64.f)*swc[49+ky*7+kx];
        }
      }
      sg1[idx] = sigmoidf_(s*cwg + cwb);
    }
    { // g2: spatial (n=64 rows, h=8 cols)
      int n = idx>>3, h = idx&7;
      float s = 0.f;
      for (int ky=0;ky<7;ky++){
        int pn = n-3+ky; if (pn<0||pn>=64) continue;
        for (int kx=0;kx<7;kx++){
          int ph = h-3+kx; if (ph<0||ph>=8) continue;
          int zi = pn*8+ph;
          s += z2mx[zi]*swh[ky*7+kx] + z2sm[zi]*(1.f/64.f)*swh[49+ky*7+kx];
        }
      }
      sg2[idx] = sigmoidf_(s*hcg + hcb);
    }
  }
  __syncthreads();

  // ---- pass 3: per-head gated dots -> softmax -> AV ----
  int b = bp>>8, yh = (bp>>4)&15, xw = bp&15;
  for (int h=0; h<8; h++){
    const float* qp = g_qkv + ((size_t)(0*NWIN+bp)*HEADS_+h)*NTOK*HD_;
    const float* kp = g_qkv + ((size_t)(1*NWIN+bp)*HEADS_+h)*NTOK*HD_;
    const float* vp = g_qkv + ((size_t)(2*NWIN+bp)*HEADS_+h)*NTOK*HD_;
    for (int i=tid;i<1024;i+=256){ sq[i]=qp[i]; sk[i]=kp[i]; sv[i]=vp[i]; }
    __syncthreads();
    {
      const float4* q4 = (const float4*)sq;
      const float4* k4 = (const float4*)sk;
      float4 qa = q4[dn*4+0], qb = q4[dn*4+1], qc = q4[dn*4+2], qd = q4[dn*4+3];
#pragma unroll
      for (int mm=0;mm<16;mm++){
        int m = dmg + mm;
        float4 ka = k4[m*4+0], kb = k4[m*4+1], kc = k4[m*4+2], kd = k4[m*4+3];
        float s = qa.x*ka.x + qa.y*ka.y + qa.z*ka.z + qa.w*ka.w
                + qb.x*kb.x + qb.y*kb.y + qb.z*kb.z + qb.w*kb.w
                + qc.x*kc.x + qc.y*kc.y + qc.z*kc.z + qc.w*kc.w
                + qd.x*kd.x + qd.y*kd.y + qd.z*kd.z + qd.w*kd.w;
        int y2 = m>>3, x2 = m&7;
        int ridx = (y1-y2+7)*15 + (x1-x2+7);
        float val = s*0.25f + srel[ridx*HEADS_ + h];
        float gsum = sg1[h*64+m] + sg2[dn*8+h] + sg3[dn*64+m];
        sdh[dn*64+m] = val * gsum * (1.f/3.f);
      }
    }
    __syncthreads();
    if (tid < 64){
      int n = tid;
      float mx = -1e30f;
      for (int j=0;j<64;j++) mx = fmaxf(mx, sdh[n*64+((j+n)&63)]);
      float s = 0.f;
      for (int j=0;j<64;j++){
        int mi = n*64+((j+n)&63);
        float e = expf(sdh[mi]-mx); sdh[mi]=e; s+=e;
      }
      float inv = 1.f/s;
      for (int j=0;j<64;j++) sdh[n*64+((j+n)&63)] *= inv;
    }
    __syncthreads();
    for (int idx=tid; idx<1024; idx+=256){
      int n = idx>>4, d = idx&15;
      float s = 0.f;
#pragma unroll
      for (int m=0;m<64;m++) s = fmaf(sdh[n*64+m], sv[m*HD_+d], s);
      int c = h*HD_ + d;
      int y = yh*8 + (n>>3), x = xw*8 + (n&7);
      g_o[((size_t)(b*MID_+c)*H_+y)*W_+x] = s;
    }
    __syncthreads();
  }
}

// ---------------- K5: Fh@Fw gating, out = o*gmat + local --------------------
__global__ void k_gmat(){
  __shared__ float Fh[128*32];
  __shared__ float Fw[32*128];
  int bc = blockIdx.x, tid = threadIdx.x;
  const float* op = g_o + (size_t)bc*HW_;
  for (int idx=tid; idx<4096; idx+=256){
    { // Fw[k][w]
      int k = idx>>7, w = idx&127;
      float mx=-1e30f, sm_=0.f;
#pragma unroll
      for (int j=0;j<4;j++){ float v = op[(k*4+j)*W_+w]; mx=fmaxf(mx,v); sm_+=v; }
      Fw[idx] = sigmoidf_(sm_*0.25f + mx);
    }
    { // Fh[y][k]
      int y = idx>>5, k = idx&31;
      float mx=-1e30f, sm_=0.f;
#pragma unroll
      for (int j=0;j<4;j++){ float v = op[y*W_ + k*4+j]; mx=fmaxf(mx,v); sm_+=v; }
      Fh[idx] = sigmoidf_(sm_*0.25f + mx);
    }
  }
  __syncthreads();
  const float* lp = g_local + (size_t)bc*HW_;
  float* outp = g_out + (size_t)bc*HW_;
  for (int idx=tid; idx<HW_; idx+=256){
    int y = idx>>7, w = idx&127;
    float gm = 0.f;
#pragma unroll
    for (int k=0;k<32;k++) gm = fmaf(Fh[y*32+k], Fw[k*128+w], gm);
    outp[idx] = op[idx]*gm + lp[idx];
  }
}

// ---------------- K6: reflect-pad + depthwise 8x8 + BN (smem-tiled) ---------
__global__ void k_dw(const float* __restrict__ dww, const float* __restrict__ g,
                     const float* __restrict__ bb){
  __shared__ float s_t[23*23];
  __shared__ float sw[64];
  int tid = threadIdx.x;
  int tx = tid & 15, ty = tid >> 4;
  int bx = blockIdx.x*16, by = blockIdx.y*16;
  int bc = blockIdx.z;
  int c  = bc & 127;
  if (tid < 64) sw[tid] = dww[c*64 + tid];
  const float* op = g_out + (size_t)bc*HW_;
  for (int i = tid; i < 23*23; i += 256){
    int iy = i/23, ix = i - iy*23;
    int py = by-3+iy, px = bx-3+ix;
    float v = 0.f;
    if (py >= 0 && py <= 128 && px >= 0 && px <= 128){
      int ry = (py==128) ? 126 : py;
      int rx = (px==128) ? 126 : px;
      v = op[ry*W_+rx];
    }
    s_t[i] = v;
  }
  __syncthreads();
  float acc = 0.f;
#pragma unroll
  for (int ky=0;ky<8;ky++)
#pragma unroll
    for (int kx=0;kx<8;kx++)
      acc = fmaf(s_t[(ty+ky)*23 + tx+kx], sw[ky*8+kx], acc);
  g_dw[(size_t)bc*HW_ + (by+ty)*W_ + bx+tx] = acc*g[c] + bb[c];
}

// ------- K7: pointwise 1x1 128->128 (f32x2) -> g_proj (pixel-major) ---------
__global__ void k_pw(const float* __restrict__ w){
  __shared__ float s_in[8*1024];
  __shared__ unsigned long long s_w2[64];
  int tid = threadIdx.x;
  int p0 = tid*4;
  int by = blockIdx.y;
  int b   = blockIdx.z >> 4;
  int cog = (blockIdx.z & 15) * 8;
  unsigned long long acc[8][2];
#pragma unroll
  for (int co=0;co<8;co++){ acc[co][0]=0ULL; acc[co][1]=0ULL; }
  const float* in = g_dw + (size_t)b*MID_*HW_ + (size_t)(by*8)*W_;
  for (int c0 = 0; c0 < MID_; c0 += 8){
    for (int i = tid; i < 2048; i += 256){
      int c = i>>8, p4 = (i&255)*4;
      *(float4*)&s_in[c*1024+p4] = *(const float4*)&in[(size_t)(c0+c)*HW_ + p4];
    }
    if (tid < 64){
      float wv = w[(size_t)(cog + (tid>>3))*MID_ + c0 + (tid&7)];
      s_w2[tid] = pkf(wv, wv);
    }
    __syncthreads();
#pragma unroll
    for (int c=0;c<8;c++){
      const unsigned long long* vp = (const unsigned long long*)&s_in[c*1024+p0];
      unsigned long long v0 = vp[0], v1 = vp[1];
#pragma unroll
      for (int co=0;co<8;co++){
        unsigned long long wv = s_w2[co*8+c];
        fma2(acc[co][0], v0, wv);
        fma2(acc[co][1], v1, wv);
      }
    }
    __syncthreads();
  }
  // transposed store: g_proj[b][pixel][c]
  size_t pb = (size_t)b*HW_ + by*1024 + p0;
#pragma unroll
  for (int pp=0; pp<4; pp++){
    int pr = pp>>1, e = pp&1;
    float vals[8];
#pragma unroll
    for (int co=0;co<8;co++){
      float f0,f1; upk(acc[co][pr], f0, f1);
      vals[co] = e ? f1 : f0;
    }
    float* dst = g_proj + (pb+pp)*MID_ + cog;
    *(float4*)dst       = make_float4(vals[0],vals[1],vals[2],vals[3]);
    *((float4*)dst + 1) = make_float4(vals[4],vals[5],vals[6],vals[7]);
  }
}

// -------- K8: transposed conv (lhs_dilation=2), coalesced pixel-major -------
// block: 4 oy rows, 8 couts; thread = (po 0..63, q 0..3); thread covers
// ox in {po, po+64, po+128, po+192}, ci quarter q (interleaved at float4 level).
__global__ void __launch_bounds__(256,2) k_up(const float* __restrict__ upw, float* __restrict__ out){
  __shared__ unsigned long long sw2[128*37 + 4];  // [ci][k*4+j], pad 37 to break bank aliasing
  int tid = threadIdx.x;
  int oy0 = blockIdx.x*4;
  int b   = blockIdx.y >> 3;
  int cog = (blockIdx.y & 7) * 8;
  for (int i=tid; i<128*36; i+=256){
    int j = i & 3, rem = i >> 2;          // rem = ci*9+k
    int ci = rem/9, k = rem - ci*9;
    float wa = upw[(size_t)(cog+2*j  )*1152 + rem];
    float wb = upw[(size_t)(cog+2*j+1)*1152 + rem];
    sw2[ci*37 + k*4 + j] = pkf(wa, wb);
  }
  __syncthreads();
  int q  = tid & 3;
  int po = tid >> 2;
  int xpar = po & 1;
  const float* pbase = g_proj + (size_t)b*HW_*MID_;
  for (int oyl=0; oyl<4; oyl++){
    int oy = oy0+oyl;
    int iys[2], kys[2]; int niy;
    if (oy & 1){
      iys[0]=(oy-1)>>1; kys[0]=0; niy=1;
      if (oy+1<=254){ iys[1]=(oy+1)>>1; kys[1]=2; niy=2; }
    } else { iys[0]=oy>>1; kys[0]=1; niy=1; }
    unsigned long long acc[4][4];
#pragma unroll
    for (int s=0;s<4;s++)
#pragma unroll
      for (int j=0;j<4;j++) acc[s][j]=0ULL;
    int nix = xpar ? 2 : 1;
    for (int a=0;a<niy;a++){
      for (int e=0;e<nix;e++){
        int kx = xpar ? (e==0?0:2) : 1;
        int kb = kys[a]*3 + kx;
        const float* ip[4]; bool pv[4];
#pragma unroll
        for (int s=0;s<4;s++){
          int ox = po + 64*s;
          int ix; bool ok = true;
          if (xpar){ if (e==0) ix = (ox-1)>>1; else { ix = (ox+1)>>1; ok = (ox+1<=254); } }
          else ix = ox>>1;
          pv[s] = ok;
          ip[s] = pbase + ((size_t)(iys[a]*W_ + ix))*MID_;
        }
#pragma unroll
        for (int cc=0; cc<8; cc++){
          int ci4 = q + cc*4;
          float va[4][4];
#pragma unroll
          for (int s=0;s<4;s++){
            float4 v = pv[s] ? ((const float4*)ip[s])[ci4] : make_float4(0.f,0.f,0.f,0.f);
            va[s][0]=v.x; va[s][1]=v.y; va[s][2]=v.z; va[s][3]=v.w;
          }
#pragma unroll
          for (int e2=0;e2<4;e2++){
            int ci = ci4*4 + e2;
            const unsigned long long* wp = &sw2[ci*37 + kb*4];
            unsigned long long w0=wp[0], w1v=wp[1], w2=wp[2], w3=wp[3];
#pragma unroll
            for (int s=0;s<4;s++){
              unsigned long long vv = pkf(va[s][e2], va[s][e2]);
              fma2(acc[s][0], vv, w0);
              fma2(acc[s][1], vv, w1v);
              fma2(acc[s][2], vv, w2);
              fma2(acc[s][3], vv, w3);
            }
          }
        }
      }
    }
    // cross-q reduce (lanes 0..3 within each nibble) + store
#pragma unroll
    for (int s=0;s<4;s++){
      int ox = po + 64*s;
#pragma unroll
      for (int j=0;j<4;j++){
        float f0,f1; upk(acc[s][j], f0, f1);
        f0 += __shfl_xor_sync(0xffffffffu, f0, 1);
        f0 += __shfl_xor_sync(0xffffffffu, f0, 2);
        f1 += __shfl_xor_sync(0xffffffffu, f1, 1);
        f1 += __shfl_xor_sync(0xffffffffu, f1, 2);
        if (q == 0){
          out[(((size_t)(b*COUT_+cog+2*j  ))*256+oy)*256+ox] = f0;
          out[(((size_t)(b*COUT_+cog+2*j+1))*256+oy)*256+ox] = f1;
        }
      }
    }
  }
}

// ---------------------------------------------------------------------------
#define ATTNF_SMEM (24622*4)

extern "C" void kernel_launch(void* const* d_in, const int* in_sizes, int n_in,
                              void* d_out, int out_size){
  const float* x      = (const float*)d_in[0];
  const float* conv_w = (const float*)d_in[1];
  const float* bn1_g  = (const float*)d_in[2];
  const float* bn1_b  = (const float*)d_in[3];
  const float* qkv_w  = (const float*)d_in[4];
  const float* loc1_w = (const float*)d_in[5];
  const float* loc1_g = (const float*)d_in[6];
  const float* loc1_b = (const float*)d_in[7];
  const float* loc2_w = (const float*)d_in[8];
  const float* loc2_g = (const float*)d_in[9];
  const float* loc2_b = (const float*)d_in[10];
  const float* rel_t  = (const float*)d_in[11];
  const float* cw_w   = (const float*)d_in[12];
  const float* cw_g   = (const float*)d_in[13];
  const float* cw_b   = (const float*)d_in[14];
  const float* hc_w   = (const float*)d_in[15];
  const float* hc_g   = (const float*)d_in[16];
  const float* hc_b   = (const float*)d_in[17];
  const float* hw_w   = (const float*)d_in[18];
  const float* hw_g   = (const float*)d_in[19];
  const float* hw_b   = (const float*)d_in[20];
  const float* pdw    = (const float*)d_in[21];
  const float* pg     = (const float*)d_in[22];
  const float* pb     = (const float*)d_in[23];
  const float* ppw    = (const float*)d_in[24];
  const float* upw    = (const float*)d_in[25];
  float* out = (float*)d_out;

  cudaFuncSetAttribute(k_attnf, cudaFuncAttributeMaxDynamicSharedMemorySize, ATTNF_SMEM);

  float* g_h_p;     cudaGetSymbolAddress((void**)&g_h_p, g_h);
  float* g_local_p; cudaGetSymbolAddress((void**)&g_local_p, g_local);

  // 3 no-op launches so ncu's captured launch (#4) is k_conv3<CIN_> (conv1)
  k_nop<<<1,32>>>();
  k_nop<<<1,32>>>();
  k_nop<<<1,32>>>();
  k_conv3<CIN_><<<dim3(2,4,64), 256>>>(x, conv_w, bn1_g, bn1_b,
                                       (const float*)0, (const float*)0, (const float*)0,
                                       g_h_p, 1);
  k_conv3<MID_><<<dim3(2,4,64), 256>>>(g_h_p, loc1_w, loc1_g, loc1_b,
                                       loc2_w, loc2_g, loc2_b,
                                       g_local_p, 0);
  k_qkv  <<<dim3(1,16,192), 256>>>(qkv_w);
  k_attnf<<<1024, 256, ATTNF_SMEM>>>(rel_t, cw_w, cw_g, cw_b, hc_w, hc_g, hc_b, hw_w, hw_g, hw_b);
  k_gmat <<<512, 256>>>();
  k_dw   <<<dim3(8,8,512), 256>>>(pdw, pg, pb);
  k_pw   <<<dim3(1,16,64), 256>>>(ppw);
  k_up   <<<dim3(64, 32), 256>>>(upw, out);
}

// round 7
// speedup vs baseline: 1.5510x; 1.0003x over previous
#include <cuda_runtime.h>
#include <math.h>

#define B_    4
#define CIN_  256
#define MID_  128
#define COUT_ 64
#define H_    128
#define W_    128
#define HW_   16384
#define WS_   8
#define HEADS_ 8
#define HD_   16
#define NTOK  64
#define NWIN  1024   /* B * 16 * 16 */

// ---------------- scratch (static device memory; no allocs) ----------------
__device__ float g_h    [B_*MID_*H_*W_];
__device__ float g_local[B_*MID_*H_*W_];
__device__ float g_qkv  [3*NWIN*HEADS_*NTOK*HD_];
__device__ float g_o    [B_*MID_*H_*W_];
__device__ float g_out  [B_*MID_*H_*W_];
__device__ float g_dw   [B_*MID_*H_*W_];
__device__ float g_proj [B_*MID_*H_*W_];   // pixel-major: [b][p][c]
__device__ float g_dummy[32];

__device__ __forceinline__ float sigmoidf_(float x){ return 1.f/(1.f+expf(-x)); }

// ---- packed f32x2 helpers --------------------------------------------------
__device__ __forceinline__ void fma2(unsigned long long& d, unsigned long long a, unsigned long long b){
  asm("fma.rn.f32x2 %0, %1, %2, %3;" : "=l"(d) : "l"(a), "l"(b), "l"(d));
}
__device__ __forceinline__ unsigned long long pk2u(unsigned int lo, unsigned int hi){
  unsigned long long d; asm("mov.b64 %0, {%1, %2};" : "=l"(d) : "r"(lo), "r"(hi)); return d;
}
__device__ __forceinline__ unsigned long long pkf(float lo, float hi){
  return pk2u(__float_as_uint(lo), __float_as_uint(hi));
}
__device__ __forceinline__ void upk(unsigned long long v, float& a, float& b){
  unsigned int lo, hi; asm("mov.b64 {%0, %1}, %2;" : "=r"(lo), "=r"(hi) : "l"(v));
  a = __uint_as_float(lo); b = __uint_as_float(hi);
}
__device__ __forceinline__ unsigned int lo32(unsigned long long v){ return (unsigned int)v; }
__device__ __forceinline__ unsigned int hi32(unsigned long long v){ return (unsigned int)(v>>32); }

// ---------------- dummy (shifts ncu capture so launch#4 = conv1) ------------
__global__ void k_nop(){ g_dummy[threadIdx.x] = 0.f; }

// ---------------- K1: conv3x3 CI->MID (f32x2), BN folded, ReLU --------------
// tile 64x32, per thread 4x2 px (4 packed pairs), 8 couts, 4 ci per sync.
// Fill addressing hoisted out of ci loop; boundary zeros written once.
template<int CI>
__global__ void __launch_bounds__(256,2)
k_conv3(const float* __restrict__ x, const float* __restrict__ w,
        const float* __restrict__ g, const float* __restrict__ bb,
        const float* __restrict__ w1, const float* __restrict__ g1,
        const float* __restrict__ b1, float* __restrict__ outp, int relu){
  __shared__ float s_in[4][34*68];
  __shared__ unsigned long long s_w2[4][72];
  int tid = threadIdx.x;
  int tx = tid & 15, ty = tid >> 4;
  int bx = blockIdx.x*64, by = blockIdx.y*32;
  int b   = blockIdx.z >> 4;
  int cog = (blockIdx.z & 15) * 8;

  // ---- fill-slot precompute + one-time boundary zeroing ----
  int off[10];
#pragma unroll
  for (int s=0;s<10;s++){
    int i = tid + 256*s;
    if (i < 2312){
      int iy = i/68, ix = i - iy*68;
      int gy = by+iy-1, gx = bx+ix-1;
      bool inb = (gy>=0 && gy<H_ && gx>=0 && gx<W_ && ix<66);
      off[s] = inb ? (gy*W_+gx) : -1;
      if (!inb){ s_in[0][i]=0.f; s_in[1][i]=0.f; s_in[2][i]=0.f; s_in[3][i]=0.f; }
    } else off[s] = -1;
  }

  // ---- weight-slot precompute (two slots cover 288 entries) ----
  int c0 = tid/72, r0 = tid - c0*72, co0 = r0/9, k0 = r0 - co0*9;
  int t1 = tid + 256;
  int c1 = t1/72, r1 = t1 - c1*72, co1 = r1/9, k1 = r1 - co1*9;
  bool has1 = (t1 < 288);
  float gA  = g[cog+co0];
  float g1A = w1 ? g1[cog+co0] : 0.f;
  float gB  = has1 ? g[cog+co1] : 0.f;
  float g1B = (w1 && has1) ? g1[cog+co1] : 0.f;
  size_t wofs0  = ((size_t)(cog+co0)*CI + c0)*9 + k0;
  size_t w1ofs0 = (size_t)(cog+co0)*CI + c0;
  size_t wofs1  = has1 ? (((size_t)(cog+co1)*CI + c1)*9 + k1) : 0;
  size_t w1ofs1 = has1 ? ((size_t)(cog+co1)*CI + c1) : 0;

  unsigned long long acc[2][2][8];
#pragma unroll
  for (int py=0;py<2;py++)
#pragma unroll
    for (int pr=0;pr<2;pr++)
#pragma unroll
      for (int co=0;co<8;co++) acc[py][pr][co]=0ULL;

  for (int ci0 = 0; ci0 < CI; ci0 += 4){
#pragma unroll
    for (int c=0;c<4;c++){
      const float* xp = x + (size_t)(b*CI+ci0+c)*HW_;
#pragma unroll
      for (int s=0;s<10;s++)
        if (off[s] >= 0) s_in[c][tid+256*s] = xp[off[s]];
    }
    {
      float wv = gA * w[wofs0 + (size_t)ci0*9];
      if (w1 && k0==4) wv += g1A * w1[w1ofs0 + ci0];
      s_w2[c0][r0] = pkf(wv, wv);
      if (has1){
        float wv1 = gB * w[wofs1 + (size_t)ci0*9];
        if (w1 && k1==4) wv1 += g1B * w1[w1ofs1 + ci0];
        s_w2[c1][r1] = pkf(wv1, wv1);
      }
    }
    __syncthreads();
#pragma unroll
    for (int c=0;c<4;c++){
      unsigned long long vp[4][5];
#pragma unroll
      for (int r=0;r<4;r++){
        const unsigned long long* rp = (const unsigned long long*)&s_in[c][(ty*2+r)*68 + tx*4];
        unsigned long long A=rp[0], Bv=rp[1], Cv=rp[2];
        vp[r][0]=A; vp[r][2]=Bv; vp[r][4]=Cv;
        vp[r][1]=pk2u(hi32(A), lo32(Bv));
        vp[r][3]=pk2u(hi32(Bv), lo32(Cv));
      }
#pragma unroll
      for (int co=0;co<8;co++){
        const unsigned long long* wp = &s_w2[c][co*9];
#pragma unroll
        for (int ky=0;ky<3;ky++)
#pragma unroll
          for (int kx=0;kx<3;kx++){
            unsigned long long wv = wp[ky*3+kx];
            fma2(acc[0][0][co], vp[ky  ][kx  ], wv);
            fma2(acc[0][1][co], vp[ky  ][kx+2], wv);
            fma2(acc[1][0][co], vp[ky+1][kx  ], wv);
            fma2(acc[1][1][co], vp[ky+1][kx+2], wv);
          }
      }
    }
    __syncthreads();
  }
  int y0 = by+ty*2, x0 = bx+tx*4;
#pragma unroll
  for (int co=0;co<8;co++){
    int c = cog+co;
    float bv = bb[c] + (w1 ? b1[c] : 0.f);
    float* op = outp + ((size_t)(b*MID_+c)*H_)*W_;
#pragma unroll
    for (int py=0;py<2;py++)
#pragma unroll
      for (int pr=0;pr<2;pr++){
        float f0,f1; upk(acc[py][pr][co], f0, f1);
        f0 += bv; f1 += bv;
        if (relu){ f0=fmaxf(f0,0.f); f1=fmaxf(f1,0.f); }
        op[(y0+py)*W_ + x0+pr*2  ] = f0;
        op[(y0+py)*W_ + x0+pr*2+1] = f1;
      }
  }
}

// ---------------- K3: 1x1 conv 128->8co (f32x2), windowed store -------------
__global__ void k_qkv(const float* __restrict__ w){
  __shared__ float s_in[8*1024];
  __shared__ unsigned long long s_w2[64];
  int tid = threadIdx.x;
  int p0 = tid*4;
  int by = blockIdx.y;
  int b   = blockIdx.z / 48;
  int cog = (blockIdx.z % 48) * 8;
  unsigned long long acc[8][2];
#pragma unroll
  for (int co=0;co<8;co++){ acc[co][0]=0ULL; acc[co][1]=0ULL; }
  const float* in = g_h + (size_t)b*MID_*HW_ + (size_t)(by*8)*W_;
  for (int c0 = 0; c0 < MID_; c0 += 8){
    for (int i = tid; i < 2048; i += 256){
      int c = i>>8, p4 = (i&255)*4;
      *(float4*)&s_in[c*1024+p4] = *(const float4*)&in[(size_t)(c0+c)*HW_ + p4];
    }
    if (tid < 64){
      float wv = w[(size_t)(cog + (tid>>3))*MID_ + c0 + (tid&7)];
      s_w2[tid] = pkf(wv, wv);
    }
    __syncthreads();
#pragma unroll
    for (int c=0;c<8;c++){
      const unsigned long long* vp = (const unsigned long long*)&s_in[c*1024+p0];
      unsigned long long v0 = vp[0], v1 = vp[1];
#pragma unroll
      for (int co=0;co<8;co++){
        unsigned long long wv = s_w2[co*8+c];
        fma2(acc[co][0], v0, wv);
        fma2(acc[co][1], v1, wv);
      }
    }
    __syncthreads();
  }
#pragma unroll
  for (int co=0;co<8;co++){
    int c = cog+co;
    int s = c>>7, hd = (c>>4)&7, d = c&15;
#pragma unroll
    for (int pr=0;pr<2;pr++){
      float f0,f1; upk(acc[co][pr], f0, f1);
#pragma unroll
      for (int e=0;e<2;e++){
        int p = p0 + pr*2 + e;
        int y = by*8 + (p>>7), xx = p&127;
        int yh=y>>3, wy=y&7, xw=xx>>3, wx=xx&7;
        int bp = (b*16+yh)*16+xw;
        int n  = wy*8+wx;
        g_qkv[(((size_t)(s*NWIN+bp)*HEADS_+hd)*NTOK+n)*HD_ + d] = e ? f1 : f0;
      }
    }
  }
}

// ---------- K4: fused dots -> gates -> softmax -> attn@v -> g_o -------------
__global__ void k_attnf(const float* __restrict__ rel,
                        const float* __restrict__ cw_w, const float* __restrict__ cw_g, const float* __restrict__ cw_b,
                        const float* __restrict__ hc_w, const float* __restrict__ hc_g, const float* __restrict__ hc_b,
                        const float* __restrict__ hw_w, const float* __restrict__ hw_g, const float* __restrict__ hw_b){
  extern __shared__ float sm[];
  float* sq   = sm;              // 1024
  float* sk   = sq   + 1024;     // 1024
  float* sv   = sk   + 1024;     // 1024
  float* sdh  = sv   + 1024;     // 4096
  float* z3mx = sdh  + 4096;     // 4096
  float* z3sm = z3mx + 4096;     // 4096
  float* z1mx = z3sm + 4096;     // 512
  float* z1sm = z1mx + 512;      // 512
  float* z2mx = z1sm + 512;      // 512
  float* z2sm = z2mx + 512;      // 512
  float* sg1  = z2sm + 512;      // 512
  float* sg2  = sg1  + 512;      // 512
  float* sg3  = sg2  + 512;      // 4096
  float* swc  = sg3  + 4096;     // 98
  float* swh  = swc  + 98;       // 98
  float* sww  = swh  + 98;       // 98
  float* srel = sww  + 98;       // 1800

  int bp = blockIdx.x, tid = threadIdx.x;
  if (tid < 98){ swc[tid]=cw_w[tid]; swh[tid]=hc_w[tid]; sww[tid]=hw_w[tid]; }
  for (int i=tid; i<1800; i+=256) srel[i] = rel[i];

  int dn = tid >> 2;          // 0..63
  int dmg = (tid & 3) * 16;   // m group base
  int y1 = dn>>3, x1 = dn&7;

  // ---- pass 1: per-head dots -> z reductions ----
  for (int h=0; h<8; h++){
    const float* qp = g_qkv + ((size_t)(0*NWIN+bp)*HEADS_+h)*NTOK*HD_;
    const float* kp = g_qkv + ((size_t)(1*NWIN+bp)*HEADS_+h)*NTOK*HD_;
    for (int i=tid;i<1024;i+=256){ sq[i]=qp[i]; sk[i]=kp[i]; }
    __syncthreads();
    {
      const float4* q4 = (const float4*)sq;
      const float4* k4 = (const float4*)sk;
      float4 qa = q4[dn*4+0], qb = q4[dn*4+1], qc = q4[dn*4+2], qd = q4[dn*4+3];
#pragma unroll
      for (int mm=0;mm<16;mm++){
        int m = dmg + mm;
        float4 ka = k4[m*4+0], kb = k4[m*4+1], kc = k4[m*4+2], kd = k4[m*4+3];
        float s = qa.x*ka.x + qa.y*ka.y + qa.z*ka.z + qa.w*ka.w
                + qb.x*kb.x + qb.y*kb.y + qb.z*kb.z + qb.w*kb.w
                + qc.x*kc.x + qc.y*kc.y + qc.z*kc.z + qc.w*kc.w
                + qd.x*kd.x + qd.y*kd.y + qd.z*kd.z + qd.w*kd.w;
        int y2 = m>>3, x2 = m&7;
        int ridx = (y1-y2+7)*15 + (x1-x2+7);
        float val = s*0.25f + srel[ridx*HEADS_ + h];
        int idx = dn*64 + m;
        sdh[idx] = val;
        if (h == 0){ z3mx[idx] = val; z3sm[idx] = val; }
        else { z3mx[idx] = fmaxf(z3mx[idx], val); z3sm[idx] += val; }
      }
    }
    __syncthreads();
    if (tid < 64){               // z1: per (h, m), reduce over n
      int m = tid;
      float mx=-1e30f, s=0.f;
      for (int n=0;n<64;n++){ float v = sdh[n*64+m]; mx=fmaxf(mx,v); s+=v; }
      z1mx[h*64+m]=mx; z1sm[h*64+m]=s;
    } else if (tid < 128){       // z2: per (n, h), reduce over m
      int n = tid-64;
      float mx=-1e30f, s=0.f;
      for (int j=0;j<64;j++){ float v = sdh[n*64 + ((j+n)&63)]; mx=fmaxf(mx,v); s+=v; }
      z2mx[n*8+h]=mx; z2sm[n*8+h]=s;
    }
    __syncthreads();
  }

  // ---- pass 2: gate maps ----
  float hwg = hw_g[0], hwb = hw_b[0];
  float cwg = cw_g[0], cwb = cw_b[0];
  float hcg = hc_g[0], hcb = hc_b[0];
  for (int idx=tid; idx<4096; idx+=256){
    int n = idx>>6, m = idx&63;
    float s = 0.f;
    for (int ky=0;ky<7;ky++){
      int pn = n-3+ky; if (pn<0||pn>=64) continue;
      for (int kx=0;kx<7;kx++){
        int pm = m-3+kx; if (pm<0||pm>=64) continue;
        int zi = pn*64+pm;
        s += z3mx[zi]*sww[ky*7+kx] + z3sm[zi]*0.125f*sww[49+ky*7+kx];
      }
    }
    sg3[idx] = sigmoidf_(s*hwg + hwb);
  }
  for (int idx=tid; idx<512; idx+=256){
    { // g1: spatial (h=8 rows, m=64 cols)
      int h = idx>>6, m = idx&63;
      float s = 0.f;
      for (int ky=0;ky<7;ky++){
        int ph = h-3+ky; if (ph<0||ph>=8) continue;
        for (int kx=0;kx<7;kx++){
          int pm = m-3+kx; if (pm<0||pm>=64) continue;
          int zi = ph*64+pm;
          s += z1mx[zi]*swc[ky*7+kx] + z1sm[zi]*(1.f/64.f)*swc[49+ky*7+kx];
        }
      }
      sg1[idx] = sigmoidf_(s*cwg + cwb);
    }
    { // g2: spatial (n=64 rows, h=8 cols)
      int n = idx>>3, h = idx&7;
      float s = 0.f;
      for (int ky=0;ky<7;ky++){
        int pn = n-3+ky; if (pn<0||pn>=64) continue;
        for (int kx=0;kx<7;kx++){
          int ph = h-3+kx; if (ph<0||ph>=8) continue;
          int zi = pn*8+ph;
          s += z2mx[zi]*swh[ky*7+kx] + z2sm[zi]*(1.f/64.f)*swh[49+ky*7+kx];
        }
      }
      sg2[idx] = sigmoidf_(s*hcg + hcb);
    }
  }
  __syncthreads();

  // ---- pass 3: per-head gated dots -> softmax -> AV ----
  int b = bp>>8, yh = (bp>>4)&15, xw = bp&15;
  for (int h=0; h<8; h++){
    const float* qp = g_qkv + ((size_t)(0*NWIN+bp)*HEADS_+h)*NTOK*HD_;
    const float* kp = g_qkv + ((size_t)(1*NWIN+bp)*HEADS_+h)*NTOK*HD_;
    const float* vp = g_qkv + ((size_t)(2*NWIN+bp)*HEADS_+h)*NTOK*HD_;
    for (int i=tid;i<1024;i+=256){ sq[i]=qp[i]; sk[i]=kp[i]; sv[i]=vp[i]; }
    __syncthreads();
    {
      const float4* q4 = (const float4*)sq;
      const float4* k4 = (const float4*)sk;
      float4 qa = q4[dn*4+0], qb = q4[dn*4+1], qc = q4[dn*4+2], qd = q4[dn*4+3];
#pragma unroll
      for (int mm=0;mm<16;mm++){
        int m = dmg + mm;
        float4 ka = k4[m*4+0], kb = k4[m*4+1], kc = k4[m*4+2], kd = k4[m*4+3];
        float s = qa.x*ka.x + qa.y*ka.y + qa.z*ka.z + qa.w*ka.w
                + qb.x*kb.x + qb.y*kb.y + qb.z*kb.z + qb.w*kb.w
                + qc.x*kc.x + qc.y*kc.y + qc.z*kc.z + qc.w*kc.w
                + qd.x*kd.x + qd.y*kd.y + qd.z*kd.z + qd.w*kd.w;
        int y2 = m>>3, x2 = m&7;
        int ridx = (y1-y2+7)*15 + (x1-x2+7);
        float val = s*0.25f + srel[ridx*HEADS_ + h];
        float gsum = sg1[h*64+m] + sg2[dn*8+h] + sg3[dn*64+m];
        sdh[dn*64+m] = val * gsum * (1.f/3.f);
      }
    }
    __syncthreads();
    if (tid < 64){
      int n = tid;
      float mx = -1e30f;
      for (int j=0;j<64;j++) mx = fmaxf(mx, sdh[n*64+((j+n)&63)]);
      float s = 0.f;
      for (int j=0;j<64;j++){
        int mi = n*64+((j+n)&63);
        float e = expf(sdh[mi]-mx); sdh[mi]=e; s+=e;
      }
      float inv = 1.f/s;
      for (int j=0;j<64;j++) sdh[n*64+((j+n)&63)] *= inv;
    }
    __syncthreads();
    for (int idx=tid; idx<1024; idx+=256){
      int n = idx>>4, d = idx&15;
      float s = 0.f;
#pragma unroll
      for (int m=0;m<64;m++) s = fmaf(sdh[n*64+m], sv[m*HD_+d], s);
      int c = h*HD_ + d;
      int y = yh*8 + (n>>3), x = xw*8 + (n&7);
      g_o[((size_t)(b*MID_+c)*H_+y)*W_+x] = s;
    }
    __syncthreads();
  }
}

// ---------------- K5: Fh@Fw gating, out = o*gmat + local --------------------
__global__ void k_gmat(){
  __shared__ float Fh[128*32];
  __shared__ float Fw[32*128];
  int bc = blockIdx.x, tid = threadIdx.x;
  const float* op = g_o + (size_t)bc*HW_;
  for (int idx=tid; idx<4096; idx+=256){
    { // Fw[k][w]
      int k = idx>>7, w = idx&127;
      float mx=-1e30f, sm_=0.f;
#pragma unroll
      for (int j=0;j<4;j++){ float v = op[(k*4+j)*W_+w]; mx=fmaxf(mx,v); sm_+=v; }
      Fw[idx] = sigmoidf_(sm_*0.25f + mx);
    }
    { // Fh[y][k]
      int y = idx>>5, k = idx&31;
      float mx=-1e30f, sm_=0.f;
#pragma unroll
      for (int j=0;j<4;j++){ float v = op[y*W_ + k*4+j]; mx=fmaxf(mx,v); sm_+=v; }
      Fh[idx] = sigmoidf_(sm_*0.25f + mx);
    }
  }
  __syncthreads();
  const float* lp = g_local + (size_t)bc*HW_;
  float* outp = g_out + (size_t)bc*HW_;
  for (int idx=tid; idx<HW_; idx+=256){
    int y = idx>>7, w = idx&127;
    float gm = 0.f;
#pragma unroll
    for (int k=0;k<32;k++) gm = fmaf(Fh[y*32+k], Fw[k*128+w], gm);
    outp[idx] = op[idx]*gm + lp[idx];
  }
}

// ---------------- K6: reflect-pad + depthwise 8x8 + BN (smem-tiled) ---------
__global__ void k_dw(const float* __restrict__ dww, const float* __restrict__ g,
                     const float* __restrict__ bb){
  __shared__ float s_t[23*23];
  __shared__ float sw[64];
  int tid = threadIdx.x;
  int tx = tid & 15, ty = tid >> 4;
  int bx = blockIdx.x*16, by = blockIdx.y*16;
  int bc = blockIdx.z;
  int c  = bc & 127;
  if (tid < 64) sw[tid] = dww[c*64 + tid];
  const float* op = g_out + (size_t)bc*HW_;
  for (int i = tid; i < 23*23; i += 256){
    int iy = i/23, ix = i - iy*23;
    int py = by-3+iy, px = bx-3+ix;
    float v = 0.f;
    if (py >= 0 && py <= 128 && px >= 0 && px <= 128){
      int ry = (py==128) ? 126 : py;
      int rx = (px==128) ? 126 : px;
      v = op[ry*W_+rx];
    }
    s_t[i] = v;
  }
  __syncthreads();
  float acc = 0.f;
#pragma unroll
  for (int ky=0;ky<8;ky++)
#pragma unroll
    for (int kx=0;kx<8;kx++)
      acc = fmaf(s_t[(ty+ky)*23 + tx+kx], sw[ky*8+kx], acc);
  g_dw[(size_t)bc*HW_ + (by+ty)*W_ + bx+tx] = acc*g[c] + bb[c];
}

// ------- K7: pointwise 1x1 128->128 (f32x2) -> g_proj (pixel-major) ---------
__global__ void k_pw(const float* __restrict__ w){
  __shared__ float s_in[8*1024];
  __shared__ unsigned long long s_w2[64];
  int tid = threadIdx.x;
  int p0 = tid*4;
  int by = blockIdx.y;
  int b   = blockIdx.z >> 4;
  int cog = (blockIdx.z & 15) * 8;
  unsigned long long acc[8][2];
#pragma unroll
  for (int co=0;co<8;co++){ acc[co][0]=0ULL; acc[co][1]=0ULL; }
  const float* in = g_dw + (size_t)b*MID_*HW_ + (size_t)(by*8)*W_;
  for (int c0 = 0; c0 < MID_; c0 += 8){
    for (int i = tid; i < 2048; i += 256){
      int c = i>>8, p4 = (i&255)*4;
      *(float4*)&s_in[c*1024+p4] = *(const float4*)&in[(size_t)(c0+c)*HW_ + p4];
    }
    if (tid < 64){
      float wv = w[(size_t)(cog + (tid>>3))*MID_ + c0 + (tid&7)];
      s_w2[tid] = pkf(wv, wv);
    }
    __syncthreads();
#pragma unroll
    for (int c=0;c<8;c++){
      const unsigned long long* vp = (const unsigned long long*)&s_in[c*1024+p0];
      unsigned long long v0 = vp[0], v1 = vp[1];
#pragma unroll
      for (int co=0;co<8;co++){
        unsigned long long wv = s_w2[co*8+c];
        fma2(acc[co][0], v0, wv);
        fma2(acc[co][1], v1, wv);
      }
    }
    __syncthreads();
  }
  // transposed store: g_proj[b][pixel][c]
  size_t pb = (size_t)b*HW_ + by*1024 + p0;
#pragma unroll
  for (int pp=0; pp<4; pp++){
    int pr = pp>>1, e = pp&1;
    float vals[8];
#pragma unroll
    for (int co=0;co<8;co++){
      float f0,f1; upk(acc[co][pr], f0, f1);
      vals[co] = e ? f1 : f0;
    }
    float* dst = g_proj + (pb+pp)*MID_ + cog;
    *(float4*)dst       = make_float4(vals[0],vals[1],vals[2],vals[3]);
    *((float4*)dst + 1) = make_float4(vals[4],vals[5],vals[6],vals[7]);
  }
}

// -------- K8: transposed conv (lhs_dilation=2), coalesced pixel-major -------
// block: 4 oy rows, 8 couts; thread = (po 0..63, q 0..3); thread covers
// ox in {po, po+64, po+128, po+192}, ci quarter q (interleaved at float4 level).
__global__ void __launch_bounds__(256,2) k_up(const float* __restrict__ upw, float* __restrict__ out){
  __shared__ unsigned long long sw2[128*37 + 4];  // [ci][k*4+j], pad 37 to break bank aliasing
  int tid = threadIdx.x;
  int oy0 = blockIdx.x*4;
  int b   = blockIdx.y >> 3;
  int cog = (blockIdx.y & 7) * 8;
  for (int i=tid; i<128*36; i+=256){
    int j = i & 3, rem = i >> 2;          // rem = ci*9+k
    int ci = rem/9, k = rem - ci*9;
    float wa = upw[(size_t)(cog+2*j  )*1152 + rem];
    float wb = upw[(size_t)(cog+2*j+1)*1152 + rem];
    sw2[ci*37 + k*4 + j] = pkf(wa, wb);
  }
  __syncthreads();
  int q  = tid & 3;
  int po = tid >> 2;
  int xpar = po & 1;
  const float* pbase = g_proj + (size_t)b*HW_*MID_;
  for (int oyl=0; oyl<4; oyl++){
    int oy = oy0+oyl;
    int iys[2], kys[2]; int niy;
    if (oy & 1){
      iys[0]=(oy-1)>>1; kys[0]=0; niy=1;
      if (oy+1<=254){ iys[1]=(oy+1)>>1; kys[1]=2; niy=2; }
    } else { iys[0]=oy>>1; kys[0]=1; niy=1; }
    unsigned long long acc[4][4];
#pragma unroll
    for (int s=0;s<4;s++)
#pragma unroll
      for (int j=0;j<4;j++) acc[s][j]=0ULL;
    int nix = xpar ? 2 : 1;
    for (int a=0;a<niy;a++){
      for (int e=0;e<nix;e++){
        int kx = xpar ? (e==0?0:2) : 1;
        int kb = kys[a]*3 + kx;
        const float* ip[4]; bool pv[4];
#pragma unroll
        for (int s=0;s<4;s++){
          int ox = po + 64*s;
          int ix; bool ok = true;
          if (xpar){ if (e==0) ix = (ox-1)>>1; else { ix = (ox+1)>>1; ok = (ox+1<=254); } }
          else ix = ox>>1;
          pv[s] = ok;
          ip[s] = pbase + ((size_t)(iys[a]*W_ + ix))*MID_;
        }
#pragma unroll
        for (int cc=0; cc<8; cc++){
          int ci4 = q + cc*4;
          float va[4][4];
#pragma unroll
          for (int s=0;s<4;s++){
            float4 v = pv[s] ? ((const float4*)ip[s])[ci4] : make_float4(0.f,0.f,0.f,0.f);
            va[s][0]=v.x; va[s][1]=v.y; va[s][2]=v.z; va[s][3]=v.w;
          }
#pragma unroll
          for (int e2=0;e2<4;e2++){
            int ci = ci4*4 + e2;
            const unsigned long long* wp = &sw2[ci*37 + kb*4];
            unsigned long long w0=wp[0], w1v=wp[1], w2=wp[2], w3=wp[3];
#pragma unroll
            for (int s=0;s<4;s++){
              unsigned long long vv = pkf(va[s][e2], va[s][e2]);
              fma2(acc[s][0], vv, w0);
              fma2(acc[s][1], vv, w1v);
              fma2(acc[s][2], vv, w2);
              fma2(acc[s][3], vv, w3);
            }
          }
        }
      }
    }
    // cross-q reduce (lanes 0..3 within each nibble) + store
#pragma unroll
    for (int s=0;s<4;s++){
      int ox = po + 64*s;
#pragma unroll
      for (int j=0;j<4;j++){
        float f0,f1; upk(acc[s][j], f0, f1);
        f0 += __shfl_xor_sync(0xffffffffu, f0, 1);
        f0 += __shfl_xor_sync(0xffffffffu, f0, 2);
        f1 += __shfl_xor_sync(0xffffffffu, f1, 1);
        f1 += __shfl_xor_sync(0xffffffffu, f1, 2);
        if (q == 0){
          out[(((size_t)(b*COUT_+cog+2*j  ))*256+oy)*256+ox] = f0;
          out[(((size_t)(b*COUT_+cog+2*j+1))*256+oy)*256+ox] = f1;
        }
      }
    }
  }
}

// ---------------------------------------------------------------------------
#define ATTNF_SMEM (24622*4)

extern "C" void kernel_launch(void* const* d_in, const int* in_sizes, int n_in,
                              void* d_out, int out_size){
  const float* x      = (const float*)d_in[0];
  const float* conv_w = (const float*)d_in[1];
  const float* bn1_g  = (const float*)d_in[2];
  const float* bn1_b  = (const float*)d_in[3];
  const float* qkv_w  = (const float*)d_in[4];
  const float* loc1_w = (const float*)d_in[5];
  const float* loc1_g = (const float*)d_in[6];
  const float* loc1_b = (const float*)d_in[7];
  const float* loc2_w = (const float*)d_in[8];
  const float* loc2_g = (const float*)d_in[9];
  const float* loc2_b = (const float*)d_in[10];
  const float* rel_t  = (const float*)d_in[11];
  const float* cw_w   = (const float*)d_in[12];
  const float* cw_g   = (const float*)d_in[13];
  const float* cw_b   = (const float*)d_in[14];
  const float* hc_w   = (const float*)d_in[15];
  const float* hc_g   = (const float*)d_in[16];
  const float* hc_b   = (const float*)d_in[17];
  const float* hw_w   = (const float*)d_in[18];
  const float* hw_g   = (const float*)d_in[19];
  const float* hw_b   = (const float*)d_in[20];
  const float* pdw    = (const float*)d_in[21];
  const float* pg     = (const float*)d_in[22];
  const float* pb     = (const float*)d_in[23];
  const float* ppw    = (const float*)d_in[24];
  const float* upw    = (const float*)d_in[25];
  float* out = (float*)d_out;

  cudaFuncSetAttribute(k_attnf, cudaFuncAttributeMaxDynamicSharedMemorySize, ATTNF_SMEM);

  float* g_h_p;     cudaGetSymbolAddress((void**)&g_h_p, g_h);
  float* g_local_p; cudaGetSymbolAddress((void**)&g_local_p, g_local);

  // 3 no-op launches so ncu's captured launch (#4) is k_conv3<CIN_> (conv1)
  k_nop<<<1,32>>>();
  k_nop<<<1,32>>>();
  k_nop<<<1,32>>>();
  k_conv3<CIN_><<<dim3(2,4,64), 256>>>(x, conv_w, bn1_g, bn1_b,
                                       (const float*)0, (const float*)0, (const float*)0,
                                       g_h_p, 1);
  k_conv3<MID_><<<dim3(2,4,64), 256>>>(g_h_p, loc1_w, loc1_g, loc1_b,
                                       loc2_w, loc2_g, loc2_b,
                                       g_local_p, 0);
  k_qkv  <<<dim3(1,16,192), 256>>>(qkv_w);
  k_attnf<<<1024, 256, ATTNF_SMEM>>>(rel_t, cw_w, cw_g, cw_b, hc_w, hc_g, hc_b, hw_w, hw_g, hw_b);
  k_gmat <<<512, 256>>>();
  k_dw   <<<dim3(8,8,512), 256>>>(pdw, pg, pb);
  k_pw   <<<dim3(1,16,64), 256>>>(ppw);
  k_up   <<<dim3(64, 32), 256>>>(upw, out);
}

// round 9
// speedup vs baseline: 1.8793x; 1.2117x over previous
#include <cuda_runtime.h>
#include <math.h>

#define B_    4
#define CIN_  256
#define MID_  128
#define COUT_ 64
#define H_    128
#define W_    128
#define HW_   16384
#define HEADS_ 8
#define HD_   16
#define NTOK  64
#define NWIN  1024

__device__ float g_h    [B_*MID_*H_*W_];
__device__ float g_local[B_*MID_*H_*W_];
__device__ float g_qkv  [3*NWIN*HEADS_*NTOK*HD_];
__device__ float g_o    [B_*MID_*H_*W_];
__device__ float g_out  [B_*MID_*H_*W_];
__device__ float g_dw   [B_*MID_*H_*W_];
__device__ float g_proj [B_*MID_*H_*W_];
__device__ float g_wA1  [2*9*CIN_*128];
__device__ float g_wA2  [2*9*MID_*128];
__device__ float g_dummy[32];

__device__ __forceinline__ float sigmoidf_(float x){ return 1.f/(1.f+expf(-x)); }

__device__ __forceinline__ void fma2(unsigned long long& d, unsigned long long a, unsigned long long b){
  asm("fma.rn.f32x2 %0, %1, %2, %3;" : "=l"(d) : "l"(a), "l"(b), "l"(d));
}
__device__ __forceinline__ unsigned long long pk2u(unsigned int lo, unsigned int hi){
  unsigned long long d; asm("mov.b64 %0, {%1, %2};" : "=l"(d) : "r"(lo), "r"(hi)); return d;
}
__device__ __forceinline__ unsigned long long pkf(float lo, float hi){
  return pk2u(__float_as_uint(lo), __float_as_uint(hi));
}
__device__ __forceinline__ void upk(unsigned long long v, float& a, float& b){
  unsigned int lo, hi; asm("mov.b64 {%0, %1}, %2;" : "=r"(lo), "=r"(hi) : "l"(v));
  a = __uint_as_float(lo); b = __uint_as_float(hi);
}
__device__ __forceinline__ float tf32hi(float v){
  return __uint_as_float(__float_as_uint(v) & 0xFFFFE000u);
}
__device__ __forceinline__ void mma8(float* c, unsigned a0, unsigned a1, unsigned a2, unsigned a3,
                                     unsigned b0, unsigned b1){
  asm volatile("mma.sync.aligned.m16n8k8.row.col.f32.tf32.tf32.f32 "
    "{%0,%1,%2,%3}, {%4,%5,%6,%7}, {%8,%9}, {%0,%1,%2,%3};"
    : "+f"(c[0]), "+f"(c[1]), "+f"(c[2]), "+f"(c[3])
    : "r"(a0), "r"(a1), "r"(a2), "r"(a3), "r"(b0), "r"(b1));
}

__global__ void k_nop(){ g_dummy[threadIdx.x] = 0.f; }

// weight prep: fold BN gamma (+1x1 into center tap), tf32 hi/lo split (low13 zeroed),
// layout [hl][tap][ch][ci32][co128]
__global__ void k_prepw(const float* __restrict__ w, const float* __restrict__ g,
                        const float* __restrict__ w1, const float* __restrict__ g1,
                        float* __restrict__ dst, int CI){
  int i = blockIdx.x*256 + threadIdx.x;
  int tot = 9*CI*128;
  if (i >= tot) return;
  int tap = i/(CI*128); int rem = i - tap*CI*128; int ci = rem>>7; int co = rem&127;
  float v = g[co]*w[((size_t)co*CI+ci)*9 + tap];
  if (w1 && tap==4) v += g1[co]*w1[(size_t)co*CI+ci];
  float hi = tf32hi(v);
  float lo = tf32hi(v - hi);
  int NCH = CI/32;
  size_t o = (((size_t)tap*NCH + (ci>>5))*32 + (ci&31))*128 + co;
  dst[o] = hi; dst[tot + o] = lo;
}

// conv3x3 CI->128 via mma.sync tf32 (3xTF32). One output row per block, 8 warps.
// warp w: couts 16w..16w+15; N = 128 px (16 tiles of 8).
template<int CI>
__global__ void __launch_bounds__(256)
k_convmma(const float* __restrict__ x, const float* __restrict__ wA,
          const float* __restrict__ bias1, const float* __restrict__ bias2,
          float* __restrict__ outp, int relu){
  extern __shared__ float sh[];
  float* sInH = sh;               // [32][136], j = px+1 (j=0 and j=129 zero)
  float* sInL = sInH + 32*136;
  float* sWH  = sInL + 32*136;    // [ci32][co 128 pad136]
  float* sWL  = sWH  + 32*136;
  const int NCH = CI/32, TOT = 9*CI*128;
  int tid = threadIdx.x, lane = tid&31, wz = tid>>5;
  int cq = lane&3, r = lane>>2;
  int coW = wz*16;
  int y = blockIdx.x, b = blockIdx.y;
  int dylo = (y==0)?1:0, dyhi = (y==127)?1:2;

  float acc[16][4];
#pragma unroll
  for (int nt=0;nt<16;nt++){ acc[nt][0]=0.f; acc[nt][1]=0.f; acc[nt][2]=0.f; acc[nt][3]=0.f; }

  bool first = true;
  for (int ch=0; ch<NCH; ch++){
    for (int dy=dylo; dy<=dyhi; dy++){
      if (!first) __syncthreads();
      first = false;
      // input row fill (hi/lo), padded
      const float* inrow = x + ((size_t)b*CI + ch*32)*HW_ + (size_t)(y+dy-1)*W_;
#pragma unroll
      for (int k=0;k<4;k++){
        int u = tid + 256*k;
        int ci = u>>5, q = u&31;
        float4 v = *(const float4*)(inrow + (size_t)ci*HW_ + q*4);
        int base = ci*136 + 1 + q*4;
        float vv[4] = {v.x, v.y, v.z, v.w};
#pragma unroll
        for (int e=0;e<4;e++){
          float hi = tf32hi(vv[e]);
          sInH[base+e] = hi;
          sInL[base+e] = tf32hi(vv[e]-hi);
        }
      }
      if (tid < 32){
        sInH[tid*136]=0.f; sInL[tid*136]=0.f;
        sInH[tid*136+129]=0.f; sInL[tid*136+129]=0.f;
      }
      for (int dx=0; dx<3; dx++){
        if (dx) __syncthreads();
        // weight tile fill
        const float* wsrc = wA + (((size_t)(dy*3+dx)*NCH + ch)*32)*128;
#pragma unroll
        for (int k=0;k<4;k++){
          int u = tid + 256*k;
          int ci = u>>5, c4 = (u&31)*4;
          float4 vh = *(const float4*)(wsrc + ci*128 + c4);
          float4 vl = *(const float4*)(wsrc + TOT + ci*128 + c4);
          *(float4*)&sWH[ci*136 + c4] = vh;
          *(float4*)&sWL[ci*136 + c4] = vl;
        }
        __syncthreads();
#pragma unroll
        for (int pass=0; pass<3; pass++){
          const float* A  = (pass==2) ? sWL  : sWH;
          const float* Bm = (pass==1) ? sInL : sInH;
#pragma unroll
          for (int ks=0; ks<4; ks++){
            int kb = ks*8;
            unsigned a0 = __float_as_uint(A[(kb+cq  )*136 + coW + r    ]);
            unsigned a1 = __float_as_uint(A[(kb+cq  )*136 + coW + r + 8]);
            unsigned a2 = __float_as_uint(A[(kb+cq+4)*136 + coW + r    ]);
            unsigned a3 = __float_as_uint(A[(kb+cq+4)*136 + coW + r + 8]);
#pragma unroll
            for (int nt=0; nt<16; nt++){
              int jb = dx + nt*8 + r;
              unsigned b0 = __float_as_uint(Bm[(kb+cq  )*136 + jb]);
              unsigned b1 = __float_as_uint(Bm[(kb+cq+4)*136 + jb]);
              mma8(acc[nt], a0, a1, a2, a3, b0, b1);
            }
          }
        }
      }
    }
  }
  // epilogue: c0,c1 at (co=coW+r, px=nt*8+2cq..+1); c2,c3 at co+8
  float bv0 = bias1[coW+r]   + (bias2 ? bias2[coW+r]   : 0.f);
  float bv1 = bias1[coW+r+8] + (bias2 ? bias2[coW+r+8] : 0.f);
  float* o0 = outp + ((size_t)b*MID_ + coW + r)*HW_ + (size_t)y*W_;
  float* o1 = o0 + 8*HW_;
#pragma unroll
  for (int nt=0; nt<16; nt++){
    int px = nt*8 + 2*cq;
    float v0 = acc[nt][0]+bv0, v1 = acc[nt][1]+bv0;
    float v2 = acc[nt][2]+bv1, v3 = acc[nt][3]+bv1;
    if (relu){ v0=fmaxf(v0,0.f); v1=fmaxf(v1,0.f); v2=fmaxf(v2,0.f); v3=fmaxf(v3,0.f); }
    *(float2*)(o0+px) = make_float2(v0,v1);
    *(float2*)(o1+px) = make_float2(v2,v3);
  }
}

// K3: 1x1 conv 128->8co (f32x2), windowed store
__global__ void k_qkv(const float* __restrict__ w){
  __shared__ float s_in[8*1024];
  __shared__ unsigned long long s_w2[64];
  int tid = threadIdx.x;
  int p0 = tid*4;
  int by = blockIdx.y;
  int b   = blockIdx.z / 48;
  int cog = (blockIdx.z % 48) * 8;
  unsigned long long acc[8][2];
#pragma unroll
  for (int co=0;co<8;co++){ acc[co][0]=0ULL; acc[co][1]=0ULL; }
  const float* in = g_h + (size_t)b*MID_*HW_ + (size_t)(by*8)*W_;
  for (int c0 = 0; c0 < MID_; c0 += 8){
    for (int i = tid; i < 2048; i += 256){
      int c = i>>8, p4 = (i&255)*4;
      *(float4*)&s_in[c*1024+p4] = *(const float4*)&in[(size_t)(c0+c)*HW_ + p4];
    }
    if (tid < 64){
      float wv = w[(size_t)(cog + (tid>>3))*MID_ + c0 + (tid&7)];
      s_w2[tid] = pkf(wv, wv);
    }
    __syncthreads();
#pragma unroll
    for (int c=0;c<8;c++){
      const unsigned long long* vp = (const unsigned long long*)&s_in[c*1024+p0];
      unsigned long long v0 = vp[0], v1 = vp[1];
#pragma unroll
      for (int co=0;co<8;co++){
        unsigned long long wv = s_w2[co*8+c];
        fma2(acc[co][0], v0, wv);
        fma2(acc[co][1], v1, wv);
      }
    }
    __syncthreads();
  }
#pragma unroll
  for (int co=0;co<8;co++){
    int c = cog+co;
    int s = c>>7, hd = (c>>4)&7, d = c&15;
#pragma unroll
    for (int pr=0;pr<2;pr++){
      float f0,f1; upk(acc[co][pr], f0, f1);
#pragma unroll
      for (int e=0;e<2;e++){
        int p = p0 + pr*2 + e;
        int yy = by*8 + (p>>7), xx = p&127;
        int yh=yy>>3, wy=yy&7, xw=xx>>3, wx=xx&7;
        int bp = (b*16+yh)*16+xw;
        int n  = wy*8+wx;
        g_qkv[(((size_t)(s*NWIN+bp)*HEADS_+hd)*NTOK+n)*HD_ + d] = e ? f1 : f0;
      }
    }
  }
}

// K4: fused dots -> gates -> softmax -> attn@v -> g_o
__global__ void k_attnf(const float* __restrict__ rel,
                        const float* __restrict__ cw_w, const float* __restrict__ cw_g, const float* __restrict__ cw_b,
                        const float* __restrict__ hc_w, const float* __restrict__ hc_g, const float* __restrict__ hc_b,
                        const float* __restrict__ hw_w, const float* __restrict__ hw_g, const float* __restrict__ hw_b){
  extern __shared__ float sm[];
  float* sq   = sm;
  float* sk   = sq   + 1024;
  float* sv   = sk   + 1024;
  float* sdh  = sv   + 1024;
  float* z3mx = sdh  + 4096;
  float* z3sm = z3mx + 4096;
  float* z1mx = z3sm + 4096;
  float* z1sm = z1mx + 512;
  float* z2mx = z1sm + 512;
  float* z2sm = z2mx + 512;
  float* sg1  = z2sm + 512;
  float* sg2  = sg1  + 512;
  float* sg3  = sg2  + 512;
  float* swc  = sg3  + 4096;
  float* swh  = swc  + 98;
  float* sww  = swh  + 98;
  float* srel = sww  + 98;

  int bp = blockIdx.x, tid = threadIdx.x;
  if (tid < 98){ swc[tid]=cw_w[tid]; swh[tid]=hc_w[tid]; sww[tid]=hw_w[tid]; }
  for (int i=tid; i<1800; i+=256) srel[i] = rel[i];

  int dn = tid >> 2;
  int dmg = (tid & 3) * 16;
  int y1 = dn>>3, x1 = dn&7;

  for (int h=0; h<8; h++){
    const float* qp = g_qkv + ((size_t)(0*NWIN+bp)*HEADS_+h)*NTOK*HD_;
    const float* kp = g_qkv + ((size_t)(1*NWIN+bp)*HEADS_+h)*NTOK*HD_;
    for (int i=tid;i<1024;i+=256){ sq[i]=qp[i]; sk[i]=kp[i]; }
    __syncthreads();
    {
      const float4* q4 = (const float4*)sq;
      const float4* k4 = (const float4*)sk;
      float4 qa = q4[dn*4+0], qb = q4[dn*4+1], qc = q4[dn*4+2], qd = q4[dn*4+3];
#pragma unroll
      for (int mm=0;mm<16;mm++){
        int m = dmg + mm;
        float4 ka = k4[m*4+0], kb = k4[m*4+1], kc = k4[m*4+2], kd = k4[m*4+3];
        float s = qa.x*ka.x + qa.y*ka.y + qa.z*ka.z + qa.w*ka.w
                + qb.x*kb.x + qb.y*kb.y + qb.z*kb.z + qb.w*kb.w
                + qc.x*kc.x + qc.y*kc.y + qc.z*kc.z + qc.w*kc.w
                + qd.x*kd.x + qd.y*kd.y + qd.z*kd.z + qd.w*kd.w;
        int y2 = m>>3, x2 = m&7;
        int ridx = (y1-y2+7)*15 + (x1-x2+7);
        float val = s*0.25f + srel[ridx*HEADS_ + h];
        int idx = dn*64 + m;
        sdh[idx] = val;
        if (h == 0){ z3mx[idx] = val; z3sm[idx] = val; }
        else { z3mx[idx] = fmaxf(z3mx[idx], val); z3sm[idx] += val; }
      }
    }
    __syncthreads();
    if (tid < 64){
      int m = tid;
      float mx=-1e30f, s=0.f;
      for (int n=0;n<64;n++){ float v = sdh[n*64+m]; mx=fmaxf(mx,v); s+=v; }
      z1mx[h*64+m]=mx; z1sm[h*64+m]=s;
    } else if (tid < 128){
      int n = tid-64;
      float mx=-1e30f, s=0.f;
      for (int j=0;j<64;j++){ float v = sdh[n*64 + ((j+n)&63)]; mx=fmaxf(mx,v); s+=v; }
      z2mx[n*8+h]=mx; z2sm[n*8+h]=s;
    }
    __syncthreads();
  }

  float hwg = hw_g[0], hwb = hw_b[0];
  float cwg = cw_g[0], cwb = cw_b[0];
  float hcg = hc_g[0], hcb = hc_b[0];
  for (int idx=tid; idx<4096; idx+=256){
    int n = idx>>6, m = idx&63;
    float s = 0.f;
    for (int ky=0;ky<7;ky++){
      int pn = n-3+ky; if (pn<0||pn>=64) continue;
      for (int kx=0;kx<7;kx++){
        int pm = m-3+kx; if (pm<0||pm>=64) continue;
        int zi = pn*64+pm;
        s += z3mx[zi]*sww[ky*7+kx] + z3sm[zi]*0.125f*sww[49+ky*7+kx];
      }
    }
    sg3[idx] = sigmoidf_(s*hwg + hwb);
  }
  for (int idx=tid; idx<512; idx+=256){
    {
      int h = idx>>6, m = idx&63;
      float s = 0.f;
      for (int ky=0;ky<7;ky++){
        int ph = h-3+ky; if (ph<0||ph>=8) continue;
        for (int kx=0;kx<7;kx++){
          int pm = m-3+kx; if (pm<0||pm>=64) continue;
          int zi = ph*64+pm;
          s += z1mx[zi]*swc[ky*7+kx] + z1sm[zi]*(1.f/64.f)*swc[49+ky*7+kx];
        }
      }
      sg1[idx] = sigmoidf_(s*cwg + cwb);
    }
    {
      int n = idx>>3, h = idx&7;
      float s = 0.f;
      for (int ky=0;ky<7;ky++){
        int pn = n-3+ky; if (pn<0||pn>=64) continue;
        for (int kx=0;kx<7;kx++){
          int ph = h-3+kx; if (ph<0||ph>=8) continue;
          int zi = pn*8+ph;
          s += z2mx[zi]*swh[ky*7+kx] + z2sm[zi]*(1.f/64.f)*swh[49+ky*7+kx];
        }
      }
      sg2[idx] = sigmoidf_(s*hcg + hcb);
    }
  }
  __syncthreads();

  int b = bp>>8, yh = (bp>>4)&15, xw = bp&15;
  for (int h=0; h<8; h++){
    const float* qp = g_qkv + ((size_t)(0*NWIN+bp)*HEADS_+h)*NTOK*HD_;
    const float* kp = g_qkv + ((size_t)(1*NWIN+bp)*HEADS_+h)*NTOK*HD_;
    const float* vp = g_qkv + ((size_t)(2*NWIN+bp)*HEADS_+h)*NTOK*HD_;
    for (int i=tid;i<1024;i+=256){ sq[i]=qp[i]; sk[i]=kp[i]; sv[i]=vp[i]; }
    __syncthreads();
    {
      const float4* q4 = (const float4*)sq;
      const float4* k4 = (const float4*)sk;
      float4 qa = q4[dn*4+0], qb = q4[dn*4+1], qc = q4[dn*4+2], qd = q4[dn*4+3];
#pragma unroll
      for (int mm=0;mm<16;mm++){
        int m = dmg + mm;
        float4 ka = k4[m*4+0], kb = k4[m*4+1], kc = k4[m*4+2], kd = k4[m*4+3];
        float s = qa.x*ka.x + qa.y*ka.y + qa.z*ka.z + qa.w*ka.w
                + qb.x*kb.x + qb.y*kb.y + qb.z*kb.z + qb.w*kb.w
                + qc.x*kc.x + qc.y*kc.y + qc.z*kc.z + qc.w*kc.w
                + qd.x*kd.x + qd.y*kd.y + qd.z*kd.z + qd.w*kd.w;
        int y2 = m>>3, x2 = m&7;
        int ridx = (y1-y2+7)*15 + (x1-x2+7);
        float val = s*0.25f + srel[ridx*HEADS_ + h];
        float gsum = sg1[h*64+m] + sg2[dn*8+h] + sg3[dn*64+m];
        sdh[dn*64+m] = val * gsum * (1.f/3.f);
      }
    }
    __syncthreads();
    if (tid < 64){
      int n = tid;
      float mx = -1e30f;
      for (int j=0;j<64;j++) mx = fmaxf(mx, sdh[n*64+((j+n)&63)]);
      float s = 0.f;
      for (int j=0;j<64;j++){
        int mi = n*64+((j+n)&63);
        float e = expf(sdh[mi]-mx); sdh[mi]=e; s+=e;
      }
      float inv = 1.f/s;
      for (int j=0;j<64;j++) sdh[n*64+((j+n)&63)] *= inv;
    }
    __syncthreads();
    for (int idx=tid; idx<1024; idx+=256){
      int n = idx>>4, d = idx&15;
      float s = 0.f;
#pragma unroll
      for (int m=0;m<64;m++) s = fmaf(sdh[n*64+m], sv[m*HD_+d], s);
      int c = h*HD_ + d;
      int yy = yh*8 + (n>>3), xx = xw*8 + (n&7);
      g_o[((size_t)(b*MID_+c)*H_+yy)*W_+xx] = s;
    }
    __syncthreads();
  }
}

// K5: Fh@Fw gating, out = o*gmat + local
__global__ void k_gmat(){
  __shared__ float Fh[128*32];
  __shared__ float Fw[32*128];
  int bc = blockIdx.x, tid = threadIdx.x;
  const float* op = g_o + (size_t)bc*HW_;
  for (int idx=tid; idx<4096; idx+=256){
    {
      int k = idx>>7, w = idx&127;
      float mx=-1e30f, sm_=0.f;
#pragma unroll
      for (int j=0;j<4;j++){ float v = op[(k*4+j)*W_+w]; mx=fmaxf(mx,v); sm_+=v; }
      Fw[idx] = sigmoidf_(sm_*0.25f + mx);
    }
    {
      int y = idx>>5, k = idx&31;
      float mx=-1e30f, sm_=0.f;
#pragma unroll
      for (int j=0;j<4;j++){ float v = op[y*W_ + k*4+j]; mx=fmaxf(mx,v); sm_+=v; }
      Fh[idx] = sigmoidf_(sm_*0.25f + mx);
    }
  }
  __syncthreads();
  const float* lp = g_local + (size_t)bc*HW_;
  float* outp = g_out + (size_t)bc*HW_;
  for (int idx=tid; idx<HW_; idx+=256){
    int y = idx>>7, w = idx&127;
    float gm = 0.f;
#pragma unroll
    for (int k=0;k<32;k++) gm = fmaf(Fh[y*32+k], Fw[k*128+w], gm);
    outp[idx] = op[idx]*gm + lp[idx];
  }
}

// K6: reflect-pad + depthwise 8x8 + BN
__global__ void k_dw(const float* __restrict__ dww, const float* __restrict__ g,
                     const float* __restrict__ bb){
  __shared__ float s_t[23*23];
  __shared__ float sw[64];
  int tid = threadIdx.x;
  int tx = tid & 15, ty = tid >> 4;
  int bx = blockIdx.x*16, by = blockIdx.y*16;
  int bc = blockIdx.z;
  int c  = bc & 127;
  if (tid < 64) sw[tid] = dww[c*64 + tid];
  const float* op = g_out + (size_t)bc*HW_;
  for (int i = tid; i < 23*23; i += 256){
    int iy = i/23, ix = i - iy*23;
    int py = by-3+iy, px = bx-3+ix;
    float v = 0.f;
    if (py >= 0 && py <= 128 && px >= 0 && px <= 128){
      int ry = (py==128) ? 126 : py;
      int rx = (px==128) ? 126 : px;
      v = op[ry*W_+rx];
    }
    s_t[i] = v;
  }
  __syncthreads();
  float acc = 0.f;
#pragma unroll
  for (int ky=0;ky<8;ky++)
#pragma unroll
    for (int kx=0;kx<8;kx++)
      acc = fmaf(s_t[(ty+ky)*23 + tx+kx], sw[ky*8+kx], acc);
  g_dw[(size_t)bc*HW_ + (by+ty)*W_ + bx+tx] = acc*g[c] + bb[c];
}

// K7: pointwise 1x1 128->128 (f32x2) -> g_proj (pixel-major)
__global__ void k_pw(const float* __restrict__ w){
  __shared__ float s_in[8*1024];
  __shared__ unsigned long long s_w2[64];
  int tid = threadIdx.x;
  int p0 = tid*4;
  int by = blockIdx.y;
  int b   = blockIdx.z >> 4;
  int cog = (blockIdx.z & 15) * 8;
  unsigned long long acc[8][2];
#pragma unroll
  for (int co=0;co<8;co++){ acc[co][0]=0ULL; acc[co][1]=0ULL; }
  const float* in = g_dw + (size_t)b*MID_*HW_ + (size_t)(by*8)*W_;
  for (int c0 = 0; c0 < MID_; c0 += 8){
    for (int i = tid; i < 2048; i += 256){
      int c = i>>8, p4 = (i&255)*4;
      *(float4*)&s_in[c*1024+p4] = *(const float4*)&in[(size_t)(c0+c)*HW_ + p4];
    }
    if (tid < 64){
      float wv = w[(size_t)(cog + (tid>>3))*MID_ + c0 + (tid&7)];
      s_w2[tid] = pkf(wv, wv);
    }
    __syncthreads();
#pragma unroll
    for (int c=0;c<8;c++){
      const unsigned long long* vp = (const unsigned long long*)&s_in[c*1024+p0];
      unsigned long long v0 = vp[0], v1 = vp[1];
#pragma unroll
      for (int co=0;co<8;co++){
        unsigned long long wv = s_w2[co*8+c];
        fma2(acc[co][0], v0, wv);
        fma2(acc[co][1], v1, wv);
      }
    }
    __syncthreads();
  }
  size_t pb = (size_t)b*HW_ + by*1024 + p0;
#pragma unroll
  for (int pp=0; pp<4; pp++){
    int pr = pp>>1, e = pp&1;
    float vals[8];
#pragma unroll
    for (int co=0;co<8;co++){
      float f0,f1; upk(acc[co][pr], f0, f1);
      vals[co] = e ? f1 : f0;
    }
    float* dst = g_proj + (pb+pp)*MID_ + cog;
    *(float4*)dst       = make_float4(vals[0],vals[1],vals[2],vals[3]);
    *((float4*)dst + 1) = make_float4(vals[4],vals[5],vals[6],vals[7]);
  }
}

// K8: transposed conv (lhs_dilation=2), coalesced pixel-major
__global__ void __launch_bounds__(256,2) k_up(const float* __restrict__ upw, float* __restrict__ out){
  __shared__ unsigned long long sw2[128*37 + 4];
  int tid = threadIdx.x;
  int oy0 = blockIdx.x*4;
  int b   = blockIdx.y >> 3;
  int cog = (blockIdx.y & 7) * 8;
  for (int i=tid; i<128*36; i+=256){
    int j = i & 3, rem = i >> 2;
    int ci = rem/9, k = rem - ci*9;
    float wa = upw[(size_t)(cog+2*j  )*1152 + rem];
    float wb = upw[(size_t)(cog+2*j+1)*1152 + rem];
    sw2[ci*37 + k*4 + j] = pkf(wa, wb);
  }
  __syncthreads();
  int q  = tid & 3;
  int po = tid >> 2;
  int xpar = po & 1;
  const float* pbase = g_proj + (size_t)b*HW_*MID_;
  for (int oyl=0; oyl<4; oyl++){
    int oy = oy0+oyl;
    int iys[2], kys[2]; int niy;
    if (oy & 1){
      iys[0]=(oy-1)>>1; kys[0]=0; niy=1;
      if (oy+1<=254){ iys[1]=(oy+1)>>1; kys[1]=2; niy=2; }
    } else { iys[0]=oy>>1; kys[0]=1; niy=1; }
    unsigned long long acc[4][4];
#pragma unroll
    for (int s=0;s<4;s++)
#pragma unroll
      for (int j=0;j<4;j++) acc[s][j]=0ULL;
    int nix = xpar ? 2 : 1;
    for (int a=0;a<niy;a++){
      for (int e=0;e<nix;e++){
        int kx = xpar ? (e==0?0:2) : 1;
        int kb = kys[a]*3 + kx;
        const float* ip[4]; bool pv[4];
#pragma unroll
        for (int s=0;s<4;s++){
          int ox = po + 64*s;
          int ix; bool ok = true;
          if (xpar){ if (e==0) ix = (ox-1)>>1; else { ix = (ox+1)>>1; ok = (ox+1<=254); } }
          else ix = ox>>1;
          pv[s] = ok;
          ip[s] = pbase + ((size_t)(iys[a]*W_ + ix))*MID_;
        }
#pragma unroll
        for (int cc=0; cc<8; cc++){
          int ci4 = q + cc*4;
          float va[4][4];
#pragma unroll
          for (int s=0;s<4;s++){
            float4 v = pv[s] ? ((const float4*)ip[s])[ci4] : make_float4(0.f,0.f,0.f,0.f);
            va[s][0]=v.x; va[s][1]=v.y; va[s][2]=v.z; va[s][3]=v.w;
          }
#pragma unroll
          for (int e2=0;e2<4;e2++){
            int ci = ci4*4 + e2;
            const unsigned long long* wp = &sw2[ci*37 + kb*4];
            unsigned long long w0=wp[0], w1v=wp[1], w2=wp[2], w3=wp[3];
#pragma unroll
            for (int s=0;s<4;s++){
              unsigned long long vv = pkf(va[s][e2], va[s][e2]);
              fma2(acc[s][0], vv, w0);
              fma2(acc[s][1], vv, w1v);
              fma2(acc[s][2], vv, w2);
              fma2(acc[s][3], vv, w3);
            }
          }
        }
      }
    }
#pragma unroll
    for (int s=0;s<4;s++){
      int ox = po + 64*s;
#pragma unroll
      for (int j=0;j<4;j++){
        float f0,f1; upk(acc[s][j], f0, f1);
        f0 += __shfl_xor_sync(0xffffffffu, f0, 1);
        f0 += __shfl_xor_sync(0xffffffffu, f0, 2);
        f1 += __shfl_xor_sync(0xffffffffu, f1, 1);
        f1 += __shfl_xor_sync(0xffffffffu, f1, 2);
        if (q == 0){
          out[(((size_t)(b*COUT_+cog+2*j  ))*256+oy)*256+ox] = f0;
          out[(((size_t)(b*COUT_+cog+2*j+1))*256+oy)*256+ox] = f1;
        }
      }
    }
  }
}

#define ATTNF_SMEM (24622*4)
#define CONV_SMEM  (4*32*136*4)

extern "C" void kernel_launch(void* const* d_in, const int* in_sizes, int n_in,
                              void* d_out, int out_size){
  const float* x      = (const float*)d_in[0];
  const float* conv_w = (const float*)d_in[1];
  const float* bn1_g  = (const float*)d_in[2];
  const float* bn1_b  = (const float*)d_in[3];
  const float* qkv_w  = (const float*)d_in[4];
  const float* loc1_w = (const float*)d_in[5];
  const float* loc1_g = (const float*)d_in[6];
  const float* loc1_b = (const float*)d_in[7];
  const float* loc2_w = (const float*)d_in[8];
  const float* loc2_g = (const float*)d_in[9];
  const float* loc2_b = (const float*)d_in[10];
  const float* rel_t  = (const float*)d_in[11];
  const float* cw_w   = (const float*)d_in[12];
  const float* cw_g   = (const float*)d_in[13];
  const float* cw_b   = (const float*)d_in[14];
  const float* hc_w   = (const float*)d_in[15];
  const float* hc_g   = (const float*)d_in[16];
  const float* hc_b   = (const float*)d_in[17];
  const float* hw_w   = (const float*)d_in[18];
  const float* hw_g   = (const float*)d_in[19];
  const float* hw_b   = (const float*)d_in[20];
  const float* pdw    = (const float*)d_in[21];
  const float* pg     = (const float*)d_in[22];
  const float* pb     = (const float*)d_in[23];
  const float* ppw    = (const float*)d_in[24];
  const float* upw    = (const float*)d_in[25];
  float* out = (float*)d_out;

  cudaFuncSetAttribute(k_attnf, cudaFuncAttributeMaxDynamicSharedMemorySize, ATTNF_SMEM);
  cudaFuncSetAttribute(k_convmma<CIN_>, cudaFuncAttributeMaxDynamicSharedMemorySize, CONV_SMEM);
  cudaFuncSetAttribute(k_convmma<MID_>, cudaFuncAttributeMaxDynamicSharedMemorySize, CONV_SMEM);

  float* g_h_p;     cudaGetSymbolAddress((void**)&g_h_p, g_h);
  float* g_local_p; cudaGetSymbolAddress((void**)&g_local_p, g_local);
  float* g_wA1_p;   cudaGetSymbolAddress((void**)&g_wA1_p, g_wA1);
  float* g_wA2_p;   cudaGetSymbolAddress((void**)&g_wA2_p, g_wA2);

  k_nop<<<1,32>>>();   // pad: ncu captures launch #4 = conv1 mma
  k_prepw<<<1152,256>>>(conv_w, bn1_g, (const float*)0, (const float*)0, g_wA1_p, CIN_);
  k_prepw<<<576,256>>>(loc1_w, loc1_g, loc2_w, loc2_g, g_wA2_p, MID_);
  k_convmma<CIN_><<<dim3(128,B_), 256, CONV_SMEM>>>(x, g_wA1_p, bn1_b, (const float*)0, g_h_p, 1);
  k_convmma<MID_><<<dim3(128,B_), 256, CONV_SMEM>>>(g_h_p, g_wA2_p, loc1_b, loc2_b, g_local_p, 0);
  k_qkv  <<<dim3(1,16,192), 256>>>(qkv_w);
  k_attnf<<<1024, 256, ATTNF_SMEM>>>(rel_t, cw_w, cw_g, cw_b, hc_w, hc_g, hc_b, hw_w, hw_g, hw_b);
  k_gmat <<<512, 256>>>();
  k_dw   <<<dim3(8,8,512), 256>>>(pdw, pg, pb);
  k_pw   <<<dim3(1,16,64), 256>>>(ppw);
  k_up   <<<dim3(64, 32), 256>>>(upw, out);
}

// round 10
// speedup vs baseline: 2.0401x; 1.0856x over previous
#include <cuda_runtime.h>
#include <math.h>

#define B_    4
#define CIN_  256
#define MID_  128
#define COUT_ 64
#define H_    128
#define W_    128
#define HW_   16384
#define HEADS_ 8
#define HD_   16
#define NTOK  64
#define NWIN  1024

__device__ float g_h    [B_*MID_*H_*W_];
__device__ float g_local[B_*MID_*H_*W_];
__device__ float g_qkv  [3*NWIN*HEADS_*NTOK*HD_];
__device__ float g_o    [B_*MID_*H_*W_];
__device__ float g_out  [B_*MID_*H_*W_];
__device__ float g_dw   [B_*MID_*H_*W_];
__device__ float g_proj [B_*MID_*H_*W_];
__device__ float g_wA1  [9*CIN_*128];
__device__ float g_wA2  [9*MID_*128];
__device__ float g_dummy[32];

__device__ __forceinline__ float sigmoidf_(float x){ return 1.f/(1.f+expf(-x)); }

__device__ __forceinline__ void fma2(unsigned long long& d, unsigned long long a, unsigned long long b){
  asm("fma.rn.f32x2 %0, %1, %2, %3;" : "=l"(d) : "l"(a), "l"(b), "l"(d));
}
__device__ __forceinline__ unsigned long long pk2u(unsigned int lo, unsigned int hi){
  unsigned long long d; asm("mov.b64 %0, {%1, %2};" : "=l"(d) : "r"(lo), "r"(hi)); return d;
}
__device__ __forceinline__ unsigned long long pkf(float lo, float hi){
  return pk2u(__float_as_uint(lo), __float_as_uint(hi));
}
__device__ __forceinline__ void upk(unsigned long long v, float& a, float& b){
  unsigned int lo, hi; asm("mov.b64 {%0, %1}, %2;" : "=r"(lo), "=r"(hi) : "l"(v));
  a = __uint_as_float(lo); b = __uint_as_float(hi);
}
__device__ __forceinline__ float tf32hi(float v){
  return __uint_as_float(__float_as_uint(v) & 0xFFFFE000u);
}
__device__ __forceinline__ float tf32rn(float v){
  unsigned u; asm("cvt.rna.tf32.f32 %0, %1;" : "=r"(u) : "f"(v));
  return __uint_as_float(u);
}
__device__ __forceinline__ void mma8(float* c, unsigned a0, unsigned a1, unsigned a2, unsigned a3,
                                     unsigned b0, unsigned b1){
  asm volatile("mma.sync.aligned.m16n8k8.row.col.f32.tf32.tf32.f32 "
    "{%0,%1,%2,%3}, {%4,%5,%6,%7}, {%8,%9}, {%0,%1,%2,%3};"
    : "+f"(c[0]), "+f"(c[1]), "+f"(c[2]), "+f"(c[3])
    : "r"(a0), "r"(a1), "r"(a2), "r"(a3), "r"(b0), "r"(b1));
}

__global__ void k_nop(){ g_dummy[threadIdx.x] = 0.f; }

// weight prep: fold BN gamma (+1x1 into center tap), ROUND-to-nearest tf32,
// layout [tap][ch][ci32][co128]
__global__ void k_prepw(const float* __restrict__ w, const float* __restrict__ g,
                        const float* __restrict__ w1, const float* __restrict__ g1,
                        float* __restrict__ dst, int CI){
  int i = blockIdx.x*256 + threadIdx.x;
  int tot = 9*CI*128;
  if (i >= tot) return;
  int tap = i/(CI*128); int rem = i - tap*CI*128; int ci = rem>>7; int co = rem&127;
  float v = g[co]*w[((size_t)co*CI+ci)*9 + tap];
  if (w1 && tap==4) v += g1[co]*w1[(size_t)co*CI+ci];
  int NCH = CI/32;
  size_t o = (((size_t)tap*NCH + (ci>>5))*32 + (ci&31))*128 + co;
  dst[o] = tf32rn(v);
}

// conv3x3 CI->128 via mma.sync tf32 (2xTF32: input hi/lo, weights rn-tf32).
// One output row per block, 8 warps; warp = 16 couts x 128 px.
// smem: sIn2 [32ci][132 float2 (hi,lo)], sW [3dx][32ci][co pad136].
template<int CI>
__global__ void __launch_bounds__(256)
k_convmma(const float* __restrict__ x, const float* __restrict__ wA,
          const float* __restrict__ bias1, const float* __restrict__ bias2,
          float* __restrict__ outp, int relu){
  extern __shared__ float sh[];
  float2* sIn2 = (float2*)sh;            // 32*132 float2 = 33792B
  float*  sW   = sh + 32*132*2;          // 3*32*136 floats = 52224B
  const int NCH = CI/32;
  int tid = threadIdx.x, lane = tid&31, wz = tid>>5;
  int cq = lane&3, r = lane>>2;
  int coW = wz*16;
  int y = blockIdx.x, b = blockIdx.y;
  int dylo = (y==0)?1:0, dyhi = (y==127)?1:2;

  float acc[16][4];
#pragma unroll
  for (int nt=0;nt<16;nt++){ acc[nt][0]=0.f; acc[nt][1]=0.f; acc[nt][2]=0.f; acc[nt][3]=0.f; }

  bool first = true;
  for (int ch=0; ch<NCH; ch++){
    for (int dy=dylo; dy<=dyhi; dy++){
      if (!first) __syncthreads();
      first = false;
      // ---- input row fill: (hi,lo) pairs, j = px+1, zeros at j=0 and 129 ----
      const float* inrow = x + ((size_t)b*CI + ch*32)*HW_ + (size_t)(y+dy-1)*W_;
#pragma unroll
      for (int k=0;k<4;k++){
        int u = tid + 256*k;
        int ci = u>>5, q = u&31;
        float4 v = *(const float4*)(inrow + (size_t)ci*HW_ + q*4);
        int base = ci*132 + 1 + q*4;
        float vv[4] = {v.x, v.y, v.z, v.w};
#pragma unroll
        for (int e=0;e<4;e++){
          float hi = tf32hi(vv[e]);
          sIn2[base+e] = make_float2(hi, tf32hi(vv[e]-hi));
        }
      }
      if (tid < 32){
        sIn2[tid*132]     = make_float2(0.f,0.f);
        sIn2[tid*132+129] = make_float2(0.f,0.f);
      }
      // ---- weight fill: all 3 dx tiles at once ----
      const float* wbase = wA + ((size_t)(dy*3)*NCH + 0)*0 /*dummy*/;
#pragma unroll
      for (int k=0;k<12;k++){
        int u = tid + 256*k;
        int dx = u>>10, rem = u&1023;
        int ci = rem>>5, c4 = (rem&31)*4;
        float4 vh = *(const float4*)(wA + (((size_t)(dy*3+dx)*NCH + ch)*32 + ci)*128 + c4);
        *(float4*)&sW[dx*(32*136) + ci*136 + c4] = vh;
      }
      (void)wbase;
      __syncthreads();
      // ---- mma phase ----
#pragma unroll
      for (int dx=0; dx<3; dx++){
        const float* A = sW + dx*(32*136);
#pragma unroll
        for (int ks=0; ks<4; ks++){
          int kb = ks*8;
          unsigned a0 = __float_as_uint(A[(kb+cq  )*136 + coW + r    ]);
          unsigned a1 = __float_as_uint(A[(kb+cq  )*136 + coW + r + 8]);
          unsigned a2 = __float_as_uint(A[(kb+cq+4)*136 + coW + r    ]);
          unsigned a3 = __float_as_uint(A[(kb+cq+4)*136 + coW + r + 8]);
#pragma unroll
          for (int nt=0; nt<16; nt++){
            int jb = dx + nt*8 + r;
            float2 p0 = sIn2[(kb+cq  )*132 + jb];
            float2 p1 = sIn2[(kb+cq+4)*132 + jb];
            mma8(acc[nt], a0, a1, a2, a3, __float_as_uint(p0.x), __float_as_uint(p1.x));
            mma8(acc[nt], a0, a1, a2, a3, __float_as_uint(p0.y), __float_as_uint(p1.y));
          }
        }
      }
    }
  }
  // epilogue: c0,c1 at (co=coW+r, px=nt*8+2cq..+1); c2,c3 at co+8
  float bv0 = bias1[coW+r]   + (bias2 ? bias2[coW+r]   : 0.f);
  float bv1 = bias1[coW+r+8] + (bias2 ? bias2[coW+r+8] : 0.f);
  float* o0 = outp + ((size_t)b*MID_ + coW + r)*HW_ + (size_t)y*W_;
  float* o1 = o0 + 8*HW_;
#pragma unroll
  for (int nt=0; nt<16; nt++){
    int px = nt*8 + 2*cq;
    float v0 = acc[nt][0]+bv0, v1 = acc[nt][1]+bv0;
    float v2 = acc[nt][2]+bv1, v3 = acc[nt][3]+bv1;
    if (relu){ v0=fmaxf(v0,0.f); v1=fmaxf(v1,0.f); v2=fmaxf(v2,0.f); v3=fmaxf(v3,0.f); }
    *(float2*)(o0+px) = make_float2(v0,v1);
    *(float2*)(o1+px) = make_float2(v2,v3);
  }
}

// K3: 1x1 conv 128->8co (f32x2), windowed store
__global__ void k_qkv(const float* __restrict__ w){
  __shared__ float s_in[8*1024];
  __shared__ unsigned long long s_w2[64];
  int tid = threadIdx.x;
  int p0 = tid*4;
  int by = blockIdx.y;
  int b   = blockIdx.z / 48;
  int cog = (blockIdx.z % 48) * 8;
  unsigned long long acc[8][2];
#pragma unroll
  for (int co=0;co<8;co++){ acc[co][0]=0ULL; acc[co][1]=0ULL; }
  const float* in = g_h + (size_t)b*MID_*HW_ + (size_t)(by*8)*W_;
  for (int c0 = 0; c0 < MID_; c0 += 8){
    for (int i = tid; i < 2048; i += 256){
      int c = i>>8, p4 = (i&255)*4;
      *(float4*)&s_in[c*1024+p4] = *(const float4*)&in[(size_t)(c0+c)*HW_ + p4];
    }
    if (tid < 64){
      float wv = w[(size_t)(cog + (tid>>3))*MID_ + c0 + (tid&7)];
      s_w2[tid] = pkf(wv, wv);
    }
    __syncthreads();
#pragma unroll
    for (int c=0;c<8;c++){
      const unsigned long long* vp = (const unsigned long long*)&s_in[c*1024+p0];
      unsigned long long v0 = vp[0], v1 = vp[1];
#pragma unroll
      for (int co=0;co<8;co++){
        unsigned long long wv = s_w2[co*8+c];
        fma2(acc[co][0], v0, wv);
        fma2(acc[co][1], v1, wv);
      }
    }
    __syncthreads();
  }
#pragma unroll
  for (int co=0;co<8;co++){
    int c = cog+co;
    int s = c>>7, hd = (c>>4)&7, d = c&15;
#pragma unroll
    for (int pr=0;pr<2;pr++){
      float f0,f1; upk(acc[co][pr], f0, f1);
#pragma unroll
      for (int e=0;e<2;e++){
        int p = p0 + pr*2 + e;
        int yy = by*8 + (p>>7), xx = p&127;
        int yh=yy>>3, wy=yy&7, xw=xx>>3, wx=xx&7;
        int bp = (b*16+yh)*16+xw;
        int n  = wy*8+wx;
        g_qkv[(((size_t)(s*NWIN+bp)*HEADS_+hd)*NTOK+n)*HD_ + d] = e ? f1 : f0;
      }
    }
  }
}

// K4: fused dots -> gates -> softmax -> attn@v -> g_o
__global__ void k_attnf(const float* __restrict__ rel,
                        const float* __restrict__ cw_w, const float* __restrict__ cw_g, const float* __restrict__ cw_b,
                        const float* __restrict__ hc_w, const float* __restrict__ hc_g, const float* __restrict__ hc_b,
                        const float* __restrict__ hw_w, const float* __restrict__ hw_g, const float* __restrict__ hw_b){
  extern __shared__ float sm[];
  float* sq   = sm;
  float* sk   = sq   + 1024;
  float* sv   = sk   + 1024;
  float* sdh  = sv   + 1024;
  float* z3mx = sdh  + 4096;
  float* z3sm = z3mx + 4096;
  float* z1mx = z3sm + 4096;
  float* z1sm = z1mx + 512;
  float* z2mx = z1sm + 512;
  float* z2sm = z2mx + 512;
  float* sg1  = z2sm + 512;
  float* sg2  = sg1  + 512;
  float* sg3  = sg2  + 512;
  float* swc  = sg3  + 4096;
  float* swh  = swc  + 98;
  float* sww  = swh  + 98;
  float* srel = sww  + 98;

  int bp = blockIdx.x, tid = threadIdx.x;
  if (tid < 98){ swc[tid]=cw_w[tid]; swh[tid]=hc_w[tid]; sww[tid]=hw_w[tid]; }
  for (int i=tid; i<1800; i+=256) srel[i] = rel[i];

  int dn = tid >> 2;
  int dmg = (tid & 3) * 16;
  int y1 = dn>>3, x1 = dn&7;

  for (int h=0; h<8; h++){
    const float* qp = g_qkv + ((size_t)(0*NWIN+bp)*HEADS_+h)*NTOK*HD_;
    const float* kp = g_qkv + ((size_t)(1*NWIN+bp)*HEADS_+h)*NTOK*HD_;
    for (int i=tid;i<1024;i+=256){ sq[i]=qp[i]; sk[i]=kp[i]; }
    __syncthreads();
    {
      const float4* q4 = (const float4*)sq;
      const float4* k4 = (const float4*)sk;
      float4 qa = q4[dn*4+0], qb = q4[dn*4+1], qc = q4[dn*4+2], qd = q4[dn*4+3];
#pragma unroll
      for (int mm=0;mm<16;mm++){
        int m = dmg + mm;
        float4 ka = k4[m*4+0], kb = k4[m*4+1], kc = k4[m*4+2], kd = k4[m*4+3];
        float s = qa.x*ka.x + qa.y*ka.y + qa.z*ka.z + qa.w*ka.w
                + qb.x*kb.x + qb.y*kb.y + qb.z*kb.z + qb.w*kb.w
                + qc.x*kc.x + qc.y*kc.y + qc.z*kc.z + qc.w*kc.w
                + qd.x*kd.x + qd.y*kd.y + qd.z*kd.z + qd.w*kd.w;
        int y2 = m>>3, x2 = m&7;
        int ridx = (y1-y2+7)*15 + (x1-x2+7);
        float val = s*0.25f + srel[ridx*HEADS_ + h];
        int idx = dn*64 + m;
        sdh[idx] = val;
        if (h == 0){ z3mx[idx] = val; z3sm[idx] = val; }
        else { z3mx[idx] = fmaxf(z3mx[idx], val); z3sm[idx] += val; }
      }
    }
    __syncthreads();
    if (tid < 64){
      int m = tid;
      float mx=-1e30f, s=0.f;
      for (int n=0;n<64;n++){ float v = sdh[n*64+m]; mx=fmaxf(mx,v); s+=v; }
      z1mx[h*64+m]=mx; z1sm[h*64+m]=s;
    } else if (tid < 128){
      int n = tid-64;
      float mx=-1e30f, s=0.f;
      for (int j=0;j<64;j++){ float v = sdh[n*64 + ((j+n)&63)]; mx=fmaxf(mx,v); s+=v; }
      z2mx[n*8+h]=mx; z2sm[n*8+h]=s;
    }
    __syncthreads();
  }

  float hwg = hw_g[0], hwb = hw_b[0];
  float cwg = cw_g[0], cwb = cw_b[0];
  float hcg = hc_g[0], hcb = hc_b[0];
  for (int idx=tid; idx<4096; idx+=256){
    int n = idx>>6, m = idx&63;
    float s = 0.f;
    for (int ky=0;ky<7;ky++){
      int pn = n-3+ky; if (pn<0||pn>=64) continue;
      for (int kx=0;kx<7;kx++){
        int pm = m-3+kx; if (pm<0||pm>=64) continue;
        int zi = pn*64+pm;
        s += z3mx[zi]*sww[ky*7+kx] + z3sm[zi]*0.125f*sww[49+ky*7+kx];
      }
    }
    sg3[idx] = sigmoidf_(s*hwg + hwb);
  }
  for (int idx=tid; idx<512; idx+=256){
    {
      int h = idx>>6, m = idx&63;
      float s = 0.f;
      for (int ky=0;ky<7;ky++){
        int ph = h-3+ky; if (ph<0||ph>=8) continue;
        for (int kx=0;kx<7;kx++){
          int pm = m-3+kx; if (pm<0||pm>=64) continue;
          int zi = ph*64+pm;
          s += z1mx[zi]*swc[ky*7+kx] + z1sm[zi]*(1.f/64.f)*swc[49+ky*7+kx];
        }
      }
      sg1[idx] = sigmoidf_(s*cwg + cwb);
    }
    {
      int n = idx>>3, h = idx&7;
      float s = 0.f;
      for (int ky=0;ky<7;ky++){
        int pn = n-3+ky; if (pn<0||pn>=64) continue;
        for (int kx=0;kx<7;kx++){
          int ph = h-3+kx; if (ph<0||ph>=8) continue;
          int zi = pn*8+ph;
          s += z2mx[zi]*swh[ky*7+kx] + z2sm[zi]*(1.f/64.f)*swh[49+ky*7+kx];
        }
      }
      sg2[idx] = sigmoidf_(s*hcg + hcb);
    }
  }
  __syncthreads();

  int b = bp>>8, yh = (bp>>4)&15, xw = bp&15;
  for (int h=0; h<8; h++){
    const float* qp = g_qkv + ((size_t)(0*NWIN+bp)*HEADS_+h)*NTOK*HD_;
    const float* kp = g_qkv + ((size_t)(1*NWIN+bp)*HEADS_+h)*NTOK*HD_;
    const float* vp = g_qkv + ((size_t)(2*NWIN+bp)*HEADS_+h)*NTOK*HD_;
    for (int i=tid;i<1024;i+=256){ sq[i]=qp[i]; sk[i]=kp[i]; sv[i]=vp[i]; }
    __syncthreads();
    {
      const float4* q4 = (const float4*)sq;
      const float4* k4 = (const float4*)sk;
      float4 qa = q4[dn*4+0], qb = q4[dn*4+1], qc = q4[dn*4+2], qd = q4[dn*4+3];
#pragma unroll
      for (int mm=0;mm<16;mm++){
        int m = dmg + mm;
        float4 ka = k4[m*4+0], kb = k4[m*4+1], kc = k4[m*4+2], kd = k4[m*4+3];
        float s = qa.x*ka.x + qa.y*ka.y + qa.z*ka.z + qa.w*ka.w
                + qb.x*kb.x + qb.y*kb.y + qb.z*kb.z + qb.w*kb.w
                + qc.x*kc.x + qc.y*kc.y + qc.z*kc.z + qc.w*kc.w
                + qd.x*kd.x + qd.y*kd.y + qd.z*kd.z + qd.w*kd.w;
        int y2 = m>>3, x2 = m&7;
        int ridx = (y1-y2+7)*15 + (x1-x2+7);
        float val = s*0.25f + srel[ridx*HEADS_ + h];
        float gsum = sg1[h*64+m] + sg2[dn*8+h] + sg3[dn*64+m];
        sdh[dn*64+m] = val * gsum * (1.f/3.f);
      }
    }
    __syncthreads();
    if (tid < 64){
      int n = tid;
      float mx = -1e30f;
      for (int j=0;j<64;j++) mx = fmaxf(mx, sdh[n*64+((j+n)&63)]);
      float s = 0.f;
      for (int j=0;j<64;j++){
        int mi = n*64+((j+n)&63);
        float e = expf(sdh[mi]-mx); sdh[mi]=e; s+=e;
      }
      float inv = 1.f/s;
      for (int j=0;j<64;j++) sdh[n*64+((j+n)&63)] *= inv;
    }
    __syncthreads();
    for (int idx=tid; idx<1024; idx+=256){
      int n = idx>>4, d = idx&15;
      float s = 0.f;
#pragma unroll
      for (int m=0;m<64;m++) s = fmaf(sdh[n*64+m], sv[m*HD_+d], s);
      int c = h*HD_ + d;
      int yy = yh*8 + (n>>3), xx = xw*8 + (n&7);
      g_o[((size_t)(b*MID_+c)*H_+yy)*W_+xx] = s;
    }
    __syncthreads();
  }
}

// K5: Fh@Fw gating, out = o*gmat + local
__global__ void k_gmat(){
  __shared__ float Fh[128*32];
  __shared__ float Fw[32*128];
  int bc = blockIdx.x, tid = threadIdx.x;
  const float* op = g_o + (size_t)bc*HW_;
  for (int idx=tid; idx<4096; idx+=256){
    {
      int k = idx>>7, w = idx&127;
      float mx=-1e30f, sm_=0.f;
#pragma unroll
      for (int j=0;j<4;j++){ float v = op[(k*4+j)*W_+w]; mx=fmaxf(mx,v); sm_+=v; }
      Fw[idx] = sigmoidf_(sm_*0.25f + mx);
    }
    {
      int y = idx>>5, k = idx&31;
      float mx=-1e30f, sm_=0.f;
#pragma unroll
      for (int j=0;j<4;j++){ float v = op[y*W_ + k*4+j]; mx=fmaxf(mx,v); sm_+=v; }
      Fh[idx] = sigmoidf_(sm_*0.25f + mx);
    }
  }
  __syncthreads();
  const float* lp = g_local + (size_t)bc*HW_;
  float* outp = g_out + (size_t)bc*HW_;
  for (int idx=tid; idx<HW_; idx+=256){
    int y = idx>>7, w = idx&127;
    float gm = 0.f;
#pragma unroll
    for (int k=0;k<32;k++) gm = fmaf(Fh[y*32+k], Fw[k*128+w], gm);
    outp[idx] = op[idx]*gm + lp[idx];
  }
}

// K6: reflect-pad + depthwise 8x8 + BN
__global__ void k_dw(const float* __restrict__ dww, const float* __restrict__ g,
                     const float* __restrict__ bb){
  __shared__ float s_t[23*23];
  __shared__ float sw[64];
  int tid = threadIdx.x;
  int tx = tid & 15, ty = tid >> 4;
  int bx = blockIdx.x*16, by = blockIdx.y*16;
  int bc = blockIdx.z;
  int c  = bc & 127;
  if (tid < 64) sw[tid] = dww[c*64 + tid];
  const float* op = g_out + (size_t)bc*HW_;
  for (int i = tid; i < 23*23; i += 256){
    int iy = i/23, ix = i - iy*23;
    int py = by-3+iy, px = bx-3+ix;
    float v = 0.f;
    if (py >= 0 && py <= 128 && px >= 0 && px <= 128){
      int ry = (py==128) ? 126 : py;
      int rx = (px==128) ? 126 : px;
      v = op[ry*W_+rx];
    }
    s_t[i] = v;
  }
  __syncthreads();
  float acc = 0.f;
#pragma unroll
  for (int ky=0;ky<8;ky++)
#pragma unroll
    for (int kx=0;kx<8;kx++)
      acc = fmaf(s_t[(ty+ky)*23 + tx+kx], sw[ky*8+kx], acc);
  g_dw[(size_t)bc*HW_ + (by+ty)*W_ + bx+tx] = acc*g[c] + bb[c];
}

// K7: pointwise 1x1 128->128 (f32x2) -> g_proj (pixel-major)
__global__ void k_pw(const float* __restrict__ w){
  __shared__ float s_in[8*1024];
  __shared__ unsigned long long s_w2[64];
  int tid = threadIdx.x;
  int p0 = tid*4;
  int by = blockIdx.y;
  int b   = blockIdx.z >> 4;
  int cog = (blockIdx.z & 15) * 8;
  unsigned long long acc[8][2];
#pragma unroll
  for (int co=0;co<8;co++){ acc[co][0]=0ULL; acc[co][1]=0ULL; }
  const float* in = g_dw + (size_t)b*MID_*HW_ + (size_t)(by*8)*W_;
  for (int c0 = 0; c0 < MID_; c0 += 8){
    for (int i = tid; i < 2048; i += 256){
      int c = i>>8, p4 = (i&255)*4;
      *(float4*)&s_in[c*1024+p4] = *(const float4*)&in[(size_t)(c0+c)*HW_ + p4];
    }
    if (tid < 64){
      float wv = w[(size_t)(cog + (tid>>3))*MID_ + c0 + (tid&7)];
      s_w2[tid] = pkf(wv, wv);
    }
    __syncthreads();
#pragma unroll
    for (int c=0;c<8;c++){
      const unsigned long long* vp = (const unsigned long long*)&s_in[c*1024+p0];
      unsigned long long v0 = vp[0], v1 = vp[1];
#pragma unroll
      for (int co=0;co<8;co++){
        unsigned long long wv = s_w2[co*8+c];
        fma2(acc[co][0], v0, wv);
        fma2(acc[co][1], v1, wv);
      }
    }
    __syncthreads();
  }
  size_t pb = (size_t)b*HW_ + by*1024 + p0;
#pragma unroll
  for (int pp=0; pp<4; pp++){
    int pr = pp>>1, e = pp&1;
    float vals[8];
#pragma unroll
    for (int co=0;co<8;co++){
      float f0,f1; upk(acc[co][pr], f0, f1);
      vals[co] = e ? f1 : f0;
    }
    float* dst = g_proj + (pb+pp)*MID_ + cog;
    *(float4*)dst       = make_float4(vals[0],vals[1],vals[2],vals[3]);
    *((float4*)dst + 1) = make_float4(vals[4],vals[5],vals[6],vals[7]);
  }
}

// K8: transposed conv (lhs_dilation=2), coalesced pixel-major
__global__ void __launch_bounds__(256,2) k_up(const float* __restrict__ upw, float* __restrict__ out){
  __shared__ unsigned long long sw2[128*37 + 4];
  int tid = threadIdx.x;
  int oy0 = blockIdx.x*4;
  int b   = blockIdx.y >> 3;
  int cog = (blockIdx.y & 7) * 8;
  for (int i=tid; i<128*36; i+=256){
    int j = i & 3, rem = i >> 2;
    int ci = rem/9, k = rem - ci*9;
    float wa = upw[(size_t)(cog+2*j  )*1152 + rem];
    float wb = upw[(size_t)(cog+2*j+1)*1152 + rem];
    sw2[ci*37 + k*4 + j] = pkf(wa, wb);
  }
  __syncthreads();
  int q  = tid & 3;
  int po = tid >> 2;
  int xpar = po & 1;
  const float* pbase = g_proj + (size_t)b*HW_*MID_;
  for (int oyl=0; oyl<4; oyl++){
    int oy = oy0+oyl;
    int iys[2], kys[2]; int niy;
    if (oy & 1){
      iys[0]=(oy-1)>>1; kys[0]=0; niy=1;
      if (oy+1<=254){ iys[1]=(oy+1)>>1; kys[1]=2; niy=2; }
    } else { iys[0]=oy>>1; kys[0]=1; niy=1; }
    unsigned long long acc[4][4];
#pragma unroll
    for (int s=0;s<4;s++)
#pragma unroll
      for (int j=0;j<4;j++) acc[s][j]=0ULL;
    int nix = xpar ? 2 : 1;
    for (int a=0;a<niy;a++){
      for (int e=0;e<nix;e++){
        int kx = xpar ? (e==0?0:2) : 1;
        int kb = kys[a]*3 + kx;
        const float* ip[4]; bool pv[4];
#pragma unroll
        for (int s=0;s<4;s++){
          int ox = po + 64*s;
          int ix; bool ok = true;
          if (xpar){ if (e==0) ix = (ox-1)>>1; else { ix = (ox+1)>>1; ok = (ox+1<=254); } }
          else ix = ox>>1;
          pv[s] = ok;
          ip[s] = pbase + ((size_t)(iys[a]*W_ + ix))*MID_;
        }
#pragma unroll
        for (int cc=0; cc<8; cc++){
          int ci4 = q + cc*4;
          float va[4][4];
#pragma unroll
          for (int s=0;s<4;s++){
            float4 v = pv[s] ? ((const float4*)ip[s])[ci4] : make_float4(0.f,0.f,0.f,0.f);
            va[s][0]=v.x; va[s][1]=v.y; va[s][2]=v.z; va[s][3]=v.w;
          }
#pragma unroll
          for (int e2=0;e2<4;e2++){
            int ci = ci4*4 + e2;
            const unsigned long long* wp = &sw2[ci*37 + kb*4];
            unsigned long long w0=wp[0], w1v=wp[1], w2=wp[2], w3=wp[3];
#pragma unroll
            for (int s=0;s<4;s++){
              unsigned long long vv = pkf(va[s][e2], va[s][e2]);
              fma2(acc[s][0], vv, w0);
              fma2(acc[s][1], vv, w1v);
              fma2(acc[s][2], vv, w2);
              fma2(acc[s][3], vv, w3);
            }
          }
        }
      }
    }
#pragma unroll
    for (int s=0;s<4;s++){
      int ox = po + 64*s;
#pragma unroll
      for (int j=0;j<4;j++){
        float f0,f1; upk(acc[s][j], f0, f1);
        f0 += __shfl_xor_sync(0xffffffffu, f0, 1);
        f0 += __shfl_xor_sync(0xffffffffu, f0, 2);
        f1 += __shfl_xor_sync(0xffffffffu, f1, 1);
        f1 += __shfl_xor_sync(0xffffffffu, f1, 2);
        if (q == 0){
          out[(((size_t)(b*COUT_+cog+2*j  ))*256+oy)*256+ox] = f0;
          out[(((size_t)(b*COUT_+cog+2*j+1))*256+oy)*256+ox] = f1;
        }
      }
    }
  }
}

#define ATTNF_SMEM (24622*4)
#define CONV_SMEM  (32*132*8 + 3*32*136*4)

extern "C" void kernel_launch(void* const* d_in, const int* in_sizes, int n_in,
                              void* d_out, int out_size){
  const float* x      = (const float*)d_in[0];
  const float* conv_w = (const float*)d_in[1];
  const float* bn1_g  = (const float*)d_in[2];
  const float* bn1_b  = (const float*)d_in[3];
  const float* qkv_w  = (const float*)d_in[4];
  const float* loc1_w = (const float*)d_in[5];
  const float* loc1_g = (const float*)d_in[6];
  const float* loc1_b = (const float*)d_in[7];
  const float* loc2_w = (const float*)d_in[8];
  const float* loc2_g = (const float*)d_in[9];
  const float* loc2_b = (const float*)d_in[10];
  const float* rel_t  = (const float*)d_in[11];
  const float* cw_w   = (const float*)d_in[12];
  const float* cw_g   = (const float*)d_in[13];
  const float* cw_b   = (const float*)d_in[14];
  const float* hc_w   = (const float*)d_in[15];
  const float* hc_g   = (const float*)d_in[16];
  const float* hc_b   = (const float*)d_in[17];
  const float* hw_w   = (const float*)d_in[18];
  const float* hw_g   = (const float*)d_in[19];
  const float* hw_b   = (const float*)d_in[20];
  const float* pdw    = (const float*)d_in[21];
  const float* pg     = (const float*)d_in[22];
  const float* pb     = (const float*)d_in[23];
  const float* ppw    = (const float*)d_in[24];
  const float* upw    = (const float*)d_in[25];
  float* out = (float*)d_out;

  cudaFuncSetAttribute(k_attnf, cudaFuncAttributeMaxDynamicSharedMemorySize, ATTNF_SMEM);
  cudaFuncSetAttribute(k_convmma<CIN_>, cudaFuncAttributeMaxDynamicSharedMemorySize, CONV_SMEM);
  cudaFuncSetAttribute(k_convmma<MID_>, cudaFuncAttributeMaxDynamicSharedMemorySize, CONV_SMEM);

  float* g_h_p;     cudaGetSymbolAddress((void**)&g_h_p, g_h);
  float* g_local_p; cudaGetSymbolAddress((void**)&g_local_p, g_local);
  float* g_wA1_p;   cudaGetSymbolAddress((void**)&g_wA1_p, g_wA1);
  float* g_wA2_p;   cudaGetSymbolAddress((void**)&g_wA2_p, g_wA2);

  k_nop<<<1,32>>>();   // pad: ncu captures launch #4 = conv1 mma
  k_prepw<<<1152,256>>>(conv_w, bn1_g, (const float*)0, (const float*)0, g_wA1_p, CIN_);
  k_prepw<<<576,256>>>(loc1_w, loc1_g, loc2_w, loc2_g, g_wA2_p, MID_);
  k_convmma<CIN_><<<dim3(128,B_), 256, CONV_SMEM>>>(x, g_wA1_p, bn1_b, (const float*)0, g_h_p, 1);
  k_convmma<MID_><<<dim3(128,B_), 256, CONV_SMEM>>>(g_h_p, g_wA2_p, loc1_b, loc2_b, g_local_p, 0);
  k_qkv  <<<dim3(1,16,192), 256>>>(qkv_w);
  k_attnf<<<1024, 256, ATTNF_SMEM>>>(rel_t, cw_w, cw_g, cw_b, hc_w, hc_g, hc_b, hw_w, hw_g, hw_b);
  k_gmat <<<512, 256>>>();
  k_dw   <<<dim3(8,8,512), 256>>>(pdw, pg, pb);
  k_pw   <<<dim3(1,16,64), 256>>>(ppw);
  k_up   <<<dim3(64, 32), 256>>>(upw, out);
}

// round 12
// speedup vs baseline: 2.2570x; 1.1063x over previous
#include <cuda_runtime.h>
#include <math.h>

#define B_    4
#define CIN_  256
#define MID_  128
#define COUT_ 64
#define H_    128
#define W_    128
#define HW_   16384
#define HEADS_ 8
#define HD_   16
#define NTOK  64
#define NWIN  1024

__device__ float g_h    [B_*MID_*H_*W_];
__device__ float g_local[B_*MID_*H_*W_];
__device__ float g_qkv  [3*NWIN*HEADS_*NTOK*HD_];
__device__ float g_o    [B_*MID_*H_*W_];
__device__ float g_out  [B_*MID_*H_*W_];
__device__ float g_dw   [B_*MID_*H_*W_];
__device__ float g_proj [B_*MID_*H_*W_];
__device__ float g_wA1  [9*CIN_*128];
__device__ float g_wA2  [9*MID_*128];
__device__ float g_wq   [128*384];
__device__ float g_wp   [128*128];

__device__ __forceinline__ float sigmoidf_(float x){ return 1.f/(1.f+expf(-x)); }

__device__ __forceinline__ void fma2(unsigned long long& d, unsigned long long a, unsigned long long b){
  asm("fma.rn.f32x2 %0, %1, %2, %3;" : "=l"(d) : "l"(a), "l"(b), "l"(d));
}
__device__ __forceinline__ unsigned long long pk2u(unsigned int lo, unsigned int hi){
  unsigned long long d; asm("mov.b64 %0, {%1, %2};" : "=l"(d) : "r"(lo), "r"(hi)); return d;
}
__device__ __forceinline__ unsigned long long pkf(float lo, float hi){
  return pk2u(__float_as_uint(lo), __float_as_uint(hi));
}
__device__ __forceinline__ void upk(unsigned long long v, float& a, float& b){
  unsigned int lo, hi; asm("mov.b64 {%0, %1}, %2;" : "=r"(lo), "=r"(hi) : "l"(v));
  a = __uint_as_float(lo); b = __uint_as_float(hi);
}
__device__ __forceinline__ float tf32hi(float v){
  return __uint_as_float(__float_as_uint(v) & 0xFFFFE000u);
}
__device__ __forceinline__ float tf32rn(float v){
  unsigned u; asm("cvt.rna.tf32.f32 %0, %1;" : "=r"(u) : "f"(v));
  return __uint_as_float(u);
}
__device__ __forceinline__ void mma8(float* c, unsigned a0, unsigned a1, unsigned a2, unsigned a3,
                                     unsigned b0, unsigned b1){
  asm volatile("mma.sync.aligned.m16n8k8.row.col.f32.tf32.tf32.f32 "
    "{%0,%1,%2,%3}, {%4,%5,%6,%7}, {%8,%9}, {%0,%1,%2,%3};"
    : "+f"(c[0]), "+f"(c[1]), "+f"(c[2]), "+f"(c[3])
    : "r"(a0), "r"(a1), "r"(a2), "r"(a3), "r"(b0), "r"(b1));
}

// -------- prep ALL weights in one launch (so attnf is the 4th launch) -------
__global__ void k_prepall(const float* __restrict__ conv_w, const float* __restrict__ bn1_g,
                          const float* __restrict__ loc1_w, const float* __restrict__ loc1_g,
                          const float* __restrict__ loc2_w, const float* __restrict__ loc2_g,
                          const float* __restrict__ qkv_w,  const float* __restrict__ ppw){
  int i = blockIdx.x*256 + threadIdx.x;
  if (i < 294912){                      // conv1: [tap][ch8][ci32][co128]
    int tap = i/(256*128); int rem = i - tap*256*128; int ci = rem>>7; int co = rem&127;
    float v = bn1_g[co]*conv_w[((size_t)co*256+ci)*9 + tap];
    g_wA1[(((size_t)tap*8 + (ci>>5))*32 + (ci&31))*128 + co] = tf32rn(v);
  } else if (i < 294912+147456){        // local: loc2 1x1 folded into tap 4
    int i2 = i - 294912;
    int tap = i2/(128*128); int rem = i2 - tap*128*128; int ci = rem>>7; int co = rem&127;
    float v = loc1_g[co]*loc1_w[((size_t)co*128+ci)*9 + tap];
    if (tap==4) v += loc2_g[co]*loc2_w[(size_t)co*128+ci];
    g_wA2[(((size_t)tap*4 + (ci>>5))*32 + (ci&31))*128 + co] = tf32rn(v);
  } else if (i < 294912+147456+49152){  // qkv: [ci128][co384]
    int i3 = i - 294912 - 147456;
    int ci = i3/384, co = i3 - ci*384;
    g_wq[ci*384 + co] = tf32rn(qkv_w[(size_t)co*128 + ci]);
  } else if (i < 294912+147456+49152+16384){ // pw: [ci128][co128]
    int i4 = i - 294912 - 147456 - 49152;
    int ci = i4>>7, co = i4&127;
    g_wp[ci*128 + co] = tf32rn(ppw[(size_t)co*128 + ci]);
  }
}

// conv3x3 CI->128 via mma.sync tf32 (2xTF32). One output row per block, 8 warps.
template<int CI>
__global__ void __launch_bounds__(256)
k_convmma(const float* __restrict__ x, const float* __restrict__ wA,
          const float* __restrict__ bias1, const float* __restrict__ bias2,
          float* __restrict__ outp, int relu){
  extern __shared__ float sh[];
  float2* sIn2 = (float2*)sh;            // 32*132 float2
  float*  sW   = sh + 32*132*2;          // 3*32*136
  const int NCH = CI/32;
  int tid = threadIdx.x, lane = tid&31, wz = tid>>5;
  int cq = lane&3, r = lane>>2;
  int coW = wz*16;
  int y = blockIdx.x, b = blockIdx.y;
  int dylo = (y==0)?1:0, dyhi = (y==127)?1:2;

  float acc[16][4];
#pragma unroll
  for (int nt=0;nt<16;nt++){ acc[nt][0]=0.f; acc[nt][1]=0.f; acc[nt][2]=0.f; acc[nt][3]=0.f; }

  bool first = true;
  for (int ch=0; ch<NCH; ch++){
    for (int dy=dylo; dy<=dyhi; dy++){
      if (!first) __syncthreads();
      first = false;
      const float* inrow = x + ((size_t)b*CI + ch*32)*HW_ + (size_t)(y+dy-1)*W_;
#pragma unroll
      for (int k=0;k<4;k++){
        int u = tid + 256*k;
        int ci = u>>5, q = u&31;
        float4 v = *(const float4*)(inrow + (size_t)ci*HW_ + q*4);
        int base = ci*132 + 1 + q*4;
        float vv[4] = {v.x, v.y, v.z, v.w};
#pragma unroll
        for (int e=0;e<4;e++){
          float hi = tf32hi(vv[e]);
          sIn2[base+e] = make_float2(hi, tf32hi(vv[e]-hi));
        }
      }
      if (tid < 32){
        sIn2[tid*132]     = make_float2(0.f,0.f);
        sIn2[tid*132+129] = make_float2(0.f,0.f);
      }
#pragma unroll
      for (int k=0;k<12;k++){
        int u = tid + 256*k;
        int dx = u>>10, rem = u&1023;
        int ci = rem>>5, c4 = (rem&31)*4;
        float4 vh = *(const float4*)(wA + (((size_t)(dy*3+dx)*NCH + ch)*32 + ci)*128 + c4);
        *(float4*)&sW[dx*(32*136) + ci*136 + c4] = vh;
      }
      __syncthreads();
#pragma unroll
      for (int dx=0; dx<3; dx++){
        const float* A = sW + dx*(32*136);
#pragma unroll
        for (int ks=0; ks<4; ks++){
          int kb = ks*8;
          unsigned a0 = __float_as_uint(A[(kb+cq  )*136 + coW + r    ]);
          unsigned a1 = __float_as_uint(A[(kb+cq  )*136 + coW + r + 8]);
          unsigned a2 = __float_as_uint(A[(kb+cq+4)*136 + coW + r    ]);
          unsigned a3 = __float_as_uint(A[(kb+cq+4)*136 + coW + r + 8]);
#pragma unroll
          for (int nt=0; nt<16; nt++){
            int jb = dx + nt*8 + r;
            float2 p0 = sIn2[(kb+cq  )*132 + jb];
            float2 p1 = sIn2[(kb+cq+4)*132 + jb];
            mma8(acc[nt], a0, a1, a2, a3, __float_as_uint(p0.x), __float_as_uint(p1.x));
            mma8(acc[nt], a0, a1, a2, a3, __float_as_uint(p0.y), __float_as_uint(p1.y));
          }
        }
      }
    }
  }
  float bv0 = bias1[coW+r]   + (bias2 ? bias2[coW+r]   : 0.f);
  float bv1 = bias1[coW+r+8] + (bias2 ? bias2[coW+r+8] : 0.f);
  float* o0 = outp + ((size_t)b*MID_ + coW + r)*HW_ + (size_t)y*W_;
  float* o1 = o0 + 8*HW_;
#pragma unroll
  for (int nt=0; nt<16; nt++){
    int px = nt*8 + 2*cq;
    float v0 = acc[nt][0]+bv0, v1 = acc[nt][1]+bv0;
    float v2 = acc[nt][2]+bv1, v3 = acc[nt][3]+bv1;
    if (relu){ v0=fmaxf(v0,0.f); v1=fmaxf(v1,0.f); v2=fmaxf(v2,0.f); v3=fmaxf(v3,0.f); }
    *(float2*)(o0+px) = make_float2(v0,v1);
    *(float2*)(o1+px) = make_float2(v2,v3);
  }
}

// ----- 1x1 conv via mma (2xTF32). MODE 0: qkv (s=blockIdx.y), MODE 1: pw -----
template<int MODE>
__global__ void __launch_bounds__(256)
k_1x1mma(const float* __restrict__ in_, const float* __restrict__ wA){
  extern __shared__ float sh[];
  float2* sIn2 = (float2*)sh;            // 32*132 float2
  float*  sW   = sh + 32*132*2;          // 128*136
  const int CO = MODE ? 128 : 384;
  int tid = threadIdx.x, lane = tid&31, wz = tid>>5;
  int cq = lane&3, r = lane>>2;
  int coW = wz*16;
  int y = blockIdx.x, s = MODE ? 0 : blockIdx.y, b = blockIdx.z;

  // weight fill: 128ci x 128co section
#pragma unroll
  for (int k=0;k<16;k++){
    int u = tid + 256*k;
    int ci = u>>5, c4 = (u&31)*4;
    float4 v = *(const float4*)(wA + (size_t)ci*CO + s*128 + c4);
    *(float4*)&sW[ci*136 + c4] = v;
  }
  float acc[16][4];
#pragma unroll
  for (int nt=0;nt<16;nt++){ acc[nt][0]=0.f; acc[nt][1]=0.f; acc[nt][2]=0.f; acc[nt][3]=0.f; }

  const float* inrow = in_ + (size_t)b*MID_*HW_ + (size_t)y*W_;
  for (int ch=0; ch<4; ch++){
    __syncthreads();
#pragma unroll
    for (int k=0;k<4;k++){
      int u = tid + 256*k;
      int ci = u>>5, q = u&31;
      float4 v = *(const float4*)(inrow + (size_t)(ch*32+ci)*HW_ + q*4);
      int base = ci*132 + q*4;
      float vv[4] = {v.x, v.y, v.z, v.w};
#pragma unroll
      for (int e=0;e<4;e++){
        float hi = tf32hi(vv[e]);
        sIn2[base+e] = make_float2(hi, tf32hi(vv[e]-hi));
      }
    }
    __syncthreads();
#pragma unroll
    for (int ks=0; ks<4; ks++){
      int kb = ks*8;
      int krow = ch*32 + kb;
      unsigned a0 = __float_as_uint(sW[(krow+cq  )*136 + coW + r    ]);
      unsigned a1 = __float_as_uint(sW[(krow+cq  )*136 + coW + r + 8]);
      unsigned a2 = __float_as_uint(sW[(krow+cq+4)*136 + coW + r    ]);
      unsigned a3 = __float_as_uint(sW[(krow+cq+4)*136 + coW + r + 8]);
#pragma unroll
      for (int nt=0; nt<16; nt++){
        int jb = nt*8 + r;
        float2 p0 = sIn2[(kb+cq  )*132 + jb];
        float2 p1 = sIn2[(kb+cq+4)*132 + jb];
        mma8(acc[nt], a0, a1, a2, a3, __float_as_uint(p0.x), __float_as_uint(p1.x));
        mma8(acc[nt], a0, a1, a2, a3, __float_as_uint(p0.y), __float_as_uint(p1.y));
      }
    }
  }
  if (MODE){
    // pw: g_proj pixel-major [b][px][co]
    float* pbase = g_proj + ((size_t)b*HW_ + (size_t)y*W_)*MID_;
#pragma unroll
    for (int nt=0; nt<16; nt++){
      int px = nt*8 + 2*cq;
      float* d0 = pbase + (size_t)px*MID_;
      d0[coW+r]   = acc[nt][0];  d0[coW+r+8]   = acc[nt][2];
      float* d1 = d0 + MID_;
      d1[coW+r]   = acc[nt][1];  d1[coW+r+8]   = acc[nt][3];
    }
  } else {
    // qkv windowed scatter
    int yh = y>>3, wy = y&7;
#pragma unroll
    for (int c2=0; c2<2; c2++){
      int co_sec = coW + r + c2*8;
      int hd = co_sec>>4, d = co_sec&15;
      size_t base0 = ((size_t)s*NWIN)*HEADS_*NTOK*HD_;
#pragma unroll
      for (int nt=0; nt<16; nt++){
#pragma unroll
        for (int e=0; e<2; e++){
          int px = nt*8 + 2*cq + e;
          int xw = px>>3, wx = px&7;
          int bp = (b*16+yh)*16+xw;
          int n  = wy*8+wx;
          g_qkv[base0 + (((size_t)bp*HEADS_+hd)*NTOK+n)*HD_ + d] = acc[nt][c2*2+e];
        }
      }
    }
  }
}

// K4: fused dots -> gates -> softmax -> attn@v -> g_o
__global__ void k_attnf(const float* __restrict__ rel,
                        const float* __restrict__ cw_w, const float* __restrict__ cw_g, const float* __restrict__ cw_b,
                        const float* __restrict__ hc_w, const float* __restrict__ hc_g, const float* __restrict__ hc_b,
                        const float* __restrict__ hw_w, const float* __restrict__ hw_g, const float* __restrict__ hw_b){
  extern __shared__ float sm[];
  float* sq   = sm;
  float* sk   = sq   + 1024;
  float* sv   = sk   + 1024;
  float* sdh  = sv   + 1024;
  float* z3mx = sdh  + 4096;
  float* z3sm = z3mx + 4096;
  float* z1mx = z3sm + 4096;
  float* z1sm = z1mx + 512;
  float* z2mx = z1sm + 512;
  float* z2sm = z2mx + 512;
  float* sg1  = z2sm + 512;
  float* sg2  = sg1  + 512;
  float* sg3  = sg2  + 512;
  float* swc  = sg3  + 4096;
  float* swh  = swc  + 98;
  float* sww  = swh  + 98;
  float* srel = sww  + 98;

  int bp = blockIdx.x, tid = threadIdx.x;
  if (tid < 98){ swc[tid]=cw_w[tid]; swh[tid]=hc_w[tid]; sww[tid]=hw_w[tid]; }
  for (int i=tid; i<1800; i+=256) srel[i] = rel[i];

  int dn = tid >> 2;
  int dmg = (tid & 3) * 16;
  int y1 = dn>>3, x1 = dn&7;

  for (int h=0; h<8; h++){
    const float* qp = g_qkv + ((size_t)(0*NWIN+bp)*HEADS_+h)*NTOK*HD_;
    const float* kp = g_qkv + ((size_t)(1*NWIN+bp)*HEADS_+h)*NTOK*HD_;
    for (int i=tid;i<1024;i+=256){ sq[i]=qp[i]; sk[i]=kp[i]; }
    __syncthreads();
    {
      const float4* q4 = (const float4*)sq;
      const float4* k4 = (const float4*)sk;
      float4 qa = q4[dn*4+0], qb = q4[dn*4+1], qc = q4[dn*4+2], qd = q4[dn*4+3];
#pragma unroll
      for (int mm=0;mm<16;mm++){
        int m = dmg + mm;
        float4 ka = k4[m*4+0], kb = k4[m*4+1], kc = k4[m*4+2], kd = k4[m*4+3];
        float s = qa.x*ka.x + qa.y*ka.y + qa.z*ka.z + qa.w*ka.w
                + qb.x*kb.x + qb.y*kb.y + qb.z*kb.z + qb.w*kb.w
                + qc.x*kc.x + qc.y*kc.y + qc.z*kc.z + qc.w*kc.w
                + qd.x*kd.x + qd.y*kd.y + qd.z*kd.z + qd.w*kd.w;
        int y2 = m>>3, x2 = m&7;
        int ridx = (y1-y2+7)*15 + (x1-x2+7);
        float val = s*0.25f + srel[ridx*HEADS_ + h];
        int idx = dn*64 + m;
        sdh[idx] = val;
        if (h == 0){ z3mx[idx] = val; z3sm[idx] = val; }
        else { z3mx[idx] = fmaxf(z3mx[idx], val); z3sm[idx] += val; }
      }
    }
    __syncthreads();
    if (tid < 64){
      int m = tid;
      float mx=-1e30f, s=0.f;
      for (int n=0;n<64;n++){ float v = sdh[n*64+m]; mx=fmaxf(mx,v); s+=v; }
      z1mx[h*64+m]=mx; z1sm[h*64+m]=s;
    } else if (tid < 128){
      int n = tid-64;
      float mx=-1e30f, s=0.f;
      for (int j=0;j<64;j++){ float v = sdh[n*64 + ((j+n)&63)]; mx=fmaxf(mx,v); s+=v; }
      z2mx[n*8+h]=mx; z2sm[n*8+h]=s;
    }
    __syncthreads();
  }

  float hwg = hw_g[0], hwb = hw_b[0];
  float cwg = cw_g[0], cwb = cw_b[0];
  float hcg = hc_g[0], hcb = hc_b[0];
  for (int idx=tid; idx<4096; idx+=256){
    int n = idx>>6, m = idx&63;
    float s = 0.f;
    for (int ky=0;ky<7;ky++){
      int pn = n-3+ky; if (pn<0||pn>=64) continue;
      for (int kx=0;kx<7;kx++){
        int pm = m-3+kx; if (pm<0||pm>=64) continue;
        int zi = pn*64+pm;
        s += z3mx[zi]*sww[ky*7+kx] + z3sm[zi]*0.125f*sww[49+ky*7+kx];
      }
    }
    sg3[idx] = sigmoidf_(s*hwg + hwb);
  }
  for (int idx=tid; idx<512; idx+=256){
    {
      int h = idx>>6, m = idx&63;
      float s = 0.f;
      for (int ky=0;ky<7;ky++){
        int ph = h-3+ky; if (ph<0||ph>=8) continue;
        for (int kx=0;kx<7;kx++){
          int pm = m-3+kx; if (pm<0||pm>=64) continue;
          int zi = ph*64+pm;
          s += z1mx[zi]*swc[ky*7+kx] + z1sm[zi]*(1.f/64.f)*swc[49+ky*7+kx];
        }
      }
      sg1[idx] = sigmoidf_(s*cwg + cwb);
    }
    {
      int n = idx>>3, h = idx&7;
      float s = 0.f;
      for (int ky=0;ky<7;ky++){
        int pn = n-3+ky; if (pn<0||pn>=64) continue;
        for (int kx=0;kx<7;kx++){
          int ph = h-3+kx; if (ph<0||ph>=8) continue;
          int zi = pn*8+ph;
          s += z2mx[zi]*swh[ky*7+kx] + z2sm[zi]*(1.f/64.f)*swh[49+ky*7+kx];
        }
      }
      sg2[idx] = sigmoidf_(s*hcg + hcb);
    }
  }
  __syncthreads();

  int b = bp>>8, yh = (bp>>4)&15, xw = bp&15;
  for (int h=0; h<8; h++){
    const float* qp = g_qkv + ((size_t)(0*NWIN+bp)*HEADS_+h)*NTOK*HD_;
    const float* kp = g_qkv + ((size_t)(1*NWIN+bp)*HEADS_+h)*NTOK*HD_;
    const float* vp = g_qkv + ((size_t)(2*NWIN+bp)*HEADS_+h)*NTOK*HD_;
    for (int i=tid;i<1024;i+=256){ sq[i]=qp[i]; sk[i]=kp[i]; sv[i]=vp[i]; }
    __syncthreads();
    {
      const float4* q4 = (const float4*)sq;
      const float4* k4 = (const float4*)sk;
      float4 qa = q4[dn*4+0], qb = q4[dn*4+1], qc = q4[dn*4+2], qd = q4[dn*4+3];
#pragma unroll
      for (int mm=0;mm<16;mm++){
        int m = dmg + mm;
        float4 ka = k4[m*4+0], kb = k4[m*4+1], kc = k4[m*4+2], kd = k4[m*4+3];
        float s = qa.x*ka.x + qa.y*ka.y + qa.z*ka.z + qa.w*ka.w
                + qb.x*kb.x + qb.y*kb.y + qb.z*kb.z + qb.w*kb.w
                + qc.x*kc.x + qc.y*kc.y + qc.z*kc.z + qc.w*kc.w
                + qd.x*kd.x + qd.y*kd.y + qd.z*kd.z + qd.w*kd.w;
        int y2 = m>>3, x2 = m&7;
        int ridx = (y1-y2+7)*15 + (x1-x2+7);
        float val = s*0.25f + srel[ridx*HEADS_ + h];
        float gsum = sg1[h*64+m] + sg2[dn*8+h] + sg3[dn*64+m];
        sdh[dn*64+m] = val * gsum * (1.f/3.f);
      }
    }
    __syncthreads();
    if (tid < 64){
      int n = tid;
      float mx = -1e30f;
      for (int j=0;j<64;j++) mx = fmaxf(mx, sdh[n*64+((j+n)&63)]);
      float s = 0.f;
      for (int j=0;j<64;j++){
        int mi = n*64+((j+n)&63);
        float e = expf(sdh[mi]-mx); sdh[mi]=e; s+=e;
      }
      float inv = 1.f/s;
      for (int j=0;j<64;j++) sdh[n*64+((j+n)&63)] *= inv;
    }
    __syncthreads();
    for (int idx=tid; idx<1024; idx+=256){
      int n = idx>>4, d = idx&15;
      float s = 0.f;
#pragma unroll
      for (int m=0;m<64;m++) s = fmaf(sdh[n*64+m], sv[m*HD_+d], s);
      int c = h*HD_ + d;
      int yy = yh*8 + (n>>3), xx = xw*8 + (n&7);
      g_o[((size_t)(b*MID_+c)*H_+yy)*W_+xx] = s;
    }
    __syncthreads();
  }
}

// K5: Fh@Fw gating, out = o*gmat + local
__global__ void k_gmat(){
  __shared__ float Fh[128*32];
  __shared__ float Fw[32*128];
  int bc = blockIdx.x, tid = threadIdx.x;
  const float* op = g_o + (size_t)bc*HW_;
  for (int idx=tid; idx<4096; idx+=256){
    {
      int k = idx>>7, w = idx&127;
      float mx=-1e30f, sm_=0.f;
#pragma unroll
      for (int j=0;j<4;j++){ float v = op[(k*4+j)*W_+w]; mx=fmaxf(mx,v); sm_+=v; }
      Fw[idx] = sigmoidf_(sm_*0.25f + mx);
    }
    {
      int y = idx>>5, k = idx&31;
      float mx=-1e30f, sm_=0.f;
#pragma unroll
      for (int j=0;j<4;j++){ float v = op[y*W_ + k*4+j]; mx=fmaxf(mx,v); sm_+=v; }
      Fh[idx] = sigmoidf_(sm_*0.25f + mx);
    }
  }
  __syncthreads();
  const float* lp = g_local + (size_t)bc*HW_;
  float* outp = g_out + (size_t)bc*HW_;
  for (int idx=tid; idx<HW_; idx+=256){
    int y = idx>>7, w = idx&127;
    float gm = 0.f;
#pragma unroll
    for (int k=0;k<32;k++) gm = fmaf(Fh[y*32+k], Fw[k*128+w], gm);
    outp[idx] = op[idx]*gm + lp[idx];
  }
}

// K6: reflect-pad + depthwise 8x8 + BN
__global__ void k_dw(const float* __restrict__ dww, const float* __restrict__ g,
                     const float* __restrict__ bb){
  __shared__ float s_t[23*23];
  __shared__ float sw[64];
  int tid = threadIdx.x;
  int tx = tid & 15, ty = tid >> 4;
  int bx = blockIdx.x*16, by = blockIdx.y*16;
  int bc = blockIdx.z;
  int c  = bc & 127;
  if (tid < 64) sw[tid] = dww[c*64 + tid];
  const float* op = g_out + (size_t)bc*HW_;
  for (int i = tid; i < 23*23; i += 256){
    int iy = i/23, ix = i - iy*23;
    int py = by-3+iy, px = bx-3+ix;
    float v = 0.f;
    if (py >= 0 && py <= 128 && px >= 0 && px <= 128){
      int ry = (py==128) ? 126 : py;
      int rx = (px==128) ? 126 : px;
      v = op[ry*W_+rx];
    }
    s_t[i] = v;
  }
  __syncthreads();
  float acc = 0.f;
#pragma unroll
  for (int ky=0;ky<8;ky++)
#pragma unroll
    for (int kx=0;kx<8;kx++)
      acc = fmaf(s_t[(ty+ky)*23 + tx+kx], sw[ky*8+kx], acc);
  g_dw[(size_t)bc*HW_ + (by+ty)*W_ + bx+tx] = acc*g[c] + bb[c];
}

// K8: transposed conv (lhs_dilation=2), coalesced pixel-major
__global__ void __launch_bounds__(256,2) k_up(const float* __restrict__ upw, float* __restrict__ out){
  __shared__ unsigned long long sw2[128*37 + 4];
  int tid = threadIdx.x;
  int oy0 = blockIdx.x*4;
  int b   = blockIdx.y >> 3;
  int cog = (blockIdx.y & 7) * 8;
  for (int i=tid; i<128*36; i+=256){
    int j = i & 3, rem = i >> 2;
    int ci = rem/9, k = rem - ci*9;
    float wa = upw[(size_t)(cog+2*j  )*1152 + rem];
    float wb = upw[(size_t)(cog+2*j+1)*1152 + rem];
    sw2[ci*37 + k*4 + j] = pkf(wa, wb);
  }
  __syncthreads();
  int q  = tid & 3;
  int po = tid >> 2;
  int xpar = po & 1;
  const float* pbase = g_proj + (size_t)b*HW_*MID_;
  for (int oyl=0; oyl<4; oyl++){
    int oy = oy0+oyl;
    int iys[2], kys[2]; int niy;
    if (oy & 1){
      iys[0]=(oy-1)>>1; kys[0]=0; niy=1;
      if (oy+1<=254){ iys[1]=(oy+1)>>1; kys[1]=2; niy=2; }
    } else { iys[0]=oy>>1; kys[0]=1; niy=1; }
    unsigned long long acc[4][4];
#pragma unroll
    for (int s=0;s<4;s++)
#pragma unroll
      for (int j=0;j<4;j++) acc[s][j]=0ULL;
    int nix = xpar ? 2 : 1;
    for (int a=0;a<niy;a++){
      for (int e=0;e<nix;e++){
        int kx = xpar ? (e==0?0:2) : 1;
        int kb = kys[a]*3 + kx;
        const float* ip[4]; bool pv[4];
#pragma unroll
        for (int s=0;s<4;s++){
          int ox = po + 64*s;
          int ix; bool ok = true;
          if (xpar){ if (e==0) ix = (ox-1)>>1; else { ix = (ox+1)>>1; ok = (ox+1<=254); } }
          else ix = ox>>1;
          pv[s] = ok;
          ip[s] = pbase + ((size_t)(iys[a]*W_ + ix))*MID_;
        }
#pragma unroll
        for (int cc=0; cc<8; cc++){
          int ci4 = q + cc*4;
          float va[4][4];
#pragma unroll
          for (int s=0;s<4;s++){
            float4 v = pv[s] ? ((const float4*)ip[s])[ci4] : make_float4(0.f,0.f,0.f,0.f);
            va[s][0]=v.x; va[s][1]=v.y; va[s][2]=v.z; va[s][3]=v.w;
          }
#pragma unroll
          for (int e2=0;e2<4;e2++){
            int ci = ci4*4 + e2;
            const unsigned long long* wp = &sw2[ci*37 + kb*4];
            unsigned long long w0=wp[0], w1v=wp[1], w2=wp[2], w3=wp[3];
#pragma unroll
            for (int s=0;s<4;s++){
              unsigned long long vv = pkf(va[s][e2], va[s][e2]);
              fma2(acc[s][0], vv, w0);
              fma2(acc[s][1], vv, w1v);
              fma2(acc[s][2], vv, w2);
              fma2(acc[s][3], vv, w3);
            }
          }
        }
      }
    }
#pragma unroll
    for (int s=0;s<4;s++){
      int ox = po + 64*s;
#pragma unroll
      for (int j=0;j<4;j++){
        float f0,f1; upk(acc[s][j], f0, f1);
        f0 += __shfl_xor_sync(0xffffffffu, f0, 1);
        f0 += __shfl_xor_sync(0xffffffffu, f0, 2);
        f1 += __shfl_xor_sync(0xffffffffu, f1, 1);
        f1 += __shfl_xor_sync(0xffffffffu, f1, 2);
        if (q == 0){
          out[(((size_t)(b*COUT_+cog+2*j  ))*256+oy)*256+ox] = f0;
          out[(((size_t)(b*COUT_+cog+2*j+1))*256+oy)*256+ox] = f1;
        }
      }
    }
  }
}

#define ATTNF_SMEM (24622*4)
#define CONV_SMEM  (32*132*8 + 3*32*136*4)
#define ONE_SMEM   (32*132*8 + 128*136*4)

extern "C" void kernel_launch(void* const* d_in, const int* in_sizes, int n_in,
                              void* d_out, int out_size){
  const float* x      = (const float*)d_in[0];
  const float* conv_w = (const float*)d_in[1];
  const float* bn1_g  = (const float*)d_in[2];
  const float* bn1_b  = (const float*)d_in[3];
  const float* qkv_w  = (const float*)d_in[4];
  const float* loc1_w = (const float*)d_in[5];
  const float* loc1_g = (const float*)d_in[6];
  const float* loc1_b = (const float*)d_in[7];
  const float* loc2_w = (const float*)d_in[8];
  const float* loc2_g = (const float*)d_in[9];
  const float* loc2_b = (const float*)d_in[10];
  const float* rel_t  = (const float*)d_in[11];
  const float* cw_w   = (const float*)d_in[12];
  const float* cw_g   = (const float*)d_in[13];
  const float* cw_b   = (const float*)d_in[14];
  const float* hc_w   = (const float*)d_in[15];
  const float* hc_g   = (const float*)d_in[16];
  const float* hc_b   = (const float*)d_in[17];
  const float* hw_w   = (const float*)d_in[18];
  const float* hw_g   = (const float*)d_in[19];
  const float* hw_b   = (const float*)d_in[20];
  const float* pdw    = (const float*)d_in[21];
  const float* pg     = (const float*)d_in[22];
  const float* pb     = (const float*)d_in[23];
  const float* ppw    = (const float*)d_in[24];
  const float* upw    = (const float*)d_in[25];
  float* out = (float*)d_out;

  cudaFuncSetAttribute(k_attnf, cudaFuncAttributeMaxDynamicSharedMemorySize, ATTNF_SMEM);
  cudaFuncSetAttribute(k_convmma<CIN_>, cudaFuncAttributeMaxDynamicSharedMemorySize, CONV_SMEM);
  cudaFuncSetAttribute(k_convmma<MID_>, cudaFuncAttributeMaxDynamicSharedMemorySize, CONV_SMEM);
  cudaFuncSetAttribute(k_1x1mma<0>, cudaFuncAttributeMaxDynamicSharedMemorySize, ONE_SMEM);
  cudaFuncSetAttribute(k_1x1mma<1>, cudaFuncAttributeMaxDynamicSharedMemorySize, ONE_SMEM);

  float* g_h_p;     cudaGetSymbolAddress((void**)&g_h_p, g_h);
  float* g_local_p; cudaGetSymbolAddress((void**)&g_local_p, g_local);
  float* g_dw_p;    cudaGetSymbolAddress((void**)&g_dw_p, g_dw);
  float* g_wA1_p;   cudaGetSymbolAddress((void**)&g_wA1_p, g_wA1);
  float* g_wA2_p;   cudaGetSymbolAddress((void**)&g_wA2_p, g_wA2);
  float* g_wq_p;    cudaGetSymbolAddress((void**)&g_wq_p, g_wq);
  float* g_wp_p;    cudaGetSymbolAddress((void**)&g_wp_p, g_wp);

  // order: attnf is the 4th launch -> captured by ncu
  k_prepall<<<1984,256>>>(conv_w, bn1_g, loc1_w, loc1_g, loc2_w, loc2_g, qkv_w, ppw);
  k_convmma<CIN_><<<dim3(128,B_), 256, CONV_SMEM>>>(x, g_wA1_p, bn1_b, (const float*)0, g_h_p, 1);
  k_1x1mma<0><<<dim3(128,3,B_), 256, ONE_SMEM>>>(g_h_p, g_wq_p);
  k_attnf<<<1024, 256, ATTNF_SMEM>>>(rel_t, cw_w, cw_g, cw_b, hc_w, hc_g, hc_b, hw_w, hw_g, hw_b);
  k_convmma<MID_><<<dim3(128,B_), 256, CONV_SMEM>>>(g_h_p, g_wA2_p, loc1_b, loc2_b, g_local_p, 0);
  k_gmat <<<512, 256>>>();
  k_dw   <<<dim3(8,8,512), 256>>>(pdw, pg, pb);
  k_1x1mma<1><<<dim3(128,1,B_), 256, ONE_SMEM>>>(g_dw_p, g_wp_p);
  k_up   <<<dim3(64, 32), 256>>>(upw, out);
}

// round 17
// speedup vs baseline: 2.4506x; 1.0858x over previous
#include <cuda_runtime.h>
#include <math.h>

#define B_    4
#define CIN_  256
#define MID_  128
#define COUT_ 64
#define H_    128
#define W_    128
#define HW_   16384
#define HEADS_ 8
#define HD_   16
#define NTOK  64
#define NWIN  1024

__device__ float g_h    [B_*MID_*H_*W_];
__device__ float g_local[B_*MID_*H_*W_];
__device__ float g_qkv  [3*NWIN*HEADS_*NTOK*HD_];
__device__ float g_o    [B_*MID_*H_*W_];
__device__ float g_out  [B_*MID_*H_*W_];
__device__ float g_dw   [B_*MID_*H_*W_];
__device__ float g_proj [B_*MID_*H_*W_];
__device__ float g_wA1  [9*CIN_*128];
__device__ float g_wA2  [9*MID_*128];
__device__ float g_wq   [128*384];
__device__ float g_wp   [128*128];
__device__ float g_wup  [9*128*72];

__device__ __forceinline__ float sigmoidf_(float x){ return 1.f/(1.f+expf(-x)); }
__device__ __forceinline__ float tf32hi(float v){
  return __uint_as_float(__float_as_uint(v) & 0xFFFFE000u);
}
__device__ __forceinline__ float tf32rn(float v){
  unsigned u; asm("cvt.rna.tf32.f32 %0, %1;" : "=r"(u) : "f"(v));
  return __uint_as_float(u);
}
__device__ __forceinline__ void mma8(float* c, unsigned a0, unsigned a1, unsigned a2, unsigned a3,
                                     unsigned b0, unsigned b1){
  asm volatile("mma.sync.aligned.m16n8k8.row.col.f32.tf32.tf32.f32 "
    "{%0,%1,%2,%3}, {%4,%5,%6,%7}, {%8,%9}, {%0,%1,%2,%3};"
    : "+f"(c[0]), "+f"(c[1]), "+f"(c[2]), "+f"(c[3])
    : "r"(a0), "r"(a1), "r"(a2), "r"(a3), "r"(b0), "r"(b1));
}

// -------- prep ALL weights in one launch --------
__global__ void k_prepall(const float* __restrict__ conv_w, const float* __restrict__ bn1_g,
                          const float* __restrict__ loc1_w, const float* __restrict__ loc1_g,
                          const float* __restrict__ loc2_w, const float* __restrict__ loc2_g,
                          const float* __restrict__ qkv_w,  const float* __restrict__ ppw,
                          const float* __restrict__ upw){
  int i = blockIdx.x*256 + threadIdx.x;
  if (i < 294912){                      // conv1: [tap][ch8][ci32][co128]
    int tap = i/(256*128); int rem = i - tap*256*128; int ci = rem>>7; int co = rem&127;
    float v = bn1_g[co]*conv_w[((size_t)co*256+ci)*9 + tap];
    g_wA1[(((size_t)tap*8 + (ci>>5))*32 + (ci&31))*128 + co] = tf32rn(v);
  } else if (i < 294912+147456){        // local: loc2 folded into tap 4
    int i2 = i - 294912;
    int tap = i2/(128*128); int rem = i2 - tap*128*128; int ci = rem>>7; int co = rem&127;
    float v = loc1_g[co]*loc1_w[((size_t)co*128+ci)*9 + tap];
    if (tap==4) v += loc2_g[co]*loc2_w[(size_t)co*128+ci];
    g_wA2[(((size_t)tap*4 + (ci>>5))*32 + (ci&31))*128 + co] = tf32rn(v);
  } else if (i < 294912+147456+49152){  // qkv: [ci128][co384]
    int i3 = i - 294912 - 147456;
    int ci = i3/384, co = i3 - ci*384;
    g_wq[ci*384 + co] = tf32rn(qkv_w[(size_t)co*128 + ci]);
  } else if (i < 294912+147456+49152+16384){ // pw: [ci128][co128]
    int i4 = i - 294912 - 147456 - 49152;
    int ci = i4>>7, co = i4&127;
    g_wp[ci*128 + co] = tf32rn(ppw[(size_t)co*128 + ci]);
  } else if (i < 294912+147456+49152+16384+73728){ // up: [kk9][ci128][co64 pad72]
    int i5 = i - 294912 - 147456 - 49152 - 16384;
    int kk = i5/(128*64); int rem = i5 - kk*128*64; int ci = rem>>6; int co = rem&63;
    g_wup[((size_t)kk*128 + ci)*72 + co] = tf32rn(upw[(size_t)co*1152 + ci*9 + kk]);
  }
}

// conv3x3 CI->128 via mma.sync tf32 (2xTF32). One output row per block, 8 warps.
template<int CI>
__global__ void __launch_bounds__(256)
k_convmma(const float* __restrict__ x, const float* __restrict__ wA,
          const float* __restrict__ bias1, const float* __restrict__ bias2,
          float* __restrict__ outp, int relu){
  extern __shared__ float sh[];
  float2* sIn2 = (float2*)sh;
  float*  sW   = sh + 32*132*2;
  const int NCH = CI/32;
  int tid = threadIdx.x, lane = tid&31, wz = tid>>5;
  int cq = lane&3, r = lane>>2;
  int coW = wz*16;
  int y = blockIdx.x, b = blockIdx.y;
  int dylo = (y==0)?1:0, dyhi = (y==127)?1:2;

  float acc[16][4];
#pragma unroll
  for (int nt=0;nt<16;nt++){ acc[nt][0]=0.f; acc[nt][1]=0.f; acc[nt][2]=0.f; acc[nt][3]=0.f; }

  bool first = true;
  for (int ch=0; ch<NCH; ch++){
    for (int dy=dylo; dy<=dyhi; dy++){
      if (!first) __syncthreads();
      first = false;
      const float* inrow = x + ((size_t)b*CI + ch*32)*HW_ + (size_t)(y+dy-1)*W_;
#pragma unroll
      for (int k=0;k<4;k++){
        int u = tid + 256*k;
        int ci = u>>5, q = u&31;
        float4 v = *(const float4*)(inrow + (size_t)ci*HW_ + q*4);
        int base = ci*132 + 1 + q*4;
        float vv[4] = {v.x, v.y, v.z, v.w};
#pragma unroll
        for (int e=0;e<4;e++){
          float hi = tf32hi(vv[e]);
          sIn2[base+e] = make_float2(hi, tf32hi(vv[e]-hi));
        }
      }
      if (tid < 32){
        sIn2[tid*132]     = make_float2(0.f,0.f);
        sIn2[tid*132+129] = make_float2(0.f,0.f);
      }
#pragma unroll
      for (int k=0;k<12;k++){
        int u = tid + 256*k;
        int dx = u>>10, rem = u&1023;
        int ci = rem>>5, c4 = (rem&31)*4;
        float4 vh = *(const float4*)(wA + (((size_t)(dy*3+dx)*NCH + ch)*32 + ci)*128 + c4);
        *(float4*)&sW[dx*(32*136) + ci*136 + c4] = vh;
      }
      __syncthreads();
#pragma unroll
      for (int dx=0; dx<3; dx++){
        const float* A = sW + dx*(32*136);
#pragma unroll
        for (int ks=0; ks<4; ks++){
          int kb = ks*8;
          unsigned a0 = __float_as_uint(A[(kb+cq  )*136 + coW + r    ]);
          unsigned a1 = __float_as_uint(A[(kb+cq  )*136 + coW + r + 8]);
          unsigned a2 = __float_as_uint(A[(kb+cq+4)*136 + coW + r    ]);
          unsigned a3 = __float_as_uint(A[(kb+cq+4)*136 + coW + r + 8]);
#pragma unroll
          for (int nt=0; nt<16; nt++){
            int jb = dx + nt*8 + r;
            float2 p0 = sIn2[(kb+cq  )*132 + jb];
            float2 p1 = sIn2[(kb+cq+4)*132 + jb];
            mma8(acc[nt], a0, a1, a2, a3, __float_as_uint(p0.x), __float_as_uint(p1.x));
            mma8(acc[nt], a0, a1, a2, a3, __float_as_uint(p0.y), __float_as_uint(p1.y));
          }
        }
      }
    }
  }
  float bv0 = bias1[coW+r]   + (bias2 ? bias2[coW+r]   : 0.f);
  float bv1 = bias1[coW+r+8] + (bias2 ? bias2[coW+r+8] : 0.f);
  float* o0 = outp + ((size_t)b*MID_ + coW + r)*HW_ + (size_t)y*W_;
  float* o1 = o0 + 8*HW_;
#pragma unroll
  for (int nt=0; nt<16; nt++){
    int px = nt*8 + 2*cq;
    float v0 = acc[nt][0]+bv0, v1 = acc[nt][1]+bv0;
    float v2 = acc[nt][2]+bv1, v3 = acc[nt][3]+bv1;
    if (relu){ v0=fmaxf(v0,0.f); v1=fmaxf(v1,0.f); v2=fmaxf(v2,0.f); v3=fmaxf(v3,0.f); }
    *(float2*)(o0+px) = make_float2(v0,v1);
    *(float2*)(o1+px) = make_float2(v2,v3);
  }
}

// ----- 1x1 conv via mma. MODE 0: qkv (s=blockIdx.y), MODE 1: pw -----
template<int MODE>
__global__ void __launch_bounds__(256)
k_1x1mma(const float* __restrict__ in_, const float* __restrict__ wA){
  extern __shared__ float sh[];
  float2* sIn2 = (float2*)sh;
  float*  sW   = sh + 32*132*2;
  const int CO = MODE ? 128 : 384;
  int tid = threadIdx.x, lane = tid&31, wz = tid>>5;
  int cq = lane&3, r = lane>>2;
  int coW = wz*16;
  int y = blockIdx.x, s = MODE ? 0 : blockIdx.y, b = blockIdx.z;

#pragma unroll
  for (int k=0;k<16;k++){
    int u = tid + 256*k;
    int ci = u>>5, c4 = (u&31)*4;
    float4 v = *(const float4*)(wA + (size_t)ci*CO + s*128 + c4);
    *(float4*)&sW[ci*136 + c4] = v;
  }
  float acc[16][4];
#pragma unroll
  for (int nt=0;nt<16;nt++){ acc[nt][0]=0.f; acc[nt][1]=0.f; acc[nt][2]=0.f; acc[nt][3]=0.f; }

  const float* inrow = in_ + (size_t)b*MID_*HW_ + (size_t)y*W_;
  for (int ch=0; ch<4; ch++){
    __syncthreads();
#pragma unroll
    for (int k=0;k<4;k++){
      int u = tid + 256*k;
      int ci = u>>5, q = u&31;
      float4 v = *(const float4*)(inrow + (size_t)(ch*32+ci)*HW_ + q*4);
      int base = ci*132 + q*4;
      float vv[4] = {v.x, v.y, v.z, v.w};
#pragma unroll
      for (int e=0;e<4;e++){
        float hi = tf32hi(vv[e]);
        sIn2[base+e] = make_float2(hi, tf32hi(vv[e]-hi));
      }
    }
    __syncthreads();
#pragma unroll
    for (int ks=0; ks<4; ks++){
      int kb = ks*8;
      int krow = ch*32 + kb;
      unsigned a0 = __float_as_uint(sW[(krow+cq  )*136 + coW + r    ]);
      unsigned a1 = __float_as_uint(sW[(krow+cq  )*136 + coW + r + 8]);
      unsigned a2 = __float_as_uint(sW[(krow+cq+4)*136 + coW + r    ]);
      unsigned a3 = __float_as_uint(sW[(krow+cq+4)*136 + coW + r + 8]);
#pragma unroll
      for (int nt=0; nt<16; nt++){
        int jb = nt*8 + r;
        float2 p0 = sIn2[(kb+cq  )*132 + jb];
        float2 p1 = sIn2[(kb+cq+4)*132 + jb];
        mma8(acc[nt], a0, a1, a2, a3, __float_as_uint(p0.x), __float_as_uint(p1.x));
        mma8(acc[nt], a0, a1, a2, a3, __float_as_uint(p0.y), __float_as_uint(p1.y));
      }
    }
  }
  if (MODE){
    float* pbase = g_proj + ((size_t)b*HW_ + (size_t)y*W_)*MID_;
#pragma unroll
    for (int nt=0; nt<16; nt++){
      int px = nt*8 + 2*cq;
      float* d0 = pbase + (size_t)px*MID_;
      d0[coW+r]   = acc[nt][0];  d0[coW+r+8]   = acc[nt][2];
      float* d1 = d0 + MID_;
      d1[coW+r]   = acc[nt][1];  d1[coW+r+8]   = acc[nt][3];
    }
  } else {
    int yh = y>>3, wy = y&7;
#pragma unroll
    for (int c2=0; c2<2; c2++){
      int co_sec = coW + r + c2*8;
      int hd = co_sec>>4, d = co_sec&15;
      size_t base0 = ((size_t)s*NWIN)*HEADS_*NTOK*HD_;
#pragma unroll
      for (int nt=0; nt<16; nt++){
#pragma unroll
        for (int e=0; e<2; e++){
          int px = nt*8 + 2*cq + e;
          int xw = px>>3, wx = px&7;
          int bp = (b*16+yh)*16+xw;
          int n  = wy*8+wx;
          g_qkv[base0 + (((size_t)bp*HEADS_+hd)*NTOK+n)*HD_ + d] = acc[nt][c2*2+e];
        }
      }
    }
  }
}

// K4: fused dots -> gates -> softmax -> attn@v -> g_o
__global__ void k_attnf(const float* __restrict__ rel,
                        const float* __restrict__ cw_w, const float* __restrict__ cw_g, const float* __restrict__ cw_b,
                        const float* __restrict__ hc_w, const float* __restrict__ hc_g, const float* __restrict__ hc_b,
                        const float* __restrict__ hw_w, const float* __restrict__ hw_g, const float* __restrict__ hw_b){
  extern __shared__ float sm[];
  float* sq   = sm;
  float* sk   = sq   + 1024;
  float* sv   = sk   + 1024;
  float* sdh  = sv   + 1024;
  float* z3mx = sdh  + 4096;
  float* z3sm = z3mx + 4096;
  float* z1mx = z3sm + 4096;
  float* z1sm = z1mx + 512;
  float* z2mx = z1sm + 512;
  float* z2sm = z2mx + 512;
  float* sg1  = z2sm + 512;
  float* sg2  = sg1  + 512;
  float* sg3  = sg2  + 512;
  float* swc  = sg3  + 4096;
  float* swh  = swc  + 98;
  float* sww  = swh  + 98;
  float* srel = sww  + 98;

  int bp = blockIdx.x, tid = threadIdx.x;
  if (tid < 98){ swc[tid]=cw_w[tid]; swh[tid]=hc_w[tid]; sww[tid]=hw_w[tid]; }
  for (int i=tid; i<1800; i+=256) srel[i] = rel[i];

  int dn = tid >> 2;
  int dmg = (tid & 3) * 16;
  int y1 = dn>>3, x1 = dn&7;

  for (int h=0; h<8; h++){
    const float* qp = g_qkv + ((size_t)(0*NWIN+bp)*HEADS_+h)*NTOK*HD_;
    const float* kp = g_qkv + ((size_t)(1*NWIN+bp)*HEADS_+h)*NTOK*HD_;
    for (int i=tid;i<1024;i+=256){ sq[i]=qp[i]; sk[i]=kp[i]; }
    __syncthreads();
    {
      const float4* q4 = (const float4*)sq;
      const float4* k4 = (const float4*)sk;
      float4 qa = q4[dn*4+0], qb = q4[dn*4+1], qc = q4[dn*4+2], qd = q4[dn*4+3];
#pragma unroll
      for (int mm=0;mm<16;mm++){
        int m = dmg + mm;
        float4 ka = k4[m*4+0], kb = k4[m*4+1], kc = k4[m*4+2], kd = k4[m*4+3];
        float s = qa.x*ka.x + qa.y*ka.y + qa.z*ka.z + qa.w*ka.w
                + qb.x*kb.x + qb.y*kb.y + qb.z*kb.z + qb.w*kb.w
                + qc.x*kc.x + qc.y*kc.y + qc.z*kc.z + qc.w*kc.w
                + qd.x*kd.x + qd.y*kd.y + qd.z*kd.z + qd.w*kd.w;
        int y2 = m>>3, x2 = m&7;
        int ridx = (y1-y2+7)*15 + (x1-x2+7);
        float val = s*0.25f + srel[ridx*HEADS_ + h];
        int idx = dn*64 + m;
        sdh[idx] = val;
        if (h == 0){ z3mx[idx] = val; z3sm[idx] = val; }
        else { z3mx[idx] = fmaxf(z3mx[idx], val); z3sm[idx] += val; }
      }
    }
    __syncthreads();
    if (tid < 64){
      int m = tid;
      float mx=-1e30f, s=0.f;
      for (int n=0;n<64;n++){ float v = sdh[n*64+m]; mx=fmaxf(mx,v); s+=v; }
      z1mx[h*64+m]=mx; z1sm[h*64+m]=s;
    } else if (tid < 128){
      int n = tid-64;
      float mx=-1e30f, s=0.f;
      for (int j=0;j<64;j++){ float v = sdh[n*64 + ((j+n)&63)]; mx=fmaxf(mx,v); s+=v; }
      z2mx[n*8+h]=mx; z2sm[n*8+h]=s;
    }
    __syncthreads();
  }

  float hwg = hw_g[0], hwb = hw_b[0];
  float cwg = cw_g[0], cwb = cw_b[0];
  float hcg = hc_g[0], hcb = hc_b[0];
  for (int idx=tid; idx<4096; idx+=256){
    int n = idx>>6, m = idx&63;
    float s = 0.f;
    for (int ky=0;ky<7;ky++){
      int pn = n-3+ky; if (pn<0||pn>=64) continue;
      for (int kx=0;kx<7;kx++){
        int pm = m-3+kx; if (pm<0||pm>=64) continue;
        int zi = pn*64+pm;
        s += z3mx[zi]*sww[ky*7+kx] + z3sm[zi]*0.125f*sww[49+ky*7+kx];
      }
    }
    sg3[idx] = sigmoidf_(s*hwg + hwb);
  }
  for (int idx=tid; idx<512; idx+=256){
    {
      int h = idx>>6, m = idx&63;
      float s = 0.f;
      for (int ky=0;ky<7;ky++){
        int ph = h-3+ky; if (ph<0||ph>=8) continue;
        for (int kx=0;kx<7;kx++){
          int pm = m-3+kx; if (pm<0||pm>=64) continue;
          int zi = ph*64+pm;
          s += z1mx[zi]*swc[ky*7+kx] + z1sm[zi]*(1.f/64.f)*swc[49+ky*7+kx];
        }
      }
      sg1[idx] = sigmoidf_(s*cwg + cwb);
    }
    {
      int n = idx>>3, h = idx&7;
      float s = 0.f;
      for (int ky=0;ky<7;ky++){
        int pn = n-3+ky; if (pn<0||pn>=64) continue;
        for (int kx=0;kx<7;kx++){
          int ph = h-3+kx; if (ph<0||ph>=8) continue;
          int zi = pn*8+ph;
          s += z2mx[zi]*swh[ky*7+kx] + z2sm[zi]*(1.f/64.f)*swh[49+ky*7+kx];
        }
      }
      sg2[idx] = sigmoidf_(s*hcg + hcb);
    }
  }
  __syncthreads();

  int b = bp>>8, yh = (bp>>4)&15, xw = bp&15;
  for (int h=0; h<8; h++){
    const float* qp = g_qkv + ((size_t)(0*NWIN+bp)*HEADS_+h)*NTOK*HD_;
    const float* kp = g_qkv + ((size_t)(1*NWIN+bp)*HEADS_+h)*NTOK*HD_;
    const float* vp = g_qkv + ((size_t)(2*NWIN+bp)*HEADS_+h)*NTOK*HD_;
    for (int i=tid;i<1024;i+=256){ sq[i]=qp[i]; sk[i]=kp[i]; sv[i]=vp[i]; }
    __syncthreads();
    {
      const float4* q4 = (const float4*)sq;
      const float4* k4 = (const float4*)sk;
      float4 qa = q4[dn*4+0], qb = q4[dn*4+1], qc = q4[dn*4+2], qd = q4[dn*4+3];
#pragma unroll
      for (int mm=0;mm<16;mm++){
        int m = dmg + mm;
        float4 ka = k4[m*4+0], kb = k4[m*4+1], kc = k4[m*4+2], kd = k4[m*4+3];
        float s = qa.x*ka.x + qa.y*ka.y + qa.z*ka.z + qa.w*ka.w
                + qb.x*kb.x + qb.y*kb.y + qb.z*kb.z + qb.w*kb.w
                + qc.x*kc.x + qc.y*kc.y + qc.z*kc.z + qc.w*kc.w
                + qd.x*kd.x + qd.y*kd.y + qd.z*kd.z + qd.w*kd.w;
        int y2 = m>>3, x2 = m&7;
        int ridx = (y1-y2+7)*15 + (x1-x2+7);
        float val = s*0.25f + srel[ridx*HEADS_ + h];
        float gsum = sg1[h*64+m] + sg2[dn*8+h] + sg3[dn*64+m];
        sdh[dn*64+m] = val * gsum * (1.f/3.f);
      }
    }
    __syncthreads();
    if (tid < 64){
      int n = tid;
      float mx = -1e30f;
      for (int j=0;j<64;j++) mx = fmaxf(mx, sdh[n*64+((j+n)&63)]);
      float s = 0.f;
      for (int j=0;j<64;j++){
        int mi = n*64+((j+n)&63);
        float e = expf(sdh[mi]-mx); sdh[mi]=e; s+=e;
      }
      float inv = 1.f/s;
      for (int j=0;j<64;j++) sdh[n*64+((j+n)&63)] *= inv;
    }
    __syncthreads();
    for (int idx=tid; idx<1024; idx+=256){
      int n = idx>>4, d = idx&15;
      float s = 0.f;
#pragma unroll
      for (int m=0;m<64;m++) s = fmaf(sdh[n*64+m], sv[m*HD_+d], s);
      int c = h*HD_ + d;
      int yy = yh*8 + (n>>3), xx = xw*8 + (n&7);
      g_o[((size_t)(b*MID_+c)*H_+yy)*W_+xx] = s;
    }
    __syncthreads();
  }
}

// K5: Fh@Fw gating, out = o*gmat + local
__global__ void k_gmat(){
  __shared__ float Fh[128*32];
  __shared__ float Fw[32*128];
  int bc = blockIdx.x, tid = threadIdx.x;
  const float* op = g_o + (size_t)bc*HW_;
  for (int idx=tid; idx<4096; idx+=256){
    {
      int k = idx>>7, w = idx&127;
      float mx=-1e30f, sm_=0.f;
#pragma unroll
      for (int j=0;j<4;j++){ float v = op[(k*4+j)*W_+w]; mx=fmaxf(mx,v); sm_+=v; }
      Fw[idx] = sigmoidf_(sm_*0.25f + mx);
    }
    {
      int y = idx>>5, k = idx&31;
      float mx=-1e30f, sm_=0.f;
#pragma unroll
      for (int j=0;j<4;j++){ float v = op[y*W_ + k*4+j]; mx=fmaxf(mx,v); sm_+=v; }
      Fh[idx] = sigmoidf_(sm_*0.25f + mx);
    }
  }
  __syncthreads();
  const float* lp = g_local + (size_t)bc*HW_;
  float* outp = g_out + (size_t)bc*HW_;
  for (int idx=tid; idx<HW_; idx+=256){
    int y = idx>>7, w = idx&127;
    float gm = 0.f;
#pragma unroll
    for (int k=0;k<32;k++) gm = fmaf(Fh[y*32+k], Fw[k*128+w], gm);
    outp[idx] = op[idx]*gm + lp[idx];
  }
}

// K6: reflect-pad + depthwise 8x8 + BN
__global__ void k_dw(const float* __restrict__ dww, const float* __restrict__ g,
                     const float* __restrict__ bb){
  __shared__ float s_t[23*23];
  __shared__ float sw[64];
  int tid = threadIdx.x;
  int tx = tid & 15, ty = tid >> 4;
  int bx = blockIdx.x*16, by = blockIdx.y*16;
  int bc = blockIdx.z;
  int c  = bc & 127;
  if (tid < 64) sw[tid] = dww[c*64 + tid];
  const float* op = g_out + (size_t)bc*HW_;
  for (int i = tid; i < 23*23; i += 256){
    int iy = i/23, ix = i - iy*23;
    int py = by-3+iy, px = bx-3+ix;
    float v = 0.f;
    if (py >= 0 && py <= 128 && px >= 0 && px <= 128){
      int ry = (py==128) ? 126 : py;
      int rx = (px==128) ? 126 : px;
      v = op[ry*W_+rx];
    }
    s_t[i] = v;
  }
  __syncthreads();
  float acc = 0.f;
#pragma unroll
  for (int ky=0;ky<8;ky++)
#pragma unroll
    for (int kx=0;kx<8;kx++)
      acc = fmaf(s_t[(ty+ky)*23 + tx+kx], sw[ky*8+kx], acc);
  g_dw[(size_t)bc*HW_ + (by+ty)*W_ + bx+tx] = acc*g[c] + bb[c];
}

// K8: transposed conv via mma (even/odd ox phases). One oy row per block.
__global__ void __launch_bounds__(256)
k_upmma(float* __restrict__ out){
  extern __shared__ float sh[];
  float2* sIn2 = (float2*)sh;          // [32ci][132] (t, hi/lo)
  float*  sW   = sh + 32*132*2;        // [3kx][32ci][72]
  int tid = threadIdx.x, lane = tid&31, wz = tid>>5;
  int cq = lane&3, r = lane>>2;
  int wm = wz&3, wn = wz>>2;
  int coW = wm*16;
  int oy = blockIdx.x, b = blockIdx.y;
  int iys[2], kys[2], niy;
  if (oy & 1){
    iys[0]=(oy-1)>>1; kys[0]=0; niy=1;
    if (oy+1<=254){ iys[1]=(oy+1)>>1; kys[1]=2; niy=2; }
  } else { iys[0]=oy>>1; kys[0]=1; niy=1; }

  float acce[8][4], acco[8][4];
#pragma unroll
  for (int nt=0;nt<8;nt++)
#pragma unroll
    for (int c=0;c<4;c++){ acce[nt][c]=0.f; acco[nt][c]=0.f; }

  bool first = true;
  for (int a=0;a<niy;a++){
    int iy = iys[a], ky = kys[a];
    for (int ch=0; ch<4; ch++){
      if (!first) __syncthreads();
      first = false;
      // B fill: row iy, t=0..127, ci chunk; hi/lo
      const float* prow = g_proj + ((size_t)b*HW_ + (size_t)iy*W_)*MID_ + ch*32;
#pragma unroll
      for (int k=0;k<4;k++){
        int u = tid + 256*k;
        int t = u>>3, c4 = (u&7)*4;
        float4 v = *(const float4*)(prow + (size_t)t*MID_ + c4);
        float vv[4] = {v.x,v.y,v.z,v.w};
#pragma unroll
        for (int e=0;e<4;e++){
          float hi = tf32hi(vv[e]);
          sIn2[(c4+e)*132 + t] = make_float2(hi, tf32hi(vv[e]-hi));
        }
      }
      if (tid < 32) sIn2[tid*132 + 128] = make_float2(0.f,0.f);
      // A fill: 3 kx tiles, 32ci x 64co
#pragma unroll
      for (int k=0;k<6;k++){
        int u = tid + 256*k;
        int kxr = u/512, rem = u - kxr*512;
        int ci = rem>>4, c4 = (rem&15)*4;
        float4 v = *(const float4*)&g_wup[((size_t)(ky*3+kxr)*128 + ch*32+ci)*72 + c4];
        *(float4*)&sW[kxr*(32*72) + ci*72 + c4] = v;
      }
      __syncthreads();
      // even phase: kx=1
      {
        const float* A = sW + 1*(32*72);
#pragma unroll
        for (int ks=0; ks<4; ks++){
          int kb = ks*8;
          unsigned a0 = __float_as_uint(A[(kb+cq  )*72 + coW + r    ]);
          unsigned a1 = __float_as_uint(A[(kb+cq  )*72 + coW + r + 8]);
          unsigned a2 = __float_as_uint(A[(kb+cq+4)*72 + coW + r    ]);
          unsigned a3 = __float_as_uint(A[(kb+cq+4)*72 + coW + r + 8]);
#pragma unroll
          for (int nt=0; nt<8; nt++){
            int jb = wn*64 + nt*8 + r;
            float2 p0 = sIn2[(kb+cq  )*132 + jb];
            float2 p1 = sIn2[(kb+cq+4)*132 + jb];
            mma8(acce[nt], a0, a1, a2, a3, __float_as_uint(p0.x), __float_as_uint(p1.x));
            mma8(acce[nt], a0, a1, a2, a3, __float_as_uint(p0.y), __float_as_uint(p1.y));
          }
        }
      }
      // odd phase: kx=0 (jb), kx=2 (jb+1)
#pragma unroll
      for (int kxi=0; kxi<2; kxi++){
        const float* A = sW + (kxi?2:0)*(32*72);
        int sh_ = kxi ? 1 : 0;
#pragma unroll
        for (int ks=0; ks<4; ks++){
          int kb = ks*8;
          unsigned a0 = __float_as_uint(A[(kb+cq  )*72 + coW + r    ]);
          unsigned a1 = __float_as_uint(A[(kb+cq  )*72 + coW + r + 8]);
          unsigned a2 = __float_as_uint(A[(kb+cq+4)*72 + coW + r    ]);
          unsigned a3 = __float_as_uint(A[(kb+cq+4)*72 + coW + r + 8]);
#pragma unroll
          for (int nt=0; nt<8; nt++){
            int jb = wn*64 + nt*8 + r + sh_;
            float2 p0 = sIn2[(kb+cq  )*132 + jb];
            float2 p1 = sIn2[(kb+cq+4)*132 + jb];
            mma8(acco[nt], a0, a1, a2, a3, __float_as_uint(p0.x), __float_as_uint(p1.x));
            mma8(acco[nt], a0, a1, a2, a3, __float_as_uint(p0.y), __float_as_uint(p1.y));
          }
        }
      }
    }
  }
  // store: n = wn*64+nt*8+2cq -> ox0=2n (div by 4): {e0, o0, e1, o1}
  float* r0 = out + (((size_t)(b*COUT_ + coW + r))*256 + oy)*256;
  float* r1 = r0 + (size_t)8*256*256;
#pragma unroll
  for (int nt=0; nt<8; nt++){
    int ox0 = 2*(wn*64 + nt*8 + 2*cq);
    *(float4*)(r0 + ox0) = make_float4(acce[nt][0], acco[nt][0], acce[nt][1], acco[nt][1]);
    *(float4*)(r1 + ox0) = make_float4(acce[nt][2], acco[nt][2], acce[nt][3], acco[nt][3]);
  }
}

#define ATTNF_SMEM (24622*4)
#define CONV_SMEM  (32*132*8 + 3*32*136*4)
#define ONE_SMEM   (32*132*8 + 128*136*4)
#define UP_SMEM    (32*132*8 + 3*32*72*4)

extern "C" void kernel_launch(void* const* d_in, const int* in_sizes, int n_in,
                              void* d_out, int out_size){
  const float* x      = (const float*)d_in[0];
  const float* conv_w = (const float*)d_in[1];
  const float* bn1_g  = (const float*)d_in[2];
  const float* bn1_b  = (const float*)d_in[3];
  const float* qkv_w  = (const float*)d_in[4];
  const float* loc1_w = (const float*)d_in[5];
  const float* loc1_g = (const float*)d_in[6];
  const float* loc1_b = (const float*)d_in[7];
  const float* loc2_w = (const float*)d_in[8];
  const float* loc2_g = (const float*)d_in[9];
  const float* loc2_b = (const float*)d_in[10];
  const float* rel_t  = (const float*)d_in[11];
  const float* cw_w   = (const float*)d_in[12];
  const float* cw_g   = (const float*)d_in[13];
  const float* cw_b   = (const float*)d_in[14];
  const float* hc_w   = (const float*)d_in[15];
  const float* hc_g   = (const float*)d_in[16];
  const float* hc_b   = (const float*)d_in[17];
  const float* hw_w   = (const float*)d_in[18];
  const float* hw_g   = (const float*)d_in[19];
  const float* hw_b   = (const float*)d_in[20];
  const float* pdw    = (const float*)d_in[21];
  const float* pg     = (const float*)d_in[22];
  const float* pb     = (const float*)d_in[23];
  const float* ppw    = (const float*)d_in[24];
  const float* upw    = (const float*)d_in[25];
  float* out = (float*)d_out;

  cudaFuncSetAttribute(k_attnf, cudaFuncAttributeMaxDynamicSharedMemorySize, ATTNF_SMEM);
  cudaFuncSetAttribute(k_convmma<CIN_>, cudaFuncAttributeMaxDynamicSharedMemorySize, CONV_SMEM);
  cudaFuncSetAttribute(k_convmma<MID_>, cudaFuncAttributeMaxDynamicSharedMemorySize, CONV_SMEM);
  cudaFuncSetAttribute(k_1x1mma<0>, cudaFuncAttributeMaxDynamicSharedMemorySize, ONE_SMEM);
  cudaFuncSetAttribute(k_1x1mma<1>, cudaFuncAttributeMaxDynamicSharedMemorySize, ONE_SMEM);
  cudaFuncSetAttribute(k_upmma, cudaFuncAttributeMaxDynamicSharedMemorySize, UP_SMEM);

  float* g_h_p;     cudaGetSymbolAddress((void**)&g_h_p, g_h);
  float* g_local_p; cudaGetSymbolAddress((void**)&g_local_p, g_local);
  float* g_dw_p;    cudaGetSymbolAddress((void**)&g_dw_p, g_dw);
  float* g_wA1_p;   cudaGetSymbolAddress((void**)&g_wA1_p, g_wA1);
  float* g_wA2_p;   cudaGetSymbolAddress((void**)&g_wA2_p, g_wA2);
  float* g_wq_p;    cudaGetSymbolAddress((void**)&g_wq_p, g_wq);
  float* g_wp_p;    cudaGetSymbolAddress((void**)&g_wp_p, g_wp);

  k_prepall<<<2272,256>>>(conv_w, bn1_g, loc1_w, loc1_g, loc2_w, loc2_g, qkv_w, ppw, upw);
  k_convmma<CIN_><<<dim3(128,B_), 256, CONV_SMEM>>>(x, g_wA1_p, bn1_b, (const float*)0, g_h_p, 1);
  k_1x1mma<0><<<dim3(128,3,B_), 256, ONE_SMEM>>>(g_h_p, g_wq_p);
  k_attnf<<<1024, 256, ATTNF_SMEM>>>(rel_t, cw_w, cw_g, cw_b, hc_w, hc_g, hc_b, hw_w, hw_g, hw_b);
  k_convmma<MID_><<<dim3(128,B_), 256, CONV_SMEM>>>(g_h_p, g_wA2_p, loc1_b, loc2_b, g_local_p, 0);
  k_gmat <<<512, 256>>>();
  k_dw   <<<dim3(8,8,512), 256>>>(pdw, pg, pb);
  k_1x1mma<1><<<dim3(128,1,B_), 256, ONE_SMEM>>>(g_dw_p, g_wp_p);
  k_upmma<<<dim3(256, B_), 256, UP_SMEM>>>(out);
}